// round 1
// baseline (speedup 1.0000x reference)
#include <cuda_runtime.h>
#include <math.h>
#include <stdint.h>
#include <stddef.h>

// ---------------------------------------------------------------------------
// DGCNN classifier, B=8, N=1024, K=20.
// Scratch: __device__ globals (allocation-free rule).
// ---------------------------------------------------------------------------

#define BATCH 8
#define NPTS 1024
#define KNN 20
#define NPOINTS (BATCH * NPTS)          // 8192
#define MROWS (NPOINTS * KNN)           // 163840

__device__ float g_xp[NPOINTS * 3];
__device__ float g_feat[NPOINTS * 512];
__device__ float g_D[(size_t)BATCH * NPTS * NPTS];
__device__ int   g_idx[NPOINTS * KNN];
__device__ float g_xx[NPOINTS];
__device__ float g_E[(size_t)MROWS * 128];
__device__ float g_H[(size_t)MROWS * 256];
__device__ float g_t[NPOINTS * 256];
__device__ float g_h5[(size_t)NPOINTS * 1024];
__device__ float g_part[256 * 1024 * 2];
__device__ float g_scale[1024];
__device__ float g_shift[1024];
__device__ float g_w1t[6 * 64];
__device__ float g_w2t[128 * 64];
__device__ float g_w3t[128 * 128];
__device__ float g_w4t[256 * 256];
__device__ float g_w5t[512 * 1024];
__device__ float g_pooled[BATCH * 2048];
__device__ float g_fc1raw[BATCH * 512];
__device__ float g_fc1[BATCH * 512];
__device__ float g_fc2raw[BATCH * 256];
__device__ float g_fc2[BATCH * 256];

#define NEG_BIG (-3.0e38f)

// ---------------------------------------------------------------------------
// small utility kernels
// ---------------------------------------------------------------------------

__global__ void transpose_x_k(const float* __restrict__ x, float* __restrict__ xp) {
    int l = blockIdx.x * blockDim.x + threadIdx.x;
    if (l >= BATCH * NPTS * 3) return;
    int c = l % 3;
    int n = (l / 3) % NPTS;
    int b = l / (3 * NPTS);
    xp[l] = x[((size_t)b * 3 + c) * NPTS + n];
}

// Wt[c][o] = W[o][c]; W is (O, Kc)
__global__ void wt_k(const float* __restrict__ W, int O, int Kc, float* __restrict__ Wt) {
    int l = blockIdx.x * blockDim.x + threadIdx.x;
    if (l >= O * Kc) return;
    int o = l % O;
    int c = l / O;
    Wt[l] = W[(size_t)o * Kc + c];
}

// per-point squared norm; F pre-offset, row stride ldf, C channels
__global__ void xx_k(const float* __restrict__ F, int ldf, int C, float* __restrict__ xx) {
    int g = blockIdx.x * blockDim.x + threadIdx.x;
    int p = g >> 5, lane = g & 31;
    if (p >= NPOINTS) return;
    const float* f = F + (size_t)p * ldf;
    float s = 0.f;
    for (int c = lane; c < C; c += 32) { float v = f[c]; s += v * v; }
    #pragma unroll
    for (int off = 16; off; off >>= 1) s += __shfl_down_sync(0xffffffffu, s, off);
    if (lane == 0) xx[p] = s;
}

// ---------------------------------------------------------------------------
// pairwise neg-distances per batch: D[b][i][j] = -(xx_i - 2*dot + xx_j)
// grid (16 jtiles, 16 itiles, 8 batches), 256 threads, 64x64 tile
// ---------------------------------------------------------------------------
__global__ void dist_k(const float* __restrict__ F, int ldf, int C,
                       const float* __restrict__ xx, float* __restrict__ D) {
    __shared__ float Fi[64][33];
    __shared__ float Fj[64][33];
    int b = blockIdx.z;
    int i0 = blockIdx.y * 64, j0 = blockIdx.x * 64;
    int tid = threadIdx.x;
    int tm = tid / 16, tn = tid % 16;
    const float* Fb = F + (size_t)b * NPTS * ldf;
    float acc[4][4];
    #pragma unroll
    for (int i = 0; i < 4; i++)
        #pragma unroll
        for (int j = 0; j < 4; j++) acc[i][j] = 0.f;

    for (int c0 = 0; c0 < C; c0 += 32) {
        for (int l = tid; l < 64 * 32; l += 256) {
            int r = l >> 5, c = l & 31;
            Fi[r][c] = (c0 + c < C) ? Fb[(size_t)(i0 + r) * ldf + c0 + c] : 0.f;
            Fj[r][c] = (c0 + c < C) ? Fb[(size_t)(j0 + r) * ldf + c0 + c] : 0.f;
        }
        __syncthreads();
        #pragma unroll 8
        for (int c = 0; c < 32; c++) {
            float a[4], bb[4];
            #pragma unroll
            for (int i = 0; i < 4; i++) a[i] = Fi[tm * 4 + i][c];
            #pragma unroll
            for (int j = 0; j < 4; j++) bb[j] = Fj[tn * 4 + j][c];
            #pragma unroll
            for (int i = 0; i < 4; i++)
                #pragma unroll
                for (int j = 0; j < 4; j++) acc[i][j] += a[i] * bb[j];
        }
        __syncthreads();
    }
    #pragma unroll
    for (int i = 0; i < 4; i++) {
        int ii = i0 + tm * 4 + i;
        float xi = xx[b * NPTS + ii];
        #pragma unroll
        for (int j = 0; j < 4; j++) {
            int jj = j0 + tn * 4 + j;
            float nd = -(xi - 2.f * acc[i][j] + xx[b * NPTS + jj]);
            D[((size_t)b * NPTS + ii) * NPTS + jj] = nd;
        }
    }
}

// ---------------------------------------------------------------------------
// top-k (k=20) by repeated argmax, tie-break lower index (matches lax.top_k;
// only the SET matters downstream due to max-pool, but keep ties exact).
// ---------------------------------------------------------------------------
__global__ void topk_k(const float* __restrict__ D, int* __restrict__ idx) {
    __shared__ float nd[NPTS];
    __shared__ float bv[256];
    __shared__ int   bi[256];
    int row = blockIdx.x;
    int tid = threadIdx.x;
    for (int j = tid; j < NPTS; j += 256) nd[j] = D[(size_t)row * NPTS + j];
    __syncthreads();
    for (int it = 0; it < KNN; it++) {
        float best = NEG_BIG; int bidx = 0x7fffffff;
        for (int j = tid; j < NPTS; j += 256) {
            float v = nd[j];
            if (v > best) { best = v; bidx = j; }
        }
        bv[tid] = best; bi[tid] = bidx;
        __syncthreads();
        for (int s = 128; s > 0; s >>= 1) {
            if (tid < s) {
                float v2 = bv[tid + s]; int i2 = bi[tid + s];
                if (v2 > bv[tid] || (v2 == bv[tid] && i2 < bi[tid])) { bv[tid] = v2; bi[tid] = i2; }
            }
            __syncthreads();
        }
        if (tid == 0) { idx[row * KNN + it] = bi[0]; nd[bi[0]] = NEG_BIG; }
        __syncthreads();
    }
}

// ---------------------------------------------------------------------------
// E[(p*K+kk)][c] = F[nbr][c] - F[p][c]   (nbr is within-batch index)
// ---------------------------------------------------------------------------
__global__ void gather_k(const float* __restrict__ F, int ldf, int C,
                         const int* __restrict__ idx, float* __restrict__ E) {
    size_t tot = (size_t)MROWS * C;
    size_t l = (size_t)blockIdx.x * blockDim.x + threadIdx.x;
    if (l >= tot) return;
    int c = (int)(l % C);
    size_t r = l / C;
    int p = (int)(r / KNN);
    int b = p >> 10;
    int nbr = idx[r];
    float v = F[((size_t)(b * NPTS + nbr)) * ldf + c] - F[(size_t)p * ldf + c];
    E[l] = v;
}

// ---------------------------------------------------------------------------
// generic tiled fp32 GEMM: C(M,N) = A(M,K)*B(K,N); A lda, B ldb, C ldc.
// M,N multiples of 64 for all call sites; K arbitrary (zero-padded tiles).
// 256 threads, 64x64 block tile, 4x4 per thread.
// ---------------------------------------------------------------------------
__global__ void gemm_k(const float* __restrict__ A, int lda,
                       const float* __restrict__ B, int ldb,
                       float* __restrict__ C, int ldc,
                       int M, int N, int K) {
    __shared__ float As[16][65];
    __shared__ float Bs[16][64];
    int tid = threadIdx.x;
    int tm = tid / 16, tn = tid % 16;
    int m0 = blockIdx.y * 64;
    int n0 = blockIdx.x * 64;
    float acc[4][4];
    #pragma unroll
    for (int i = 0; i < 4; i++)
        #pragma unroll
        for (int j = 0; j < 4; j++) acc[i][j] = 0.f;

    for (int k0 = 0; k0 < K; k0 += 16) {
        for (int l = tid; l < 64 * 16; l += 256) {
            int m = l >> 4, kk = l & 15;
            As[kk][m] = (k0 + kk < K) ? A[(size_t)(m0 + m) * lda + k0 + kk] : 0.f;
        }
        for (int l = tid; l < 16 * 64; l += 256) {
            int kk = l >> 6, n = l & 63;
            Bs[kk][n] = (k0 + kk < K) ? B[(size_t)(k0 + kk) * ldb + n0 + n] : 0.f;
        }
        __syncthreads();
        #pragma unroll
        for (int kk = 0; kk < 16; kk++) {
            float a[4], b[4];
            #pragma unroll
            for (int i = 0; i < 4; i++) a[i] = As[kk][tm * 4 + i];
            #pragma unroll
            for (int j = 0; j < 4; j++) b[j] = Bs[kk][tn * 4 + j];
            #pragma unroll
            for (int i = 0; i < 4; i++)
                #pragma unroll
                for (int j = 0; j < 4; j++) acc[i][j] += a[i] * b[j];
        }
        __syncthreads();
    }
    #pragma unroll
    for (int i = 0; i < 4; i++)
        #pragma unroll
        for (int j = 0; j < 4; j++)
            C[(size_t)(m0 + tm * 4 + i) * ldc + n0 + tn * 4 + j] = acc[i][j];
}

// ---------------------------------------------------------------------------
// BN stats stage 1: per-channel sum / sumsq over row chunk.
// h = H[row][o] (+ t[row/Kn][o] if t != null)
// ---------------------------------------------------------------------------
__global__ void stats1_k(const float* __restrict__ H, const float* __restrict__ t,
                         int M, int O, int Kn, float* __restrict__ part) {
    int chunk = (M + gridDim.x - 1) / gridDim.x;
    int r0 = blockIdx.x * chunk;
    int r1 = min(M, r0 + chunk);
    for (int o = threadIdx.x; o < O; o += blockDim.x) {
        float s = 0.f, s2 = 0.f;
        if (t) {
            for (int r = r0; r < r1; r++) {
                float v = H[(size_t)r * O + o] + t[(size_t)(r / Kn) * O + o];
                s += v; s2 += v * v;
            }
        } else {
            for (int r = r0; r < r1; r++) {
                float v = H[(size_t)r * O + o];
                s += v; s2 += v * v;
            }
        }
        part[((size_t)blockIdx.x * O + o) * 2]     = s;
        part[((size_t)blockIdx.x * O + o) * 2 + 1] = s2;
    }
}

__global__ void stats2_k(const float* __restrict__ part, int npart, int O, double invM,
                         const float* __restrict__ gamma, const float* __restrict__ beta,
                         float* __restrict__ scale, float* __restrict__ shift) {
    for (int o = threadIdx.x; o < O; o += blockDim.x) {
        double s = 0.0, s2 = 0.0;
        for (int p = 0; p < npart; p++) {
            s  += part[((size_t)p * O + o) * 2];
            s2 += part[((size_t)p * O + o) * 2 + 1];
        }
        double mean = s * invM;
        double var = s2 * invM - mean * mean;
        double sc = (double)gamma[o] / sqrt(var + 1e-5);
        scale[o] = (float)sc;
        shift[o] = (float)((double)beta[o] - mean * sc);
    }
}

// ---------------------------------------------------------------------------
// apply BN + LeakyReLU, max over k, write into g_feat column block
// ---------------------------------------------------------------------------
__global__ void apply_max_k(const float* __restrict__ H, const float* __restrict__ t,
                            const float* __restrict__ scale, const float* __restrict__ shift,
                            int O, float* __restrict__ outFeat, int ldo, int colofs) {
    int p = blockIdx.x;
    for (int o = threadIdx.x; o < O; o += blockDim.x) {
        float sc = scale[o], sh = shift[o];
        float tv = t[(size_t)p * O + o];
        float best = NEG_BIG;
        #pragma unroll 4
        for (int kk = 0; kk < KNN; kk++) {
            float v = (H[((size_t)p * KNN + kk) * O + o] + tv) * sc + sh;
            v = v >= 0.f ? v : 0.2f * v;
            best = fmaxf(best, v);
        }
        outFeat[(size_t)p * ldo + colofs + o] = best;
    }
}

// ---------------------------------------------------------------------------
// conv5 pooling: per (b, o) max & mean over N of lrelu(bn(h))
// grid (4, 8), 256 threads
// ---------------------------------------------------------------------------
__global__ void pool_k(const float* __restrict__ h5, const float* __restrict__ scale,
                       const float* __restrict__ shift, float* __restrict__ pooled) {
    int b = blockIdx.y;
    int o = blockIdx.x * blockDim.x + threadIdx.x;
    float sc = scale[o], sh = shift[o];
    float mx = NEG_BIG, sm = 0.f;
    for (int n = 0; n < NPTS; n++) {
        float v = h5[((size_t)b * NPTS + n) * 1024 + o] * sc + sh;
        v = v >= 0.f ? v : 0.2f * v;
        mx = fmaxf(mx, v);
        sm += v;
    }
    pooled[b * 2048 + o] = mx;
    pooled[b * 2048 + 1024 + o] = sm * (1.f / (float)NPTS);
}

// ---------------------------------------------------------------------------
// tiny FC: Y[b][o] = sum_c X[b][c] * W[o][c] (+ bias). block per o, 128 thr.
// ---------------------------------------------------------------------------
__global__ void fc_k(const float* __restrict__ X, int bcols,
                     const float* __restrict__ W, const float* __restrict__ bias,
                     float* __restrict__ Y, int O) {
    int o = blockIdx.x;
    const float* w = W + (size_t)o * bcols;
    float acc[BATCH];
    #pragma unroll
    for (int b = 0; b < BATCH; b++) acc[b] = 0.f;
    for (int c = threadIdx.x; c < bcols; c += blockDim.x) {
        float wv = w[c];
        #pragma unroll
        for (int b = 0; b < BATCH; b++) acc[b] += X[(size_t)b * bcols + c] * wv;
    }
    #pragma unroll
    for (int b = 0; b < BATCH; b++)
        #pragma unroll
        for (int off = 16; off; off >>= 1)
            acc[b] += __shfl_down_sync(0xffffffffu, acc[b], off);
    __shared__ float sm[BATCH][4];
    int warp = threadIdx.x >> 5, lane = threadIdx.x & 31;
    if (lane == 0)
        #pragma unroll
        for (int b = 0; b < BATCH; b++) sm[b][warp] = acc[b];
    __syncthreads();
    if (threadIdx.x == 0) {
        float bs = bias ? bias[o] : 0.f;
        #pragma unroll
        for (int b = 0; b < BATCH; b++) {
            float v = sm[b][0] + sm[b][1] + sm[b][2] + sm[b][3] + bs;
            Y[(size_t)b * O + o] = v;
        }
    }
}

// BN over batch axis (8 samples) + lrelu
__global__ void bnrow_k(const float* __restrict__ Yraw, int O,
                        const float* __restrict__ gamma, const float* __restrict__ beta,
                        float* __restrict__ Yact) {
    int o = blockIdx.x * blockDim.x + threadIdx.x;
    if (o >= O) return;
    float v[BATCH];
    double s = 0.0, s2 = 0.0;
    #pragma unroll
    for (int b = 0; b < BATCH; b++) {
        v[b] = Yraw[(size_t)b * O + o];
        s += v[b]; s2 += (double)v[b] * v[b];
    }
    double mean = s / (double)BATCH;
    double var = s2 / (double)BATCH - mean * mean;
    double sc = (double)gamma[o] / sqrt(var + 1e-5);
    double sh = (double)beta[o] - mean * sc;
    #pragma unroll
    for (int b = 0; b < BATCH; b++) {
        float u = (float)((double)v[b] * sc + sh);
        Yact[(size_t)b * O + o] = u >= 0.f ? u : 0.2f * u;
    }
}

// ---------------------------------------------------------------------------
// host orchestration
// ---------------------------------------------------------------------------
static inline float* sym_addr(const void* symbol) {
    void* p = nullptr;
    cudaGetSymbolAddress(&p, symbol);
    return (float*)p;
}

extern "C" void kernel_launch(void* const* d_in, const int* in_sizes, int n_in,
                              void* d_out, int out_size) {
    const float* x   = (const float*)d_in[0];
    const float* w1  = (const float*)d_in[1];
    const float* g1  = (const float*)d_in[2];
    const float* b1  = (const float*)d_in[3];
    const float* w2  = (const float*)d_in[4];
    const float* g2  = (const float*)d_in[5];
    const float* b2  = (const float*)d_in[6];
    const float* w3  = (const float*)d_in[7];
    const float* g3  = (const float*)d_in[8];
    const float* b3  = (const float*)d_in[9];
    const float* w4  = (const float*)d_in[10];
    const float* g4  = (const float*)d_in[11];
    const float* b4  = (const float*)d_in[12];
    const float* w5  = (const float*)d_in[13];
    const float* g5  = (const float*)d_in[14];
    const float* b5  = (const float*)d_in[15];
    const float* lw1 = (const float*)d_in[16];
    const float* g6  = (const float*)d_in[17];
    const float* b6  = (const float*)d_in[18];
    const float* lw2 = (const float*)d_in[19];
    const float* lb2 = (const float*)d_in[20];
    const float* g7  = (const float*)d_in[21];
    const float* b7  = (const float*)d_in[22];
    const float* lw3 = (const float*)d_in[23];
    const float* lb3 = (const float*)d_in[24];

    float* xp    = sym_addr(g_xp);
    float* feat  = sym_addr(g_feat);
    float* D     = sym_addr(g_D);
    int*   idx   = (int*)sym_addr(g_idx);
    float* xxv   = sym_addr(g_xx);
    float* E     = sym_addr(g_E);
    float* H     = sym_addr(g_H);
    float* tbuf  = sym_addr(g_t);
    float* h5    = sym_addr(g_h5);
    float* part  = sym_addr(g_part);
    float* scale = sym_addr(g_scale);
    float* shift = sym_addr(g_shift);
    float* w1t   = sym_addr(g_w1t);
    float* w2t   = sym_addr(g_w2t);
    float* w3t   = sym_addr(g_w3t);
    float* w4t   = sym_addr(g_w4t);
    float* w5t   = sym_addr(g_w5t);
    float* pooled = sym_addr(g_pooled);
    float* fc1raw = sym_addr(g_fc1raw);
    float* fc1    = sym_addr(g_fc1);
    float* fc2raw = sym_addr(g_fc2raw);
    float* fc2    = sym_addr(g_fc2);

    transpose_x_k<<<(BATCH * NPTS * 3 + 255) / 256, 256>>>(x, xp);
    wt_k<<<(64 * 6 + 255) / 256, 256>>>(w1, 64, 6, w1t);
    wt_k<<<(64 * 128 + 255) / 256, 256>>>(w2, 64, 128, w2t);
    wt_k<<<(128 * 128 + 255) / 256, 256>>>(w3, 128, 128, w3t);
    wt_k<<<(256 * 256 + 255) / 256, 256>>>(w4, 256, 256, w4t);
    wt_k<<<(1024 * 512 + 255) / 256, 256>>>(w5, 1024, 512, w5t);

    // layer configs
    struct Cfg {
        const float* Fin; int ldf; int C; int O; int colout;
        const float* wt; const float* gamma; const float* beta;
    };
    Cfg cfgs[4] = {
        { xp,          3,   3,   64,  0,   w1t, g1, b1 },
        { feat + 0,    512, 64,  64,  64,  w2t, g2, b2 },
        { feat + 64,   512, 64,  128, 128, w3t, g3, b3 },
        { feat + 128,  512, 128, 256, 256, w4t, g4, b4 },
    };

    for (int L = 0; L < 4; L++) {
        const Cfg& c = cfgs[L];
        xx_k<<<(NPOINTS * 32 + 255) / 256, 256>>>(c.Fin, c.ldf, c.C, xxv);
        dist_k<<<dim3(16, 16, 8), 256>>>(c.Fin, c.ldf, c.C, xxv, D);
        topk_k<<<NPOINTS, 256>>>(D, idx);
        size_t tot = (size_t)MROWS * c.C;
        gather_k<<<(unsigned)((tot + 255) / 256), 256>>>(c.Fin, c.ldf, c.C, idx, E);
        // H = E * Wt[0:C]
        gemm_k<<<dim3(c.O / 64, MROWS / 64), 256>>>(E, c.C, c.wt, c.O, H, c.O,
                                                    MROWS, c.O, c.C);
        // t = F * Wt[C:2C]
        gemm_k<<<dim3(c.O / 64, NPOINTS / 64), 256>>>(c.Fin, c.ldf, c.wt + (size_t)c.C * c.O,
                                                      c.O, tbuf, c.O, NPOINTS, c.O, c.C);
        stats1_k<<<256, 256>>>(H, tbuf, MROWS, c.O, KNN, part);
        stats2_k<<<1, 256>>>(part, 256, c.O, 1.0 / (double)MROWS, c.gamma, c.beta, scale, shift);
        apply_max_k<<<NPOINTS, 256>>>(H, tbuf, scale, shift, c.O, feat, 512, c.colout);
    }

    // conv5: (8192 x 512) @ (512 x 1024)
    gemm_k<<<dim3(1024 / 64, NPOINTS / 64), 256>>>(feat, 512, w5t, 1024, h5, 1024,
                                                   NPOINTS, 1024, 512);
    stats1_k<<<256, 256>>>(h5, nullptr, NPOINTS, 1024, 1, part);
    stats2_k<<<1, 256>>>(part, 256, 1024, 1.0 / (double)NPOINTS, g5, b5, scale, shift);
    pool_k<<<dim3(4, 8), 256>>>(h5, scale, shift, pooled);

    // head
    fc_k<<<512, 128>>>(pooled, 2048, lw1, nullptr, fc1raw, 512);
    bnrow_k<<<2, 256>>>(fc1raw, 512, g6, b6, fc1);
    fc_k<<<256, 128>>>(fc1, 512, lw2, lb2, fc2raw, 256);
    bnrow_k<<<1, 256>>>(fc2raw, 256, g7, b7, fc2);
    fc_k<<<40, 128>>>(fc2, 256, lw3, lb3, (float*)d_out, 40);
}

// round 4
// speedup vs baseline: 1.5280x; 1.5280x over previous
#include <cuda_runtime.h>
#include <math.h>
#include <stdint.h>
#include <stddef.h>

// ---------------------------------------------------------------------------
// DGCNN classifier, B=8, N=1024, K=20. fp32 throughout.
// Round 4: round-2 structure with cancellation-safe edge math:
//   h = (nbr - ctr) . Wlo  +  ctr . Whi     (difference formed FIRST)
// ---------------------------------------------------------------------------

#define BATCH 8
#define NPTS 1024
#define KNN 20
#define NPOINTS (BATCH * NPTS)          // 8192
#define MROWS (NPOINTS * KNN)           // 163840
#define NEG_BIG (-3.0e38f)
#define POS_BIG (3.0e38f)

__device__ float g_xp[NPOINTS * 3];
__device__ float g_feat[NPOINTS * 512];
__device__ float g_D[(size_t)BATCH * NPTS * NPTS];      // 32 MB
__device__ int   g_idx[NPOINTS * KNN];
__device__ float g_xx[NPOINTS];
__device__ float g_t[NPOINTS * 256];                    // 8 MB
__device__ float g_max[NPOINTS * 256];
__device__ float g_min[NPOINTS * 256];
__device__ float g_h5[(size_t)NPOINTS * 1024];          // 33 MB
__device__ float g_psum[2048 * 256];
__device__ float g_psq[2048 * 256];
__device__ float g_scale[1024];
__device__ float g_shift[1024];
__device__ float g_wlot[128 * 256];
__device__ float g_whit[128 * 256];
__device__ float g_w5t[512 * 1024];
__device__ float g_pooled[BATCH * 2048];
__device__ float g_fc1raw[BATCH * 512];
__device__ float g_fc1[BATCH * 512];
__device__ float g_fc2raw[BATCH * 256];
__device__ float g_fc2[BATCH * 256];

// ---------------------------------------------------------------------------
// small utility kernels
// ---------------------------------------------------------------------------

__global__ void transpose_x_k(const float* __restrict__ x, float* __restrict__ xp) {
    int l = blockIdx.x * blockDim.x + threadIdx.x;
    if (l >= BATCH * NPTS * 3) return;
    int c = l % 3;
    int n = (l / 3) % NPTS;
    int b = l / (3 * NPTS);
    xp[l] = x[((size_t)b * 3 + c) * NPTS + n];
}

// split W (O x 2C) into Wlo^T (C x O) and Whi^T (C x O)
__global__ void wprep_k(const float* __restrict__ W, int O, int C,
                        float* __restrict__ wlot, float* __restrict__ whit) {
    int l = blockIdx.x * blockDim.x + threadIdx.x;
    if (l >= O * C) return;
    int o = l % O;
    int c = l / O;
    wlot[l] = W[(size_t)o * 2 * C + c];
    whit[l] = W[(size_t)o * 2 * C + C + c];
}

__global__ void wt_k(const float* __restrict__ W, int O, int Kc, float* __restrict__ Wt) {
    int l = blockIdx.x * blockDim.x + threadIdx.x;
    if (l >= O * Kc) return;
    int o = l % O;
    int c = l / O;
    Wt[l] = W[(size_t)o * Kc + c];
}

__global__ void xx_k(const float* __restrict__ F, int ldf, int C, float* __restrict__ xx) {
    int g = blockIdx.x * blockDim.x + threadIdx.x;
    int p = g >> 5, lane = g & 31;
    if (p >= NPOINTS) return;
    const float* f = F + (size_t)p * ldf;
    float s = 0.f;
    for (int c = lane; c < C; c += 32) { float v = f[c]; s += v * v; }
    #pragma unroll
    for (int off = 16; off; off >>= 1) s += __shfl_down_sync(0xffffffffu, s, off);
    if (lane == 0) xx[p] = s;
}

// ---------------------------------------------------------------------------
// pairwise neg-dist, 128x128 tile, 8x8 per thread, per batch
// grid (8, 8, 8), 256 threads
// ---------------------------------------------------------------------------
__global__ void dist8_k(const float* __restrict__ F, int ldf, int C,
                        const float* __restrict__ xx, float* __restrict__ D) {
    __shared__ float Fi[16][128];
    __shared__ float Fj[16][128];
    int b = blockIdx.z;
    int i0 = blockIdx.y * 128, j0 = blockIdx.x * 128;
    int tid = threadIdx.x;
    int tm = tid / 16, tn = tid % 16;
    const float* Fb = F + (size_t)b * NPTS * ldf;
    float acc[8][8];
    #pragma unroll
    for (int i = 0; i < 8; i++)
        #pragma unroll
        for (int j = 0; j < 8; j++) acc[i][j] = 0.f;

    for (int c0 = 0; c0 < C; c0 += 16) {
        #pragma unroll
        for (int q = 0; q < 8; q++) {
            int l = q * 256 + tid;
            int kk = l & 15, m = l >> 4;
            Fi[kk][m] = (c0 + kk < C) ? Fb[(size_t)(i0 + m) * ldf + c0 + kk] : 0.f;
            Fj[kk][m] = (c0 + kk < C) ? Fb[(size_t)(j0 + m) * ldf + c0 + kk] : 0.f;
        }
        __syncthreads();
        #pragma unroll
        for (int kk = 0; kk < 16; kk++) {
            float a[8], bb[8];
            *(float4*)&a[0] = *(const float4*)&Fi[kk][tm * 8];
            *(float4*)&a[4] = *(const float4*)&Fi[kk][tm * 8 + 4];
            *(float4*)&bb[0] = *(const float4*)&Fj[kk][tn * 8];
            *(float4*)&bb[4] = *(const float4*)&Fj[kk][tn * 8 + 4];
            #pragma unroll
            for (int i = 0; i < 8; i++)
                #pragma unroll
                for (int j = 0; j < 8; j++) acc[i][j] += a[i] * bb[j];
        }
        __syncthreads();
    }
    float xj[8];
    #pragma unroll
    for (int j = 0; j < 8; j++) xj[j] = xx[b * NPTS + j0 + tn * 8 + j];
    #pragma unroll
    for (int i = 0; i < 8; i++) {
        int ii = i0 + tm * 8 + i;
        float xi = xx[b * NPTS + ii];
        float out[8];
        #pragma unroll
        for (int j = 0; j < 8; j++) out[j] = -(xi - 2.f * acc[i][j] + xj[j]);
        float* dst = &D[((size_t)b * NPTS + ii) * NPTS + j0 + tn * 8];
        *(float4*)&dst[0] = *(float4*)&out[0];
        *(float4*)&dst[4] = *(float4*)&out[4];
    }
}

// ---------------------------------------------------------------------------
// warp-per-row top-20 by iterative argmax, row cached in registers.
// block 256 = 8 warps, grid NPOINTS/8
// ---------------------------------------------------------------------------
__global__ void topk_warp_k(const float* __restrict__ D, int* __restrict__ idx) {
    int warp = threadIdx.x >> 5, lane = threadIdx.x & 31;
    int row = blockIdx.x * 8 + warp;
    float vals[32];
    const float* dr = D + (size_t)row * NPTS;
    #pragma unroll
    for (int i = 0; i < 32; i++) vals[i] = dr[i * 32 + lane];

    // local best (value, slot); strictly-greater keeps lowest slot on ties
    float lbv = vals[0]; int lbi = 0;
    #pragma unroll
    for (int i = 1; i < 32; i++) if (vals[i] > lbv) { lbv = vals[i]; lbi = i; }

    for (int it = 0; it < KNN; it++) {
        float cv = lbv;
        int cg = lbi * 32 + lane;
        #pragma unroll
        for (int off = 16; off; off >>= 1) {
            float ov = __shfl_down_sync(0xffffffffu, cv, off);
            int oi = __shfl_down_sync(0xffffffffu, cg, off);
            if (ov > cv || (ov == cv && oi < cg)) { cv = ov; cg = oi; }
        }
        int winner = __shfl_sync(0xffffffffu, cg, 0);
        if (lane == 0) idx[row * KNN + it] = winner;
        if ((winner & 31) == lane) {
            int slot = winner >> 5;
            #pragma unroll
            for (int i = 0; i < 32; i++) if (i == slot) vals[i] = NEG_BIG;
            lbv = vals[0]; lbi = 0;
            #pragma unroll
            for (int i = 1; i < 32; i++) if (vals[i] > lbv) { lbv = vals[i]; lbi = i; }
        }
    }
}

// ---------------------------------------------------------------------------
// generic 64x64 tiled GEMM (for t = F * Whit): C(M,N) = A(M,K)*B(K,N)
// ---------------------------------------------------------------------------
__global__ void gemm_k(const float* __restrict__ A, int lda,
                       const float* __restrict__ B, int ldb,
                       float* __restrict__ C, int ldc,
                       int M, int N, int K) {
    __shared__ float As[16][65];
    __shared__ float Bs[16][64];
    int tid = threadIdx.x;
    int tm = tid / 16, tn = tid % 16;
    int m0 = blockIdx.y * 64;
    int n0 = blockIdx.x * 64;
    float acc[4][4];
    #pragma unroll
    for (int i = 0; i < 4; i++)
        #pragma unroll
        for (int j = 0; j < 4; j++) acc[i][j] = 0.f;

    for (int k0 = 0; k0 < K; k0 += 16) {
        for (int l = tid; l < 64 * 16; l += 256) {
            int m = l >> 4, kk = l & 15;
            As[kk][m] = (k0 + kk < K) ? A[(size_t)(m0 + m) * lda + k0 + kk] : 0.f;
        }
        for (int l = tid; l < 16 * 64; l += 256) {
            int kk = l >> 6, n = l & 63;
            Bs[kk][n] = (k0 + kk < K) ? B[(size_t)(k0 + kk) * ldb + n0 + n] : 0.f;
        }
        __syncthreads();
        #pragma unroll
        for (int kk = 0; kk < 16; kk++) {
            float a[4], b[4];
            #pragma unroll
            for (int i = 0; i < 4; i++) a[i] = As[kk][tm * 4 + i];
            #pragma unroll
            for (int j = 0; j < 4; j++) b[j] = Bs[kk][tn * 4 + j];
            #pragma unroll
            for (int i = 0; i < 4; i++)
                #pragma unroll
                for (int j = 0; j < 4; j++) acc[i][j] += a[i] * b[j];
        }
        __syncthreads();
    }
    #pragma unroll
    for (int i = 0; i < 4; i++)
        #pragma unroll
        for (int j = 0; j < 4; j++)
            C[(size_t)(m0 + tm * 4 + i) * ldc + n0 + tn * 4 + j] = acc[i][j];
}

// ---------------------------------------------------------------------------
// fused edge layer: A = (nbr - ctr) gathered on the fly, h = A.Wlo + t,
// per-point max/min over k, per-block sum/sumsq partials.
// tile = 80 rows (4 points x 20 k) x 64 cols. 320 threads, 4x4 per thread.
// grid (O/64, NPOINTS/4)
// ---------------------------------------------------------------------------
__global__ __launch_bounds__(320)
void edge_fused_k(const float* __restrict__ F, int ldf, int C, int O,
                  const int* __restrict__ idx, const float* __restrict__ wlot,
                  const float* __restrict__ t,
                  float* __restrict__ gmax, float* __restrict__ gmin,
                  float* __restrict__ psum, float* __restrict__ psq) {
    __shared__ int   sidx[80];   // neighbor row offset
    __shared__ int   sctr[80];   // center row offset
    __shared__ float As[16][80];
    __shared__ float Bs[16][64];
    __shared__ float red[20][68];

    int tid = threadIdx.x;
    int tm = tid / 16;          // 0..19, rows tm*4 .. tm*4+3
    int tn = tid % 16;          // cols tn*4 .. tn*4+3
    int blockPt = blockIdx.y;   // 4 points
    int n0 = blockIdx.x * 64;

    if (tid < 80) {
        int gp = blockPt * 4 + tid / 20;       // global point
        int b = gp >> 10;
        int nbr = idx[blockPt * 80 + tid];
        sidx[tid] = ((b << 10) + nbr) * ldf;
        sctr[tid] = gp * ldf;
    }
    __syncthreads();

    float acc[4][4];
    #pragma unroll
    for (int i = 0; i < 4; i++)
        #pragma unroll
        for (int j = 0; j < 4; j++) acc[i][j] = 0.f;

    for (int c0 = 0; c0 < C; c0 += 16) {
        #pragma unroll
        for (int q = 0; q < 4; q++) {
            int l = q * 320 + tid;
            int m = l % 80, kk = l / 80;
            int cc = c0 + kk;
            // difference formed FIRST (cancellation-safe; center row L1-resident)
            As[kk][m] = (cc < C) ? (F[(size_t)sidx[m] + cc] - F[(size_t)sctr[m] + cc]) : 0.f;
        }
        for (int l = tid; l < 1024; l += 320) {
            int kk = l >> 6, n = l & 63;
            Bs[kk][n] = (c0 + kk < C) ? wlot[(size_t)(c0 + kk) * O + n0 + n] : 0.f;
        }
        __syncthreads();
        #pragma unroll
        for (int kk = 0; kk < 16; kk++) {
            float a[4], b[4];
            *(float4*)a = *(const float4*)&As[kk][tm * 4];
            *(float4*)b = *(const float4*)&Bs[kk][tn * 4];
            #pragma unroll
            for (int i = 0; i < 4; i++)
                #pragma unroll
                for (int j = 0; j < 4; j++) acc[i][j] += a[i] * b[j];
        }
        __syncthreads();
    }

    int pLoc = tm / 5;
    int P = blockPt * 4 + pLoc;
    float4 tv = *(const float4*)&t[(size_t)P * O + n0 + tn * 4];
    float tvj[4] = { tv.x, tv.y, tv.z, tv.w };

    float vmax[4], vmin[4], vs[4], vs2[4];
    #pragma unroll
    for (int j = 0; j < 4; j++) {
        vmax[j] = NEG_BIG; vmin[j] = POS_BIG; vs[j] = 0.f; vs2[j] = 0.f;
        #pragma unroll
        for (int i = 0; i < 4; i++) {
            float v = acc[i][j] + tvj[j];
            vmax[j] = fmaxf(vmax[j], v);
            vmin[j] = fminf(vmin[j], v);
            vs[j] += v;
            vs2[j] += v * v;
        }
    }

    // pass 1: max
    #pragma unroll
    for (int j = 0; j < 4; j++) red[tm][tn * 4 + j] = vmax[j];
    __syncthreads();
    if (tm % 5 == 0) {
        #pragma unroll
        for (int j = 0; j < 4; j++) {
            int c = tn * 4 + j;
            float m = red[tm][c];
            #pragma unroll
            for (int q = 1; q < 5; q++) m = fmaxf(m, red[tm + q][c]);
            gmax[(size_t)P * O + n0 + c] = m;
        }
    }
    __syncthreads();
    // pass 2: min
    #pragma unroll
    for (int j = 0; j < 4; j++) red[tm][tn * 4 + j] = vmin[j];
    __syncthreads();
    if (tm % 5 == 0) {
        #pragma unroll
        for (int j = 0; j < 4; j++) {
            int c = tn * 4 + j;
            float m = red[tm][c];
            #pragma unroll
            for (int q = 1; q < 5; q++) m = fminf(m, red[tm + q][c]);
            gmin[(size_t)P * O + n0 + c] = m;
        }
    }
    __syncthreads();
    // pass 3: sum (over all 80 rows)
    #pragma unroll
    for (int j = 0; j < 4; j++) red[tm][tn * 4 + j] = vs[j];
    __syncthreads();
    if (tm == 0) {
        #pragma unroll
        for (int j = 0; j < 4; j++) {
            int c = tn * 4 + j;
            float s = 0.f;
            #pragma unroll
            for (int q = 0; q < 20; q++) s += red[q][c];
            psum[(size_t)blockPt * O + n0 + c] = s;
        }
    }
    __syncthreads();
    // pass 4: sumsq
    #pragma unroll
    for (int j = 0; j < 4; j++) red[tm][tn * 4 + j] = vs2[j];
    __syncthreads();
    if (tm == 0) {
        #pragma unroll
        for (int j = 0; j < 4; j++) {
            int c = tn * 4 + j;
            float s = 0.f;
            #pragma unroll
            for (int q = 0; q < 20; q++) s += red[q][c];
            psq[(size_t)blockPt * O + n0 + c] = s;
        }
    }
}

// ---------------------------------------------------------------------------
// reduce stats partials -> scale/shift. grid = O blocks, 256 threads.
// ---------------------------------------------------------------------------
__global__ void statsred_k(const float* __restrict__ psum, const float* __restrict__ psq,
                           int R, int O, double invM,
                           const float* __restrict__ gamma, const float* __restrict__ beta,
                           float* __restrict__ scale, float* __restrict__ shift) {
    int o = blockIdx.x;
    double ls = 0.0, ls2 = 0.0;
    for (int r = threadIdx.x; r < R; r += 256) {
        ls += psum[(size_t)r * O + o];
        ls2 += psq[(size_t)r * O + o];
    }
    __shared__ double sd[256], sd2[256];
    sd[threadIdx.x] = ls; sd2[threadIdx.x] = ls2;
    __syncthreads();
    for (int s = 128; s > 0; s >>= 1) {
        if (threadIdx.x < s) { sd[threadIdx.x] += sd[threadIdx.x + s]; sd2[threadIdx.x] += sd2[threadIdx.x + s]; }
        __syncthreads();
    }
    if (threadIdx.x == 0) {
        double mean = sd[0] * invM;
        double var = sd2[0] * invM - mean * mean;
        double sc = (double)gamma[o] / sqrt(var + 1e-5);
        scale[o] = (float)sc;
        shift[o] = (float)((double)beta[o] - mean * sc);
    }
}

// apply BN + lrelu to the monotone-selected extreme, write feat column block
__global__ void bnapply_k(const float* __restrict__ gmax, const float* __restrict__ gmin,
                          const float* __restrict__ scale, const float* __restrict__ shift,
                          int O, float* __restrict__ outFeat, int ldo, int colofs) {
    int l = blockIdx.x * blockDim.x + threadIdx.x;
    if (l >= NPOINTS * O) return;
    int o = l % O;
    int p = l / O;
    float sc = scale[o];
    float v = (sc >= 0.f) ? gmax[l] : gmin[l];
    float u = v * sc + shift[o];
    u = u >= 0.f ? u : 0.2f * u;
    outFeat[(size_t)p * ldo + colofs + o] = u;
}

// ---------------------------------------------------------------------------
// conv5 GEMM: 128x128 tile, 8x8 per thread, 256 threads + stats partials.
// ---------------------------------------------------------------------------
__global__ __launch_bounds__(256)
void gemm5_k(const float* __restrict__ A, int lda,
             const float* __restrict__ B, int ldb,
             float* __restrict__ C, int ldc, int K,
             float* __restrict__ psum, float* __restrict__ psq, int Ostats) {
    __shared__ float As[16][128];
    __shared__ float Bs[16][128];
    int tid = threadIdx.x;
    int tm = tid / 16, tn = tid % 16;
    int m0 = blockIdx.y * 128;
    int n0 = blockIdx.x * 128;
    float acc[8][8];
    #pragma unroll
    for (int i = 0; i < 8; i++)
        #pragma unroll
        for (int j = 0; j < 8; j++) acc[i][j] = 0.f;

    for (int k0 = 0; k0 < K; k0 += 16) {
        #pragma unroll
        for (int q = 0; q < 8; q++) {
            int l = q * 256 + tid;
            int kk = l & 15, m = l >> 4;
            As[kk][m] = A[(size_t)(m0 + m) * lda + k0 + kk];
        }
        #pragma unroll
        for (int q = 0; q < 8; q++) {
            int l = q * 256 + tid;
            int kk = l >> 7, n = l & 127;
            Bs[kk][n] = B[(size_t)(k0 + kk) * ldb + n0 + n];
        }
        __syncthreads();
        #pragma unroll
        for (int kk = 0; kk < 16; kk++) {
            float a[8], b[8];
            *(float4*)&a[0] = *(const float4*)&As[kk][tm * 8];
            *(float4*)&a[4] = *(const float4*)&As[kk][tm * 8 + 4];
            *(float4*)&b[0] = *(const float4*)&Bs[kk][tn * 8];
            *(float4*)&b[4] = *(const float4*)&Bs[kk][tn * 8 + 4];
            #pragma unroll
            for (int i = 0; i < 8; i++)
                #pragma unroll
                for (int j = 0; j < 8; j++) acc[i][j] += a[i] * b[j];
        }
        __syncthreads();
    }
    #pragma unroll
    for (int i = 0; i < 8; i++) {
        float* dst = &C[(size_t)(m0 + tm * 8 + i) * ldc + n0 + tn * 8];
        *(float4*)&dst[0] = *(float4*)&acc[i][0];
        *(float4*)&dst[4] = *(float4*)&acc[i][4];
    }
    // stats partials: reuse As as reduction buffer [16][128]
    float(*red)[128] = As;
    float cs[8], cq[8];
    #pragma unroll
    for (int j = 0; j < 8; j++) {
        cs[j] = 0.f; cq[j] = 0.f;
        #pragma unroll
        for (int i = 0; i < 8; i++) { float v = acc[i][j]; cs[j] += v; cq[j] += v * v; }
    }
    __syncthreads();
    #pragma unroll
    for (int j = 0; j < 8; j++) red[tm][tn * 8 + j] = cs[j];
    __syncthreads();
    if (tm == 0) {
        #pragma unroll
        for (int j = 0; j < 8; j++) {
            int c = tn * 8 + j;
            float s = 0.f;
            #pragma unroll
            for (int q = 0; q < 16; q++) s += red[q][c];
            psum[(size_t)blockIdx.y * Ostats + n0 + c] = s;
        }
    }
    __syncthreads();
    #pragma unroll
    for (int j = 0; j < 8; j++) red[tm][tn * 8 + j] = cq[j];
    __syncthreads();
    if (tm == 0) {
        #pragma unroll
        for (int j = 0; j < 8; j++) {
            int c = tn * 8 + j;
            float s = 0.f;
            #pragma unroll
            for (int q = 0; q < 16; q++) s += red[q][c];
            psq[(size_t)blockIdx.y * Ostats + n0 + c] = s;
        }
    }
}

// ---------------------------------------------------------------------------
// conv5 pooling: per (b, o) max & mean over N of lrelu(bn(h))
// ---------------------------------------------------------------------------
__global__ void pool_k(const float* __restrict__ h5, const float* __restrict__ scale,
                       const float* __restrict__ shift, float* __restrict__ pooled) {
    int b = blockIdx.y;
    int o = blockIdx.x * blockDim.x + threadIdx.x;
    float sc = scale[o], sh = shift[o];
    float mx = NEG_BIG, sm = 0.f;
    for (int n = 0; n < NPTS; n++) {
        float v = h5[((size_t)b * NPTS + n) * 1024 + o] * sc + sh;
        v = v >= 0.f ? v : 0.2f * v;
        mx = fmaxf(mx, v);
        sm += v;
    }
    pooled[b * 2048 + o] = mx;
    pooled[b * 2048 + 1024 + o] = sm * (1.f / (float)NPTS);
}

// ---------------------------------------------------------------------------
// tiny FC + per-batch BN
// ---------------------------------------------------------------------------
__global__ void fc_k(const float* __restrict__ X, int bcols,
                     const float* __restrict__ W, const float* __restrict__ bias,
                     float* __restrict__ Y, int O) {
    int o = blockIdx.x;
    const float* w = W + (size_t)o * bcols;
    float acc[BATCH];
    #pragma unroll
    for (int b = 0; b < BATCH; b++) acc[b] = 0.f;
    for (int c = threadIdx.x; c < bcols; c += blockDim.x) {
        float wv = w[c];
        #pragma unroll
        for (int b = 0; b < BATCH; b++) acc[b] += X[(size_t)b * bcols + c] * wv;
    }
    #pragma unroll
    for (int b = 0; b < BATCH; b++)
        #pragma unroll
        for (int off = 16; off; off >>= 1)
            acc[b] += __shfl_down_sync(0xffffffffu, acc[b], off);
    __shared__ float sm[BATCH][4];
    int warp = threadIdx.x >> 5, lane = threadIdx.x & 31;
    if (lane == 0)
        #pragma unroll
        for (int b = 0; b < BATCH; b++) sm[b][warp] = acc[b];
    __syncthreads();
    if (threadIdx.x == 0) {
        float bs = bias ? bias[o] : 0.f;
        #pragma unroll
        for (int b = 0; b < BATCH; b++)
            Y[(size_t)b * O + o] = sm[b][0] + sm[b][1] + sm[b][2] + sm[b][3] + bs;
    }
}

__global__ void bnrow_k(const float* __restrict__ Yraw, int O,
                        const float* __restrict__ gamma, const float* __restrict__ beta,
                        float* __restrict__ Yact) {
    int o = blockIdx.x * blockDim.x + threadIdx.x;
    if (o >= O) return;
    float v[BATCH];
    double s = 0.0, s2 = 0.0;
    #pragma unroll
    for (int b = 0; b < BATCH; b++) {
        v[b] = Yraw[(size_t)b * O + o];
        s += v[b]; s2 += (double)v[b] * v[b];
    }
    double mean = s / (double)BATCH;
    double var = s2 / (double)BATCH - mean * mean;
    double sc = (double)gamma[o] / sqrt(var + 1e-5);
    double sh = (double)beta[o] - mean * sc;
    #pragma unroll
    for (int b = 0; b < BATCH; b++) {
        float u = (float)((double)v[b] * sc + sh);
        Yact[(size_t)b * O + o] = u >= 0.f ? u : 0.2f * u;
    }
}

// ---------------------------------------------------------------------------
// host orchestration
// ---------------------------------------------------------------------------
static inline float* sym_addr(const void* symbol) {
    void* p = nullptr;
    cudaGetSymbolAddress(&p, symbol);
    return (float*)p;
}

extern "C" void kernel_launch(void* const* d_in, const int* in_sizes, int n_in,
                              void* d_out, int out_size) {
    const float* x   = (const float*)d_in[0];
    const float* w1  = (const float*)d_in[1];
    const float* g1  = (const float*)d_in[2];
    const float* b1  = (const float*)d_in[3];
    const float* w2  = (const float*)d_in[4];
    const float* g2  = (const float*)d_in[5];
    const float* b2  = (const float*)d_in[6];
    const float* w3  = (const float*)d_in[7];
    const float* g3  = (const float*)d_in[8];
    const float* b3  = (const float*)d_in[9];
    const float* w4  = (const float*)d_in[10];
    const float* g4  = (const float*)d_in[11];
    const float* b4  = (const float*)d_in[12];
    const float* w5  = (const float*)d_in[13];
    const float* g5  = (const float*)d_in[14];
    const float* b5  = (const float*)d_in[15];
    const float* lw1 = (const float*)d_in[16];
    const float* g6  = (const float*)d_in[17];
    const float* b6  = (const float*)d_in[18];
    const float* lw2 = (const float*)d_in[19];
    const float* lb2 = (const float*)d_in[20];
    const float* g7  = (const float*)d_in[21];
    const float* b7  = (const float*)d_in[22];
    const float* lw3 = (const float*)d_in[23];
    const float* lb3 = (const float*)d_in[24];

    float* xp    = sym_addr(g_xp);
    float* feat  = sym_addr(g_feat);
    float* D     = sym_addr(g_D);
    int*   idx   = (int*)sym_addr(g_idx);
    float* xxv   = sym_addr(g_xx);
    float* tbuf  = sym_addr(g_t);
    float* gmax  = sym_addr(g_max);
    float* gmin  = sym_addr(g_min);
    float* h5    = sym_addr(g_h5);
    float* psum  = sym_addr(g_psum);
    float* psq   = sym_addr(g_psq);
    float* scale = sym_addr(g_scale);
    float* shift = sym_addr(g_shift);
    float* wlot  = sym_addr(g_wlot);
    float* whit  = sym_addr(g_whit);
    float* w5t   = sym_addr(g_w5t);
    float* pooled = sym_addr(g_pooled);
    float* fc1raw = sym_addr(g_fc1raw);
    float* fc1    = sym_addr(g_fc1);
    float* fc2raw = sym_addr(g_fc2raw);
    float* fc2    = sym_addr(g_fc2);

    transpose_x_k<<<(BATCH * NPTS * 3 + 255) / 256, 256>>>(x, xp);
    wt_k<<<(1024 * 512 + 255) / 256, 256>>>(w5, 1024, 512, w5t);

    struct Cfg {
        const float* Fin; int ldf; int C; int O; int colout;
        const float* W; const float* gamma; const float* beta;
    };
    Cfg cfgs[4] = {
        { xp,          3,   3,   64,  0,   w1, g1, b1 },
        { feat + 0,    512, 64,  64,  64,  w2, g2, b2 },
        { feat + 64,   512, 64,  128, 128, w3, g3, b3 },
        { feat + 128,  512, 128, 256, 256, w4, g4, b4 },
    };

    for (int L = 0; L < 4; L++) {
        const Cfg& c = cfgs[L];
        wprep_k<<<(c.O * c.C + 255) / 256, 256>>>(c.W, c.O, c.C, wlot, whit);
        xx_k<<<(NPOINTS * 32 + 255) / 256, 256>>>(c.Fin, c.ldf, c.C, xxv);
        dist8_k<<<dim3(8, 8, 8), 256>>>(c.Fin, c.ldf, c.C, xxv, D);
        topk_warp_k<<<NPOINTS / 8, 256>>>(D, idx);
        // t = F * Whi^T  (NPOINTS x O)
        gemm_k<<<dim3(c.O / 64, NPOINTS / 64), 256>>>(c.Fin, c.ldf, whit, c.O,
                                                      tbuf, c.O, NPOINTS, c.O, c.C);
        edge_fused_k<<<dim3(c.O / 64, NPOINTS / 4), 320>>>(
            c.Fin, c.ldf, c.C, c.O, idx, wlot, tbuf, gmax, gmin, psum, psq);
        statsred_k<<<c.O, 256>>>(psum, psq, NPOINTS / 4, c.O, 1.0 / (double)MROWS,
                                 c.gamma, c.beta, scale, shift);
        bnapply_k<<<(NPOINTS * c.O + 255) / 256, 256>>>(gmax, gmin, scale, shift,
                                                        c.O, feat, 512, c.colout);
    }

    // conv5: (8192 x 512) @ (512 x 1024) with fused stats partials
    gemm5_k<<<dim3(1024 / 128, NPOINTS / 128), 256>>>(feat, 512, w5t, 1024, h5, 1024,
                                                      512, psum, psq, 1024);
    statsred_k<<<1024, 256>>>(psum, psq, NPOINTS / 128, 1024, 1.0 / (double)NPOINTS,
                              g5, b5, scale, shift);
    pool_k<<<dim3(4, 8), 256>>>(h5, scale, shift, pooled);

    // head
    fc_k<<<512, 128>>>(pooled, 2048, lw1, nullptr, fc1raw, 512);
    bnrow_k<<<2, 256>>>(fc1raw, 512, g6, b6, fc1);
    fc_k<<<256, 128>>>(fc1, 512, lw2, lb2, fc2raw, 256);
    bnrow_k<<<1, 256>>>(fc2raw, 256, g7, b7, fc2);
    fc_k<<<40, 128>>>(fc2, 256, lw3, lb3, (float*)d_out, 40);
}

// round 8
// speedup vs baseline: 1.5578x; 1.0195x over previous
#include <cuda_runtime.h>
#include <math.h>
#include <stdint.h>
#include <stddef.h>

// ---------------------------------------------------------------------------
// DGCNN classifier, B=8, N=1024, K=20. fp32 throughout.
// Round 8: same deltas as round 5 (4x8 edge tiles + symmetric dist,
// bit-identical accumulation orders vs round 4), but edge kernels are
// plain-named __global__ wrappers around a templated __device__ body.
// ---------------------------------------------------------------------------

#define BATCH 8
#define NPTS 1024
#define KNN 20
#define NPOINTS (BATCH * NPTS)          // 8192
#define MROWS (NPOINTS * KNN)           // 163840
#define NEG_BIG (-3.0e38f)
#define POS_BIG (3.0e38f)

__device__ float g_xp[NPOINTS * 3];
__device__ float g_feat[NPOINTS * 512];
__device__ float g_D[(size_t)BATCH * NPTS * NPTS];      // 32 MB
__device__ int   g_idx[NPOINTS * KNN];
__device__ float g_xx[NPOINTS];
__device__ float g_t[NPOINTS * 256];                    // 8 MB
__device__ float g_max[NPOINTS * 256];
__device__ float g_min[NPOINTS * 256];
__device__ float g_h5[(size_t)NPOINTS * 1024];          // 33 MB
__device__ float g_psum[2048 * 256];
__device__ float g_psq[2048 * 256];
__device__ float g_scale[1024];
__device__ float g_shift[1024];
__device__ float g_wlot[128 * 256];
__device__ float g_whit[128 * 256];
__device__ float g_w5t[512 * 1024];
__device__ float g_pooled[BATCH * 2048];
__device__ float g_fc1raw[BATCH * 512];
__device__ float g_fc1[BATCH * 512];
__device__ float g_fc2raw[BATCH * 256];
__device__ float g_fc2[BATCH * 256];

// ---------------------------------------------------------------------------
// small utility kernels
// ---------------------------------------------------------------------------

__global__ void transpose_x_k(const float* __restrict__ x, float* __restrict__ xp) {
    int l = blockIdx.x * blockDim.x + threadIdx.x;
    if (l >= BATCH * NPTS * 3) return;
    int c = l % 3;
    int n = (l / 3) % NPTS;
    int b = l / (3 * NPTS);
    xp[l] = x[((size_t)b * 3 + c) * NPTS + n];
}

// split W (O x 2C) into Wlo^T (C x O) and Whi^T (C x O)
__global__ void wprep_k(const float* __restrict__ W, int O, int C,
                        float* __restrict__ wlot, float* __restrict__ whit) {
    int l = blockIdx.x * blockDim.x + threadIdx.x;
    if (l >= O * C) return;
    int o = l % O;
    int c = l / O;
    wlot[l] = W[(size_t)o * 2 * C + c];
    whit[l] = W[(size_t)o * 2 * C + C + c];
}

__global__ void wt_k(const float* __restrict__ W, int O, int Kc, float* __restrict__ Wt) {
    int l = blockIdx.x * blockDim.x + threadIdx.x;
    if (l >= O * Kc) return;
    int o = l % O;
    int c = l / O;
    Wt[l] = W[(size_t)o * Kc + c];
}

__global__ void xx_k(const float* __restrict__ F, int ldf, int C, float* __restrict__ xx) {
    int g = blockIdx.x * blockDim.x + threadIdx.x;
    int p = g >> 5, lane = g & 31;
    if (p >= NPOINTS) return;
    const float* f = F + (size_t)p * ldf;
    float s = 0.f;
    for (int c = lane; c < C; c += 32) { float v = f[c]; s += v * v; }
    #pragma unroll
    for (int off = 16; off; off >>= 1) s += __shfl_down_sync(0xffffffffu, s, off);
    if (lane == 0) xx[p] = s;
}

// ---------------------------------------------------------------------------
// pairwise neg-dist, 128x128 tile, 8x8 per thread, per batch, SYMMETRIC:
// blocks with bj < bi exit; off-diagonal blocks write the mirror tile too.
// Value formula keeps (row_xx - 2*acc) + col_xx order for both orientations,
// so all D values are bit-identical to the full computation.
// grid (8, 8, 8), 256 threads
// ---------------------------------------------------------------------------
__global__ void dist8_k(const float* __restrict__ F, int ldf, int C,
                        const float* __restrict__ xx, float* __restrict__ D) {
    int bi = blockIdx.y, bj = blockIdx.x;
    if (bj < bi) return;
    __shared__ float Fi[16][128];
    __shared__ float Fj[16][128];
    int b = blockIdx.z;
    int i0 = bi * 128, j0 = bj * 128;
    int tid = threadIdx.x;
    int tm = tid / 16, tn = tid % 16;
    const float* Fb = F + (size_t)b * NPTS * ldf;
    float acc[8][8];
    #pragma unroll
    for (int i = 0; i < 8; i++)
        #pragma unroll
        for (int j = 0; j < 8; j++) acc[i][j] = 0.f;

    for (int c0 = 0; c0 < C; c0 += 16) {
        #pragma unroll
        for (int q = 0; q < 8; q++) {
            int l = q * 256 + tid;
            int kk = l & 15, m = l >> 4;
            Fi[kk][m] = (c0 + kk < C) ? Fb[(size_t)(i0 + m) * ldf + c0 + kk] : 0.f;
            Fj[kk][m] = (c0 + kk < C) ? Fb[(size_t)(j0 + m) * ldf + c0 + kk] : 0.f;
        }
        __syncthreads();
        #pragma unroll
        for (int kk = 0; kk < 16; kk++) {
            float a[8], bb[8];
            *(float4*)&a[0] = *(const float4*)&Fi[kk][tm * 8];
            *(float4*)&a[4] = *(const float4*)&Fi[kk][tm * 8 + 4];
            *(float4*)&bb[0] = *(const float4*)&Fj[kk][tn * 8];
            *(float4*)&bb[4] = *(const float4*)&Fj[kk][tn * 8 + 4];
            #pragma unroll
            for (int i = 0; i < 8; i++)
                #pragma unroll
                for (int j = 0; j < 8; j++) acc[i][j] += a[i] * bb[j];
        }
        __syncthreads();
    }
    float xi[8], xj[8];
    #pragma unroll
    for (int i = 0; i < 8; i++) xi[i] = xx[b * NPTS + i0 + tm * 8 + i];
    #pragma unroll
    for (int j = 0; j < 8; j++) xj[j] = xx[b * NPTS + j0 + tn * 8 + j];

    // normal tile: D[ii][jj] = -((xi - 2*acc) + xj)
    #pragma unroll
    for (int i = 0; i < 8; i++) {
        int ii = i0 + tm * 8 + i;
        float out[8];
        #pragma unroll
        for (int j = 0; j < 8; j++) out[j] = -(xi[i] - 2.f * acc[i][j] + xj[j]);
        float* dst = &D[((size_t)b * NPTS + ii) * NPTS + j0 + tn * 8];
        *(float4*)&dst[0] = *(float4*)&out[0];
        *(float4*)&dst[4] = *(float4*)&out[4];
    }
    // mirror tile: D[jj][ii] = -((xj - 2*acc) + xi)
    if (bj > bi) {
        #pragma unroll
        for (int j = 0; j < 8; j++) {
            int jj = j0 + tn * 8 + j;
            float out[8];
            #pragma unroll
            for (int i = 0; i < 8; i++) out[i] = -(xj[j] - 2.f * acc[i][j] + xi[i]);
            float* dst = &D[((size_t)b * NPTS + jj) * NPTS + i0 + tm * 8];
            *(float4*)&dst[0] = *(float4*)&out[0];
            *(float4*)&dst[4] = *(float4*)&out[4];
        }
    }
}

// ---------------------------------------------------------------------------
// warp-per-row top-20 by iterative argmax, row cached in registers.
// ---------------------------------------------------------------------------
__global__ void topk_warp_k(const float* __restrict__ D, int* __restrict__ idx) {
    int warp = threadIdx.x >> 5, lane = threadIdx.x & 31;
    int row = blockIdx.x * 8 + warp;
    float vals[32];
    const float* dr = D + (size_t)row * NPTS;
    #pragma unroll
    for (int i = 0; i < 32; i++) vals[i] = dr[i * 32 + lane];

    float lbv = vals[0]; int lbi = 0;
    #pragma unroll
    for (int i = 1; i < 32; i++) if (vals[i] > lbv) { lbv = vals[i]; lbi = i; }

    for (int it = 0; it < KNN; it++) {
        float cv = lbv;
        int cg = lbi * 32 + lane;
        #pragma unroll
        for (int off = 16; off; off >>= 1) {
            float ov = __shfl_down_sync(0xffffffffu, cv, off);
            int oi = __shfl_down_sync(0xffffffffu, cg, off);
            if (ov > cv || (ov == cv && oi < cg)) { cv = ov; cg = oi; }
        }
        int winner = __shfl_sync(0xffffffffu, cg, 0);
        if (lane == 0) idx[row * KNN + it] = winner;
        if ((winner & 31) == lane) {
            int slot = winner >> 5;
            #pragma unroll
            for (int i = 0; i < 32; i++) if (i == slot) vals[i] = NEG_BIG;
            lbv = vals[0]; lbi = 0;
            #pragma unroll
            for (int i = 1; i < 32; i++) if (vals[i] > lbv) { lbv = vals[i]; lbi = i; }
        }
    }
}

// ---------------------------------------------------------------------------
// generic 64x64 tiled GEMM (for t = F * Whit)
// ---------------------------------------------------------------------------
__global__ void gemm_k(const float* __restrict__ A, int lda,
                       const float* __restrict__ B, int ldb,
                       float* __restrict__ C, int ldc,
                       int M, int N, int K) {
    __shared__ float As[16][65];
    __shared__ float Bs[16][64];
    int tid = threadIdx.x;
    int tm = tid / 16, tn = tid % 16;
    int m0 = blockIdx.y * 64;
    int n0 = blockIdx.x * 64;
    float acc[4][4];
    #pragma unroll
    for (int i = 0; i < 4; i++)
        #pragma unroll
        for (int j = 0; j < 4; j++) acc[i][j] = 0.f;

    for (int k0 = 0; k0 < K; k0 += 16) {
        for (int l = tid; l < 64 * 16; l += 256) {
            int m = l >> 4, kk = l & 15;
            As[kk][m] = (k0 + kk < K) ? A[(size_t)(m0 + m) * lda + k0 + kk] : 0.f;
        }
        for (int l = tid; l < 16 * 64; l += 256) {
            int kk = l >> 6, n = l & 63;
            Bs[kk][n] = (k0 + kk < K) ? B[(size_t)(k0 + kk) * ldb + n0 + n] : 0.f;
        }
        __syncthreads();
        #pragma unroll
        for (int kk = 0; kk < 16; kk++) {
            float a[4], b[4];
            #pragma unroll
            for (int i = 0; i < 4; i++) a[i] = As[kk][tm * 4 + i];
            #pragma unroll
            for (int j = 0; j < 4; j++) b[j] = Bs[kk][tn * 4 + j];
            #pragma unroll
            for (int i = 0; i < 4; i++)
                #pragma unroll
                for (int j = 0; j < 4; j++) acc[i][j] += a[i] * b[j];
        }
        __syncthreads();
    }
    #pragma unroll
    for (int i = 0; i < 4; i++)
        #pragma unroll
        for (int j = 0; j < 4; j++)
            C[(size_t)(m0 + tm * 4 + i) * ldc + n0 + tn * 4 + j] = acc[i][j];
}

// ---------------------------------------------------------------------------
// fused edge layer body (device-inline, templated column width).
// tile = 80 rows x (16*TNC) cols, 320 threads, each 4 rows x TNC cols.
// Per-output accumulation order identical to the round-4 4x4 version.
// ---------------------------------------------------------------------------
template <int TNC>
__device__ __forceinline__
void edge_fused_body(const float* __restrict__ F, int ldf, int C, int O,
                     const int* __restrict__ idx, const float* __restrict__ wlot,
                     const float* __restrict__ t,
                     float* __restrict__ gmax, float* __restrict__ gmin,
                     float* __restrict__ psum, float* __restrict__ psq) {
    constexpr int NCOLS = 16 * TNC;
    __shared__ int   sidx[80];
    __shared__ int   sctr[80];
    __shared__ float As[16][80];
    __shared__ float Bs[16][NCOLS];
    __shared__ float red[20][NCOLS + 4];

    int tid = threadIdx.x;
    int tm = tid / 16;          // 0..19, rows tm*4 .. tm*4+3
    int tn = tid % 16;          // cols tn*TNC ..
    int blockPt = blockIdx.y;   // 4 points
    int n0 = blockIdx.x * NCOLS;

    if (tid < 80) {
        int gp = blockPt * 4 + tid / 20;
        int b = gp >> 10;
        int nbr = idx[blockPt * 80 + tid];
        sidx[tid] = ((b << 10) + nbr) * ldf;
        sctr[tid] = gp * ldf;
    }
    __syncthreads();

    float acc[4][TNC];
    #pragma unroll
    for (int i = 0; i < 4; i++)
        #pragma unroll
        for (int j = 0; j < TNC; j++) acc[i][j] = 0.f;

    for (int c0 = 0; c0 < C; c0 += 16) {
        #pragma unroll
        for (int q = 0; q < 4; q++) {
            int l = q * 320 + tid;
            int m = l % 80, kk = l / 80;
            int cc = c0 + kk;
            As[kk][m] = (cc < C) ? (F[(size_t)sidx[m] + cc] - F[(size_t)sctr[m] + cc]) : 0.f;
        }
        for (int l = tid; l < 16 * NCOLS; l += 320) {
            int kk = l / NCOLS, n = l % NCOLS;
            Bs[kk][n] = (c0 + kk < C) ? wlot[(size_t)(c0 + kk) * O + n0 + n] : 0.f;
        }
        __syncthreads();
        #pragma unroll
        for (int kk = 0; kk < 16; kk++) {
            float a[4], b[TNC];
            *(float4*)a = *(const float4*)&As[kk][tm * 4];
            #pragma unroll
            for (int v = 0; v < TNC / 4; v++)
                *(float4*)&b[v * 4] = *(const float4*)&Bs[kk][tn * TNC + v * 4];
            #pragma unroll
            for (int i = 0; i < 4; i++)
                #pragma unroll
                for (int j = 0; j < TNC; j++) acc[i][j] += a[i] * b[j];
        }
        __syncthreads();
    }

    int P = blockPt * 4 + tm / 5;
    float tvj[TNC];
    #pragma unroll
    for (int v = 0; v < TNC / 4; v++)
        *(float4*)&tvj[v * 4] = *(const float4*)&t[(size_t)P * O + n0 + tn * TNC + v * 4];

    float vmax[TNC], vmin[TNC], vs[TNC], vs2[TNC];
    #pragma unroll
    for (int j = 0; j < TNC; j++) {
        vmax[j] = NEG_BIG; vmin[j] = POS_BIG; vs[j] = 0.f; vs2[j] = 0.f;
        #pragma unroll
        for (int i = 0; i < 4; i++) {
            float v = acc[i][j] + tvj[j];
            vmax[j] = fmaxf(vmax[j], v);
            vmin[j] = fminf(vmin[j], v);
            vs[j] += v;
            vs2[j] += v * v;
        }
    }

    // pass 1: max
    #pragma unroll
    for (int j = 0; j < TNC; j++) red[tm][tn * TNC + j] = vmax[j];
    __syncthreads();
    if (tm % 5 == 0) {
        #pragma unroll
        for (int j = 0; j < TNC; j++) {
            int c = tn * TNC + j;
            float m = red[tm][c];
            #pragma unroll
            for (int q = 1; q < 5; q++) m = fmaxf(m, red[tm + q][c]);
            gmax[(size_t)P * O + n0 + c] = m;
        }
    }
    __syncthreads();
    // pass 2: min
    #pragma unroll
    for (int j = 0; j < TNC; j++) red[tm][tn * TNC + j] = vmin[j];
    __syncthreads();
    if (tm % 5 == 0) {
        #pragma unroll
        for (int j = 0; j < TNC; j++) {
            int c = tn * TNC + j;
            float m = red[tm][c];
            #pragma unroll
            for (int q = 1; q < 5; q++) m = fminf(m, red[tm + q][c]);
            gmin[(size_t)P * O + n0 + c] = m;
        }
    }
    __syncthreads();
    // pass 3: sum over all 80 rows
    #pragma unroll
    for (int j = 0; j < TNC; j++) red[tm][tn * TNC + j] = vs[j];
    __syncthreads();
    if (tm == 0) {
        #pragma unroll
        for (int j = 0; j < TNC; j++) {
            int c = tn * TNC + j;
            float s = 0.f;
            #pragma unroll
            for (int q = 0; q < 20; q++) s += red[q][c];
            psum[(size_t)blockPt * O + n0 + c] = s;
        }
    }
    __syncthreads();
    // pass 4: sumsq
    #pragma unroll
    for (int j = 0; j < TNC; j++) red[tm][tn * TNC + j] = vs2[j];
    __syncthreads();
    if (tm == 0) {
        #pragma unroll
        for (int j = 0; j < TNC; j++) {
            int c = tn * TNC + j;
            float s = 0.f;
            #pragma unroll
            for (int q = 0; q < 20; q++) s += red[q][c];
            psq[(size_t)blockPt * O + n0 + c] = s;
        }
    }
}

// plain-named wrappers (no templated __global__ symbols)
__global__ __launch_bounds__(320)
void edge_fused4_k(const float* __restrict__ F, int ldf, int C, int O,
                   const int* __restrict__ idx, const float* __restrict__ wlot,
                   const float* __restrict__ t,
                   float* __restrict__ gmax, float* __restrict__ gmin,
                   float* __restrict__ psum, float* __restrict__ psq) {
    edge_fused_body<4>(F, ldf, C, O, idx, wlot, t, gmax, gmin, psum, psq);
}

__global__ __launch_bounds__(320)
void edge_fused8_k(const float* __restrict__ F, int ldf, int C, int O,
                   const int* __restrict__ idx, const float* __restrict__ wlot,
                   const float* __restrict__ t,
                   float* __restrict__ gmax, float* __restrict__ gmin,
                   float* __restrict__ psum, float* __restrict__ psq) {
    edge_fused_body<8>(F, ldf, C, O, idx, wlot, t, gmax, gmin, psum, psq);
}

// ---------------------------------------------------------------------------
// reduce stats partials -> scale/shift
// ---------------------------------------------------------------------------
__global__ void statsred_k(const float* __restrict__ psum, const float* __restrict__ psq,
                           int R, int O, double invM,
                           const float* __restrict__ gamma, const float* __restrict__ beta,
                           float* __restrict__ scale, float* __restrict__ shift) {
    int o = blockIdx.x;
    double ls = 0.0, ls2 = 0.0;
    for (int r = threadIdx.x; r < R; r += 256) {
        ls += psum[(size_t)r * O + o];
        ls2 += psq[(size_t)r * O + o];
    }
    __shared__ double sd[256], sd2[256];
    sd[threadIdx.x] = ls; sd2[threadIdx.x] = ls2;
    __syncthreads();
    for (int s = 128; s > 0; s >>= 1) {
        if (threadIdx.x < s) { sd[threadIdx.x] += sd[threadIdx.x + s]; sd2[threadIdx.x] += sd2[threadIdx.x + s]; }
        __syncthreads();
    }
    if (threadIdx.x == 0) {
        double mean = sd[0] * invM;
        double var = sd2[0] * invM - mean * mean;
        double sc = (double)gamma[o] / sqrt(var + 1e-5);
        scale[o] = (float)sc;
        shift[o] = (float)((double)beta[o] - mean * sc);
    }
}

__global__ void bnapply_k(const float* __restrict__ gmax, const float* __restrict__ gmin,
                          const float* __restrict__ scale, const float* __restrict__ shift,
                          int O, float* __restrict__ outFeat, int ldo, int colofs) {
    int l = blockIdx.x * blockDim.x + threadIdx.x;
    if (l >= NPOINTS * O) return;
    int o = l % O;
    int p = l / O;
    float sc = scale[o];
    float v = (sc >= 0.f) ? gmax[l] : gmin[l];
    float u = v * sc + shift[o];
    u = u >= 0.f ? u : 0.2f * u;
    outFeat[(size_t)p * ldo + colofs + o] = u;
}

// ---------------------------------------------------------------------------
// conv5 GEMM: 128x128 tile, 8x8 per thread + stats partials
// ---------------------------------------------------------------------------
__global__ __launch_bounds__(256)
void gemm5_k(const float* __restrict__ A, int lda,
             const float* __restrict__ B, int ldb,
             float* __restrict__ C, int ldc, int K,
             float* __restrict__ psum, float* __restrict__ psq, int Ostats) {
    __shared__ float As[16][128];
    __shared__ float Bs[16][128];
    int tid = threadIdx.x;
    int tm = tid / 16, tn = tid % 16;
    int m0 = blockIdx.y * 128;
    int n0 = blockIdx.x * 128;
    float acc[8][8];
    #pragma unroll
    for (int i = 0; i < 8; i++)
        #pragma unroll
        for (int j = 0; j < 8; j++) acc[i][j] = 0.f;

    for (int k0 = 0; k0 < K; k0 += 16) {
        #pragma unroll
        for (int q = 0; q < 8; q++) {
            int l = q * 256 + tid;
            int kk = l & 15, m = l >> 4;
            As[kk][m] = A[(size_t)(m0 + m) * lda + k0 + kk];
        }
        #pragma unroll
        for (int q = 0; q < 8; q++) {
            int l = q * 256 + tid;
            int kk = l >> 7, n = l & 127;
            Bs[kk][n] = B[(size_t)(k0 + kk) * ldb + n0 + n];
        }
        __syncthreads();
        #pragma unroll
        for (int kk = 0; kk < 16; kk++) {
            float a[8], b[8];
            *(float4*)&a[0] = *(const float4*)&As[kk][tm * 8];
            *(float4*)&a[4] = *(const float4*)&As[kk][tm * 8 + 4];
            *(float4*)&b[0] = *(const float4*)&Bs[kk][tn * 8];
            *(float4*)&b[4] = *(const float4*)&Bs[kk][tn * 8 + 4];
            #pragma unroll
            for (int i = 0; i < 8; i++)
                #pragma unroll
                for (int j = 0; j < 8; j++) acc[i][j] += a[i] * b[j];
        }
        __syncthreads();
    }
    #pragma unroll
    for (int i = 0; i < 8; i++) {
        float* dst = &C[(size_t)(m0 + tm * 8 + i) * ldc + n0 + tn * 8];
        *(float4*)&dst[0] = *(float4*)&acc[i][0];
        *(float4*)&dst[4] = *(float4*)&acc[i][4];
    }
    float(*red)[128] = As;
    float cs[8], cq[8];
    #pragma unroll
    for (int j = 0; j < 8; j++) {
        cs[j] = 0.f; cq[j] = 0.f;
        #pragma unroll
        for (int i = 0; i < 8; i++) { float v = acc[i][j]; cs[j] += v; cq[j] += v * v; }
    }
    __syncthreads();
    #pragma unroll
    for (int j = 0; j < 8; j++) red[tm][tn * 8 + j] = cs[j];
    __syncthreads();
    if (tm == 0) {
        #pragma unroll
        for (int j = 0; j < 8; j++) {
            int c = tn * 8 + j;
            float s = 0.f;
            #pragma unroll
            for (int q = 0; q < 16; q++) s += red[q][c];
            psum[(size_t)blockIdx.y * Ostats + n0 + c] = s;
        }
    }
    __syncthreads();
    #pragma unroll
    for (int j = 0; j < 8; j++) red[tm][tn * 8 + j] = cq[j];
    __syncthreads();
    if (tm == 0) {
        #pragma unroll
        for (int j = 0; j < 8; j++) {
            int c = tn * 8 + j;
            float s = 0.f;
            #pragma unroll
            for (int q = 0; q < 16; q++) s += red[q][c];
            psq[(size_t)blockIdx.y * Ostats + n0 + c] = s;
        }
    }
}

// ---------------------------------------------------------------------------
// conv5 pooling
// ---------------------------------------------------------------------------
__global__ void pool_k(const float* __restrict__ h5, const float* __restrict__ scale,
                       const float* __restrict__ shift, float* __restrict__ pooled) {
    int b = blockIdx.y;
    int o = blockIdx.x * blockDim.x + threadIdx.x;
    float sc = scale[o], sh = shift[o];
    float mx = NEG_BIG, sm = 0.f;
    for (int n = 0; n < NPTS; n++) {
        float v = h5[((size_t)b * NPTS + n) * 1024 + o] * sc + sh;
        v = v >= 0.f ? v : 0.2f * v;
        mx = fmaxf(mx, v);
        sm += v;
    }
    pooled[b * 2048 + o] = mx;
    pooled[b * 2048 + 1024 + o] = sm * (1.f / (float)NPTS);
}

// ---------------------------------------------------------------------------
// tiny FC + per-batch BN
// ---------------------------------------------------------------------------
__global__ void fc_k(const float* __restrict__ X, int bcols,
                     const float* __restrict__ W, const float* __restrict__ bias,
                     float* __restrict__ Y, int O) {
    int o = blockIdx.x;
    const float* w = W + (size_t)o * bcols;
    float acc[BATCH];
    #pragma unroll
    for (int b = 0; b < BATCH; b++) acc[b] = 0.f;
    for (int c = threadIdx.x; c < bcols; c += blockDim.x) {
        float wv = w[c];
        #pragma unroll
        for (int b = 0; b < BATCH; b++) acc[b] += X[(size_t)b * bcols + c] * wv;
    }
    #pragma unroll
    for (int b = 0; b < BATCH; b++)
        #pragma unroll
        for (int off = 16; off; off >>= 1)
            acc[b] += __shfl_down_sync(0xffffffffu, acc[b], off);
    __shared__ float sm[BATCH][4];
    int warp = threadIdx.x >> 5, lane = threadIdx.x & 31;
    if (lane == 0)
        #pragma unroll
        for (int b = 0; b < BATCH; b++) sm[b][warp] = acc[b];
    __syncthreads();
    if (threadIdx.x == 0) {
        float bs = bias ? bias[o] : 0.f;
        #pragma unroll
        for (int b = 0; b < BATCH; b++)
            Y[(size_t)b * O + o] = sm[b][0] + sm[b][1] + sm[b][2] + sm[b][3] + bs;
    }
}

__global__ void bnrow_k(const float* __restrict__ Yraw, int O,
                        const float* __restrict__ gamma, const float* __restrict__ beta,
                        float* __restrict__ Yact) {
    int o = blockIdx.x * blockDim.x + threadIdx.x;
    if (o >= O) return;
    float v[BATCH];
    double s = 0.0, s2 = 0.0;
    #pragma unroll
    for (int b = 0; b < BATCH; b++) {
        v[b] = Yraw[(size_t)b * O + o];
        s += v[b]; s2 += (double)v[b] * v[b];
    }
    double mean = s / (double)BATCH;
    double var = s2 / (double)BATCH - mean * mean;
    double sc = (double)gamma[o] / sqrt(var + 1e-5);
    double sh = (double)beta[o] - mean * sc;
    #pragma unroll
    for (int b = 0; b < BATCH; b++) {
        float u = (float)((double)v[b] * sc + sh);
        Yact[(size_t)b * O + o] = u >= 0.f ? u : 0.2f * u;
    }
}

// ---------------------------------------------------------------------------
// host orchestration
// ---------------------------------------------------------------------------
static inline float* sym_addr(const void* symbol) {
    void* p = nullptr;
    cudaGetSymbolAddress(&p, symbol);
    return (float*)p;
}

extern "C" void kernel_launch(void* const* d_in, const int* in_sizes, int n_in,
                              void* d_out, int out_size) {
    const float* x   = (const float*)d_in[0];
    const float* w1  = (const float*)d_in[1];
    const float* g1  = (const float*)d_in[2];
    const float* b1  = (const float*)d_in[3];
    const float* w2  = (const float*)d_in[4];
    const float* g2  = (const float*)d_in[5];
    const float* b2  = (const float*)d_in[6];
    const float* w3  = (const float*)d_in[7];
    const float* g3  = (const float*)d_in[8];
    const float* b3  = (const float*)d_in[9];
    const float* w4  = (const float*)d_in[10];
    const float* g4  = (const float*)d_in[11];
    const float* b4  = (const float*)d_in[12];
    const float* w5  = (const float*)d_in[13];
    const float* g5  = (const float*)d_in[14];
    const float* b5  = (const float*)d_in[15];
    const float* lw1 = (const float*)d_in[16];
    const float* g6  = (const float*)d_in[17];
    const float* b6  = (const float*)d_in[18];
    const float* lw2 = (const float*)d_in[19];
    const float* lb2 = (const float*)d_in[20];
    const float* g7  = (const float*)d_in[21];
    const float* b7  = (const float*)d_in[22];
    const float* lw3 = (const float*)d_in[23];
    const float* lb3 = (const float*)d_in[24];

    float* xp    = sym_addr(g_xp);
    float* feat  = sym_addr(g_feat);
    float* D     = sym_addr(g_D);
    int*   idx   = (int*)sym_addr(g_idx);
    float* xxv   = sym_addr(g_xx);
    float* tbuf  = sym_addr(g_t);
    float* gmax  = sym_addr(g_max);
    float* gmin  = sym_addr(g_min);
    float* h5    = sym_addr(g_h5);
    float* psum  = sym_addr(g_psum);
    float* psq   = sym_addr(g_psq);
    float* scale = sym_addr(g_scale);
    float* shift = sym_addr(g_shift);
    float* wlot  = sym_addr(g_wlot);
    float* whit  = sym_addr(g_whit);
    float* w5t   = sym_addr(g_w5t);
    float* pooled = sym_addr(g_pooled);
    float* fc1raw = sym_addr(g_fc1raw);
    float* fc1    = sym_addr(g_fc1);
    float* fc2raw = sym_addr(g_fc2raw);
    float* fc2    = sym_addr(g_fc2);

    transpose_x_k<<<(BATCH * NPTS * 3 + 255) / 256, 256>>>(x, xp);
    wt_k<<<(1024 * 512 + 255) / 256, 256>>>(w5, 1024, 512, w5t);

    struct Cfg {
        const float* Fin; int ldf; int C; int O; int colout;
        const float* W; const float* gamma; const float* beta;
    };
    Cfg cfgs[4] = {
        { xp,          3,   3,   64,  0,   w1, g1, b1 },
        { feat + 0,    512, 64,  64,  64,  w2, g2, b2 },
        { feat + 64,   512, 64,  128, 128, w3, g3, b3 },
        { feat + 128,  512, 128, 256, 256, w4, g4, b4 },
    };

    for (int L = 0; L < 4; L++) {
        const Cfg& c = cfgs[L];
        wprep_k<<<(c.O * c.C + 255) / 256, 256>>>(c.W, c.O, c.C, wlot, whit);
        xx_k<<<(NPOINTS * 32 + 255) / 256, 256>>>(c.Fin, c.ldf, c.C, xxv);
        dist8_k<<<dim3(8, 8, 8), 256>>>(c.Fin, c.ldf, c.C, xxv, D);
        topk_warp_k<<<NPOINTS / 8, 256>>>(D, idx);
        gemm_k<<<dim3(c.O / 64, NPOINTS / 64), 256>>>(c.Fin, c.ldf, whit, c.O,
                                                      tbuf, c.O, NPOINTS, c.O, c.C);
        if (c.O >= 128) {
            edge_fused8_k<<<dim3(c.O / 128, NPOINTS / 4), 320>>>(
                c.Fin, c.ldf, c.C, c.O, idx, wlot, tbuf, gmax, gmin, psum, psq);
        } else {
            edge_fused4_k<<<dim3(c.O / 64, NPOINTS / 4), 320>>>(
                c.Fin, c.ldf, c.C, c.O, idx, wlot, tbuf, gmax, gmin, psum, psq);
        }
        statsred_k<<<c.O, 256>>>(psum, psq, NPOINTS / 4, c.O, 1.0 / (double)MROWS,
                                 c.gamma, c.beta, scale, shift);
        bnapply_k<<<(NPOINTS * c.O + 255) / 256, 256>>>(gmax, gmin, scale, shift,
                                                        c.O, feat, 512, c.colout);
    }

    // conv5: (8192 x 512) @ (512 x 1024) with fused stats partials
    gemm5_k<<<dim3(1024 / 128, NPOINTS / 128), 256>>>(feat, 512, w5t, 1024, h5, 1024,
                                                      512, psum, psq, 1024);
    statsred_k<<<1024, 256>>>(psum, psq, NPOINTS / 128, 1024, 1.0 / (double)NPOINTS,
                              g5, b5, scale, shift);
    pool_k<<<dim3(4, 8), 256>>>(h5, scale, shift, pooled);

    // head
    fc_k<<<512, 128>>>(pooled, 2048, lw1, nullptr, fc1raw, 512);
    bnrow_k<<<2, 256>>>(fc1raw, 512, g6, b6, fc1);
    fc_k<<<256, 128>>>(fc1, 512, lw2, lb2, fc2raw, 256);
    bnrow_k<<<1, 256>>>(fc2raw, 256, g7, b7, fc2);
    fc_k<<<40, 128>>>(fc2, 256, lw3, lb3, (float*)d_out, 40);
}

// round 9
// speedup vs baseline: 1.7299x; 1.1105x over previous
#include <cuda_runtime.h>
#include <math.h>
#include <stdint.h>
#include <stddef.h>

// ---------------------------------------------------------------------------
// DGCNN classifier, B=8, N=1024, K=20. fp32 throughout.
// Round 9: coalesced float4 edge-gather (8x less sector traffic).
// All loaded values identical -> outputs bit-identical to rounds 4/8.
// ---------------------------------------------------------------------------

#define BATCH 8
#define NPTS 1024
#define KNN 20
#define NPOINTS (BATCH * NPTS)          // 8192
#define MROWS (NPOINTS * KNN)           // 163840
#define NEG_BIG (-3.0e38f)
#define POS_BIG (3.0e38f)

__device__ float g_xp[NPOINTS * 3];
__device__ float g_feat[NPOINTS * 512];
__device__ float g_D[(size_t)BATCH * NPTS * NPTS];      // 32 MB
__device__ int   g_idx[NPOINTS * KNN];
__device__ float g_xx[NPOINTS];
__device__ float g_t[NPOINTS * 256];                    // 8 MB
__device__ float g_max[NPOINTS * 256];
__device__ float g_min[NPOINTS * 256];
__device__ float g_h5[(size_t)NPOINTS * 1024];          // 33 MB
__device__ float g_psum[2048 * 256];
__device__ float g_psq[2048 * 256];
__device__ float g_scale[1024];
__device__ float g_shift[1024];
__device__ float g_wlot[128 * 256];
__device__ float g_whit[128 * 256];
__device__ float g_w5t[512 * 1024];
__device__ float g_pooled[BATCH * 2048];
__device__ float g_fc1raw[BATCH * 512];
__device__ float g_fc1[BATCH * 512];
__device__ float g_fc2raw[BATCH * 256];
__device__ float g_fc2[BATCH * 256];

// ---------------------------------------------------------------------------
// small utility kernels
// ---------------------------------------------------------------------------

__global__ void transpose_x_k(const float* __restrict__ x, float* __restrict__ xp) {
    int l = blockIdx.x * blockDim.x + threadIdx.x;
    if (l >= BATCH * NPTS * 3) return;
    int c = l % 3;
    int n = (l / 3) % NPTS;
    int b = l / (3 * NPTS);
    xp[l] = x[((size_t)b * 3 + c) * NPTS + n];
}

// split W (O x 2C) into Wlo^T (C x O) and Whi^T (C x O)
__global__ void wprep_k(const float* __restrict__ W, int O, int C,
                        float* __restrict__ wlot, float* __restrict__ whit) {
    int l = blockIdx.x * blockDim.x + threadIdx.x;
    if (l >= O * C) return;
    int o = l % O;
    int c = l / O;
    wlot[l] = W[(size_t)o * 2 * C + c];
    whit[l] = W[(size_t)o * 2 * C + C + c];
}

__global__ void wt_k(const float* __restrict__ W, int O, int Kc, float* __restrict__ Wt) {
    int l = blockIdx.x * blockDim.x + threadIdx.x;
    if (l >= O * Kc) return;
    int o = l % O;
    int c = l / O;
    Wt[l] = W[(size_t)o * Kc + c];
}

__global__ void xx_k(const float* __restrict__ F, int ldf, int C, float* __restrict__ xx) {
    int g = blockIdx.x * blockDim.x + threadIdx.x;
    int p = g >> 5, lane = g & 31;
    if (p >= NPOINTS) return;
    const float* f = F + (size_t)p * ldf;
    float s = 0.f;
    for (int c = lane; c < C; c += 32) { float v = f[c]; s += v * v; }
    #pragma unroll
    for (int off = 16; off; off >>= 1) s += __shfl_down_sync(0xffffffffu, s, off);
    if (lane == 0) xx[p] = s;
}

// ---------------------------------------------------------------------------
// pairwise neg-dist, 128x128 tile, 8x8 per thread, per batch, SYMMETRIC
// ---------------------------------------------------------------------------
__global__ void dist8_k(const float* __restrict__ F, int ldf, int C,
                        const float* __restrict__ xx, float* __restrict__ D) {
    int bi = blockIdx.y, bj = blockIdx.x;
    if (bj < bi) return;
    __shared__ float Fi[16][128];
    __shared__ float Fj[16][128];
    int b = blockIdx.z;
    int i0 = bi * 128, j0 = bj * 128;
    int tid = threadIdx.x;
    int tm = tid / 16, tn = tid % 16;
    const float* Fb = F + (size_t)b * NPTS * ldf;
    float acc[8][8];
    #pragma unroll
    for (int i = 0; i < 8; i++)
        #pragma unroll
        for (int j = 0; j < 8; j++) acc[i][j] = 0.f;

    for (int c0 = 0; c0 < C; c0 += 16) {
        #pragma unroll
        for (int q = 0; q < 8; q++) {
            int l = q * 256 + tid;
            int kk = l & 15, m = l >> 4;
            Fi[kk][m] = (c0 + kk < C) ? Fb[(size_t)(i0 + m) * ldf + c0 + kk] : 0.f;
            Fj[kk][m] = (c0 + kk < C) ? Fb[(size_t)(j0 + m) * ldf + c0 + kk] : 0.f;
        }
        __syncthreads();
        #pragma unroll
        for (int kk = 0; kk < 16; kk++) {
            float a[8], bb[8];
            *(float4*)&a[0] = *(const float4*)&Fi[kk][tm * 8];
            *(float4*)&a[4] = *(const float4*)&Fi[kk][tm * 8 + 4];
            *(float4*)&bb[0] = *(const float4*)&Fj[kk][tn * 8];
            *(float4*)&bb[4] = *(const float4*)&Fj[kk][tn * 8 + 4];
            #pragma unroll
            for (int i = 0; i < 8; i++)
                #pragma unroll
                for (int j = 0; j < 8; j++) acc[i][j] += a[i] * bb[j];
        }
        __syncthreads();
    }
    float xi[8], xj[8];
    #pragma unroll
    for (int i = 0; i < 8; i++) xi[i] = xx[b * NPTS + i0 + tm * 8 + i];
    #pragma unroll
    for (int j = 0; j < 8; j++) xj[j] = xx[b * NPTS + j0 + tn * 8 + j];

    #pragma unroll
    for (int i = 0; i < 8; i++) {
        int ii = i0 + tm * 8 + i;
        float out[8];
        #pragma unroll
        for (int j = 0; j < 8; j++) out[j] = -(xi[i] - 2.f * acc[i][j] + xj[j]);
        float* dst = &D[((size_t)b * NPTS + ii) * NPTS + j0 + tn * 8];
        *(float4*)&dst[0] = *(float4*)&out[0];
        *(float4*)&dst[4] = *(float4*)&out[4];
    }
    if (bj > bi) {
        #pragma unroll
        for (int j = 0; j < 8; j++) {
            int jj = j0 + tn * 8 + j;
            float out[8];
            #pragma unroll
            for (int i = 0; i < 8; i++) out[i] = -(xj[j] - 2.f * acc[i][j] + xi[i]);
            float* dst = &D[((size_t)b * NPTS + jj) * NPTS + i0 + tm * 8];
            *(float4*)&dst[0] = *(float4*)&out[0];
            *(float4*)&dst[4] = *(float4*)&out[4];
        }
    }
}

// ---------------------------------------------------------------------------
// warp-per-row top-20 by iterative argmax, row cached in registers.
// ---------------------------------------------------------------------------
__global__ void topk_warp_k(const float* __restrict__ D, int* __restrict__ idx) {
    int warp = threadIdx.x >> 5, lane = threadIdx.x & 31;
    int row = blockIdx.x * 8 + warp;
    float vals[32];
    const float* dr = D + (size_t)row * NPTS;
    #pragma unroll
    for (int i = 0; i < 32; i++) vals[i] = dr[i * 32 + lane];

    float lbv = vals[0]; int lbi = 0;
    #pragma unroll
    for (int i = 1; i < 32; i++) if (vals[i] > lbv) { lbv = vals[i]; lbi = i; }

    for (int it = 0; it < KNN; it++) {
        float cv = lbv;
        int cg = lbi * 32 + lane;
        #pragma unroll
        for (int off = 16; off; off >>= 1) {
            float ov = __shfl_down_sync(0xffffffffu, cv, off);
            int oi = __shfl_down_sync(0xffffffffu, cg, off);
            if (ov > cv || (ov == cv && oi < cg)) { cv = ov; cg = oi; }
        }
        int winner = __shfl_sync(0xffffffffu, cg, 0);
        if (lane == 0) idx[row * KNN + it] = winner;
        if ((winner & 31) == lane) {
            int slot = winner >> 5;
            #pragma unroll
            for (int i = 0; i < 32; i++) if (i == slot) vals[i] = NEG_BIG;
            lbv = vals[0]; lbi = 0;
            #pragma unroll
            for (int i = 1; i < 32; i++) if (vals[i] > lbv) { lbv = vals[i]; lbi = i; }
        }
    }
}

// ---------------------------------------------------------------------------
// generic 64x64 tiled GEMM (for t = F * Whit)
// ---------------------------------------------------------------------------
__global__ void gemm_k(const float* __restrict__ A, int lda,
                       const float* __restrict__ B, int ldb,
                       float* __restrict__ C, int ldc,
                       int M, int N, int K) {
    __shared__ float As[16][65];
    __shared__ float Bs[16][64];
    int tid = threadIdx.x;
    int tm = tid / 16, tn = tid % 16;
    int m0 = blockIdx.y * 64;
    int n0 = blockIdx.x * 64;
    float acc[4][4];
    #pragma unroll
    for (int i = 0; i < 4; i++)
        #pragma unroll
        for (int j = 0; j < 4; j++) acc[i][j] = 0.f;

    for (int k0 = 0; k0 < K; k0 += 16) {
        for (int l = tid; l < 64 * 16; l += 256) {
            int m = l >> 4, kk = l & 15;
            As[kk][m] = (k0 + kk < K) ? A[(size_t)(m0 + m) * lda + k0 + kk] : 0.f;
        }
        for (int l = tid; l < 16 * 64; l += 256) {
            int kk = l >> 6, n = l & 63;
            Bs[kk][n] = (k0 + kk < K) ? B[(size_t)(k0 + kk) * ldb + n0 + n] : 0.f;
        }
        __syncthreads();
        #pragma unroll
        for (int kk = 0; kk < 16; kk++) {
            float a[4], b[4];
            #pragma unroll
            for (int i = 0; i < 4; i++) a[i] = As[kk][tm * 4 + i];
            #pragma unroll
            for (int j = 0; j < 4; j++) b[j] = Bs[kk][tn * 4 + j];
            #pragma unroll
            for (int i = 0; i < 4; i++)
                #pragma unroll
                for (int j = 0; j < 4; j++) acc[i][j] += a[i] * b[j];
        }
        __syncthreads();
    }
    #pragma unroll
    for (int i = 0; i < 4; i++)
        #pragma unroll
        for (int j = 0; j < 4; j++)
            C[(size_t)(m0 + tm * 4 + i) * ldc + n0 + tn * 4 + j] = acc[i][j];
}

// ---------------------------------------------------------------------------
// fused edge layer body (device-inline, templated column width).
// tile = 80 rows x (16*TNC) cols, 320 threads, each 4 rows x TNC cols.
// Gather: coalesced float4 path when C%16==0 (layers 2-4), scalar otherwise.
// Loaded values identical either way -> bit-identical results.
// ---------------------------------------------------------------------------
template <int TNC>
__device__ __forceinline__
void edge_fused_body(const float* __restrict__ F, int ldf, int C, int O,
                     const int* __restrict__ idx, const float* __restrict__ wlot,
                     const float* __restrict__ t,
                     float* __restrict__ gmax, float* __restrict__ gmin,
                     float* __restrict__ psum, float* __restrict__ psq) {
    constexpr int NCOLS = 16 * TNC;
    __shared__ int   sidx[80];
    __shared__ int   sctr[80];
    __shared__ float As[16][80];
    __shared__ float Bs[16][NCOLS];
    __shared__ float red[20][NCOLS + 4];

    int tid = threadIdx.x;
    int tm = tid / 16;          // 0..19, rows tm*4 .. tm*4+3
    int tn = tid % 16;          // cols tn*TNC ..
    int blockPt = blockIdx.y;   // 4 points
    int n0 = blockIdx.x * NCOLS;

    if (tid < 80) {
        int gp = blockPt * 4 + tid / 20;
        int b = gp >> 10;
        int nbr = idx[blockPt * 80 + tid];
        sidx[tid] = ((b << 10) + nbr) * ldf;
        sctr[tid] = gp * ldf;
    }
    __syncthreads();

    const bool vec = (C % 16 == 0);
    int gm = tid >> 2;          // 0..79, row for vector gather
    int gc = (tid & 3) * 4;     // channel sub-offset 0,4,8,12

    float acc[4][TNC];
    #pragma unroll
    for (int i = 0; i < 4; i++)
        #pragma unroll
        for (int j = 0; j < TNC; j++) acc[i][j] = 0.f;

    for (int c0 = 0; c0 < C; c0 += 16) {
        if (vec) {
            // coalesced: each thread loads 4 consecutive channels of one row
            float4 vn = *(const float4*)&F[(size_t)sidx[gm] + c0 + gc];
            float4 vc = *(const float4*)&F[(size_t)sctr[gm] + c0 + gc];
            As[gc + 0][gm] = vn.x - vc.x;
            As[gc + 1][gm] = vn.y - vc.y;
            As[gc + 2][gm] = vn.z - vc.z;
            As[gc + 3][gm] = vn.w - vc.w;
        } else {
            #pragma unroll
            for (int q = 0; q < 4; q++) {
                int l = q * 320 + tid;
                int m = l % 80, kk = l / 80;
                int cc = c0 + kk;
                As[kk][m] = (cc < C) ? (F[(size_t)sidx[m] + cc] - F[(size_t)sctr[m] + cc]) : 0.f;
            }
        }
        for (int l = tid; l < 16 * NCOLS; l += 320) {
            int kk = l / NCOLS, n = l % NCOLS;
            Bs[kk][n] = (c0 + kk < C) ? wlot[(size_t)(c0 + kk) * O + n0 + n] : 0.f;
        }
        __syncthreads();
        #pragma unroll
        for (int kk = 0; kk < 16; kk++) {
            float a[4], b[TNC];
            *(float4*)a = *(const float4*)&As[kk][tm * 4];
            #pragma unroll
            for (int v = 0; v < TNC / 4; v++)
                *(float4*)&b[v * 4] = *(const float4*)&Bs[kk][tn * TNC + v * 4];
            #pragma unroll
            for (int i = 0; i < 4; i++)
                #pragma unroll
                for (int j = 0; j < TNC; j++) acc[i][j] += a[i] * b[j];
        }
        __syncthreads();
    }

    int P = blockPt * 4 + tm / 5;
    float tvj[TNC];
    #pragma unroll
    for (int v = 0; v < TNC / 4; v++)
        *(float4*)&tvj[v * 4] = *(const float4*)&t[(size_t)P * O + n0 + tn * TNC + v * 4];

    float vmax[TNC], vmin[TNC], vs[TNC], vs2[TNC];
    #pragma unroll
    for (int j = 0; j < TNC; j++) {
        vmax[j] = NEG_BIG; vmin[j] = POS_BIG; vs[j] = 0.f; vs2[j] = 0.f;
        #pragma unroll
        for (int i = 0; i < 4; i++) {
            float v = acc[i][j] + tvj[j];
            vmax[j] = fmaxf(vmax[j], v);
            vmin[j] = fminf(vmin[j], v);
            vs[j] += v;
            vs2[j] += v * v;
        }
    }

    // pass 1: max
    #pragma unroll
    for (int j = 0; j < TNC; j++) red[tm][tn * TNC + j] = vmax[j];
    __syncthreads();
    if (tm % 5 == 0) {
        #pragma unroll
        for (int j = 0; j < TNC; j++) {
            int c = tn * TNC + j;
            float m = red[tm][c];
            #pragma unroll
            for (int q = 1; q < 5; q++) m = fmaxf(m, red[tm + q][c]);
            gmax[(size_t)P * O + n0 + c] = m;
        }
    }
    __syncthreads();
    // pass 2: min
    #pragma unroll
    for (int j = 0; j < TNC; j++) red[tm][tn * TNC + j] = vmin[j];
    __syncthreads();
    if (tm % 5 == 0) {
        #pragma unroll
        for (int j = 0; j < TNC; j++) {
            int c = tn * TNC + j;
            float m = red[tm][c];
            #pragma unroll
            for (int q = 1; q < 5; q++) m = fminf(m, red[tm + q][c]);
            gmin[(size_t)P * O + n0 + c] = m;
        }
    }
    __syncthreads();
    // pass 3: sum over all 80 rows
    #pragma unroll
    for (int j = 0; j < TNC; j++) red[tm][tn * TNC + j] = vs[j];
    __syncthreads();
    if (tm == 0) {
        #pragma unroll
        for (int j = 0; j < TNC; j++) {
            int c = tn * TNC + j;
            float s = 0.f;
            #pragma unroll
            for (int q = 0; q < 20; q++) s += red[q][c];
            psum[(size_t)blockPt * O + n0 + c] = s;
        }
    }
    __syncthreads();
    // pass 4: sumsq
    #pragma unroll
    for (int j = 0; j < TNC; j++) red[tm][tn * TNC + j] = vs2[j];
    __syncthreads();
    if (tm == 0) {
        #pragma unroll
        for (int j = 0; j < TNC; j++) {
            int c = tn * TNC + j;
            float s = 0.f;
            #pragma unroll
            for (int q = 0; q < 20; q++) s += red[q][c];
            psq[(size_t)blockPt * O + n0 + c] = s;
        }
    }
}

// plain-named wrappers
__global__ __launch_bounds__(320)
void edge_fused4_k(const float* __restrict__ F, int ldf, int C, int O,
                   const int* __restrict__ idx, const float* __restrict__ wlot,
                   const float* __restrict__ t,
                   float* __restrict__ gmax, float* __restrict__ gmin,
                   float* __restrict__ psum, float* __restrict__ psq) {
    edge_fused_body<4>(F, ldf, C, O, idx, wlot, t, gmax, gmin, psum, psq);
}

__global__ __launch_bounds__(320)
void edge_fused8_k(const float* __restrict__ F, int ldf, int C, int O,
                   const int* __restrict__ idx, const float* __restrict__ wlot,
                   const float* __restrict__ t,
                   float* __restrict__ gmax, float* __restrict__ gmin,
                   float* __restrict__ psum, float* __restrict__ psq) {
    edge_fused_body<8>(F, ldf, C, O, idx, wlot, t, gmax, gmin, psum, psq);
}

// ---------------------------------------------------------------------------
// reduce stats partials -> scale/shift
// ---------------------------------------------------------------------------
__global__ void statsred_k(const float* __restrict__ psum, const float* __restrict__ psq,
                           int R, int O, double invM,
                           const float* __restrict__ gamma, const float* __restrict__ beta,
                           float* __restrict__ scale, float* __restrict__ shift) {
    int o = blockIdx.x;
    double ls = 0.0, ls2 = 0.0;
    for (int r = threadIdx.x; r < R; r += 256) {
        ls += psum[(size_t)r * O + o];
        ls2 += psq[(size_t)r * O + o];
    }
    __shared__ double sd[256], sd2[256];
    sd[threadIdx.x] = ls; sd2[threadIdx.x] = ls2;
    __syncthreads();
    for (int s = 128; s > 0; s >>= 1) {
        if (threadIdx.x < s) { sd[threadIdx.x] += sd[threadIdx.x + s]; sd2[threadIdx.x] += sd2[threadIdx.x + s]; }
        __syncthreads();
    }
    if (threadIdx.x == 0) {
        double mean = sd[0] * invM;
        double var = sd2[0] * invM - mean * mean;
        double sc = (double)gamma[o] / sqrt(var + 1e-5);
        scale[o] = (float)sc;
        shift[o] = (float)((double)beta[o] - mean * sc);
    }
}

__global__ void bnapply_k(const float* __restrict__ gmax, const float* __restrict__ gmin,
                          const float* __restrict__ scale, const float* __restrict__ shift,
                          int O, float* __restrict__ outFeat, int ldo, int colofs) {
    int l = blockIdx.x * blockDim.x + threadIdx.x;
    if (l >= NPOINTS * O) return;
    int o = l % O;
    int p = l / O;
    float sc = scale[o];
    float v = (sc >= 0.f) ? gmax[l] : gmin[l];
    float u = v * sc + shift[o];
    u = u >= 0.f ? u : 0.2f * u;
    outFeat[(size_t)p * ldo + colofs + o] = u;
}

// ---------------------------------------------------------------------------
// conv5 GEMM: 128x128 tile, 8x8 per thread + stats partials
// ---------------------------------------------------------------------------
__global__ __launch_bounds__(256)
void gemm5_k(const float* __restrict__ A, int lda,
             const float* __restrict__ B, int ldb,
             float* __restrict__ C, int ldc, int K,
             float* __restrict__ psum, float* __restrict__ psq, int Ostats) {
    __shared__ float As[16][128];
    __shared__ float Bs[16][128];
    int tid = threadIdx.x;
    int tm = tid / 16, tn = tid % 16;
    int m0 = blockIdx.y * 128;
    int n0 = blockIdx.x * 128;
    float acc[8][8];
    #pragma unroll
    for (int i = 0; i < 8; i++)
        #pragma unroll
        for (int j = 0; j < 8; j++) acc[i][j] = 0.f;

    for (int k0 = 0; k0 < K; k0 += 16) {
        #pragma unroll
        for (int q = 0; q < 8; q++) {
            int l = q * 256 + tid;
            int kk = l & 15, m = l >> 4;
            As[kk][m] = A[(size_t)(m0 + m) * lda + k0 + kk];
        }
        #pragma unroll
        for (int q = 0; q < 8; q++) {
            int l = q * 256 + tid;
            int kk = l >> 7, n = l & 127;
            Bs[kk][n] = B[(size_t)(k0 + kk) * ldb + n0 + n];
        }
        __syncthreads();
        #pragma unroll
        for (int kk = 0; kk < 16; kk++) {
            float a[8], b[8];
            *(float4*)&a[0] = *(const float4*)&As[kk][tm * 8];
            *(float4*)&a[4] = *(const float4*)&As[kk][tm * 8 + 4];
            *(float4*)&b[0] = *(const float4*)&Bs[kk][tn * 8];
            *(float4*)&b[4] = *(const float4*)&Bs[kk][tn * 8 + 4];
            #pragma unroll
            for (int i = 0; i < 8; i++)
                #pragma unroll
                for (int j = 0; j < 8; j++) acc[i][j] += a[i] * b[j];
        }
        __syncthreads();
    }
    #pragma unroll
    for (int i = 0; i < 8; i++) {
        float* dst = &C[(size_t)(m0 + tm * 8 + i) * ldc + n0 + tn * 8];
        *(float4*)&dst[0] = *(float4*)&acc[i][0];
        *(float4*)&dst[4] = *(float4*)&acc[i][4];
    }
    float(*red)[128] = As;
    float cs[8], cq[8];
    #pragma unroll
    for (int j = 0; j < 8; j++) {
        cs[j] = 0.f; cq[j] = 0.f;
        #pragma unroll
        for (int i = 0; i < 8; i++) { float v = acc[i][j]; cs[j] += v; cq[j] += v * v; }
    }
    __syncthreads();
    #pragma unroll
    for (int j = 0; j < 8; j++) red[tm][tn * 8 + j] = cs[j];
    __syncthreads();
    if (tm == 0) {
        #pragma unroll
        for (int j = 0; j < 8; j++) {
            int c = tn * 8 + j;
            float s = 0.f;
            #pragma unroll
            for (int q = 0; q < 16; q++) s += red[q][c];
            psum[(size_t)blockIdx.y * Ostats + n0 + c] = s;
        }
    }
    __syncthreads();
    #pragma unroll
    for (int j = 0; j < 8; j++) red[tm][tn * 8 + j] = cq[j];
    __syncthreads();
    if (tm == 0) {
        #pragma unroll
        for (int j = 0; j < 8; j++) {
            int c = tn * 8 + j;
            float s = 0.f;
            #pragma unroll
            for (int q = 0; q < 16; q++) s += red[q][c];
            psq[(size_t)blockIdx.y * Ostats + n0 + c] = s;
        }
    }
}

// ---------------------------------------------------------------------------
// conv5 pooling
// ---------------------------------------------------------------------------
__global__ void pool_k(const float* __restrict__ h5, const float* __restrict__ scale,
                       const float* __restrict__ shift, float* __restrict__ pooled) {
    int b = blockIdx.y;
    int o = blockIdx.x * blockDim.x + threadIdx.x;
    float sc = scale[o], sh = shift[o];
    float mx = NEG_BIG, sm = 0.f;
    for (int n = 0; n < NPTS; n++) {
        float v = h5[((size_t)b * NPTS + n) * 1024 + o] * sc + sh;
        v = v >= 0.f ? v : 0.2f * v;
        mx = fmaxf(mx, v);
        sm += v;
    }
    pooled[b * 2048 + o] = mx;
    pooled[b * 2048 + 1024 + o] = sm * (1.f / (float)NPTS);
}

// ---------------------------------------------------------------------------
// tiny FC + per-batch BN
// ---------------------------------------------------------------------------
__global__ void fc_k(const float* __restrict__ X, int bcols,
                     const float* __restrict__ W, const float* __restrict__ bias,
                     float* __restrict__ Y, int O) {
    int o = blockIdx.x;
    const float* w = W + (size_t)o * bcols;
    float acc[BATCH];
    #pragma unroll
    for (int b = 0; b < BATCH; b++) acc[b] = 0.f;
    for (int c = threadIdx.x; c < bcols; c += blockDim.x) {
        float wv = w[c];
        #pragma unroll
        for (int b = 0; b < BATCH; b++) acc[b] += X[(size_t)b * bcols + c] * wv;
    }
    #pragma unroll
    for (int b = 0; b < BATCH; b++)
        #pragma unroll
        for (int off = 16; off; off >>= 1)
            acc[b] += __shfl_down_sync(0xffffffffu, acc[b], off);
    __shared__ float sm[BATCH][4];
    int warp = threadIdx.x >> 5, lane = threadIdx.x & 31;
    if (lane == 0)
        #pragma unroll
        for (int b = 0; b < BATCH; b++) sm[b][warp] = acc[b];
    __syncthreads();
    if (threadIdx.x == 0) {
        float bs = bias ? bias[o] : 0.f;
        #pragma unroll
        for (int b = 0; b < BATCH; b++)
            Y[(size_t)b * O + o] = sm[b][0] + sm[b][1] + sm[b][2] + sm[b][3] + bs;
    }
}

__global__ void bnrow_k(const float* __restrict__ Yraw, int O,
                        const float* __restrict__ gamma, const float* __restrict__ beta,
                        float* __restrict__ Yact) {
    int o = blockIdx.x * blockDim.x + threadIdx.x;
    if (o >= O) return;
    float v[BATCH];
    double s = 0.0, s2 = 0.0;
    #pragma unroll
    for (int b = 0; b < BATCH; b++) {
        v[b] = Yraw[(size_t)b * O + o];
        s += v[b]; s2 += (double)v[b] * v[b];
    }
    double mean = s / (double)BATCH;
    double var = s2 / (double)BATCH - mean * mean;
    double sc = (double)gamma[o] / sqrt(var + 1e-5);
    double sh = (double)beta[o] - mean * sc;
    #pragma unroll
    for (int b = 0; b < BATCH; b++) {
        float u = (float)((double)v[b] * sc + sh);
        Yact[(size_t)b * O + o] = u >= 0.f ? u : 0.2f * u;
    }
}

// ---------------------------------------------------------------------------
// host orchestration
// ---------------------------------------------------------------------------
static inline float* sym_addr(const void* symbol) {
    void* p = nullptr;
    cudaGetSymbolAddress(&p, symbol);
    return (float*)p;
}

extern "C" void kernel_launch(void* const* d_in, const int* in_sizes, int n_in,
                              void* d_out, int out_size) {
    const float* x   = (const float*)d_in[0];
    const float* w1  = (const float*)d_in[1];
    const float* g1  = (const float*)d_in[2];
    const float* b1  = (const float*)d_in[3];
    const float* w2  = (const float*)d_in[4];
    const float* g2  = (const float*)d_in[5];
    const float* b2  = (const float*)d_in[6];
    const float* w3  = (const float*)d_in[7];
    const float* g3  = (const float*)d_in[8];
    const float* b3  = (const float*)d_in[9];
    const float* w4  = (const float*)d_in[10];
    const float* g4  = (const float*)d_in[11];
    const float* b4  = (const float*)d_in[12];
    const float* w5  = (const float*)d_in[13];
    const float* g5  = (const float*)d_in[14];
    const float* b5  = (const float*)d_in[15];
    const float* lw1 = (const float*)d_in[16];
    const float* g6  = (const float*)d_in[17];
    const float* b6  = (const float*)d_in[18];
    const float* lw2 = (const float*)d_in[19];
    const float* lb2 = (const float*)d_in[20];
    const float* g7  = (const float*)d_in[21];
    const float* b7  = (const float*)d_in[22];
    const float* lw3 = (const float*)d_in[23];
    const float* lb3 = (const float*)d_in[24];

    float* xp    = sym_addr(g_xp);
    float* feat  = sym_addr(g_feat);
    float* D     = sym_addr(g_D);
    int*   idx   = (int*)sym_addr(g_idx);
    float* xxv   = sym_addr(g_xx);
    float* tbuf  = sym_addr(g_t);
    float* gmax  = sym_addr(g_max);
    float* gmin  = sym_addr(g_min);
    float* h5    = sym_addr(g_h5);
    float* psum  = sym_addr(g_psum);
    float* psq   = sym_addr(g_psq);
    float* scale = sym_addr(g_scale);
    float* shift = sym_addr(g_shift);
    float* wlot  = sym_addr(g_wlot);
    float* whit  = sym_addr(g_whit);
    float* w5t   = sym_addr(g_w5t);
    float* pooled = sym_addr(g_pooled);
    float* fc1raw = sym_addr(g_fc1raw);
    float* fc1    = sym_addr(g_fc1);
    float* fc2raw = sym_addr(g_fc2raw);
    float* fc2    = sym_addr(g_fc2);

    transpose_x_k<<<(BATCH * NPTS * 3 + 255) / 256, 256>>>(x, xp);
    wt_k<<<(1024 * 512 + 255) / 256, 256>>>(w5, 1024, 512, w5t);

    struct Cfg {
        const float* Fin; int ldf; int C; int O; int colout;
        const float* W; const float* gamma; const float* beta;
    };
    Cfg cfgs[4] = {
        { xp,          3,   3,   64,  0,   w1, g1, b1 },
        { feat + 0,    512, 64,  64,  64,  w2, g2, b2 },
        { feat + 64,   512, 64,  128, 128, w3, g3, b3 },
        { feat + 128,  512, 128, 256, 256, w4, g4, b4 },
    };

    for (int L = 0; L < 4; L++) {
        const Cfg& c = cfgs[L];
        wprep_k<<<(c.O * c.C + 255) / 256, 256>>>(c.W, c.O, c.C, wlot, whit);
        xx_k<<<(NPOINTS * 32 + 255) / 256, 256>>>(c.Fin, c.ldf, c.C, xxv);
        dist8_k<<<dim3(8, 8, 8), 256>>>(c.Fin, c.ldf, c.C, xxv, D);
        topk_warp_k<<<NPOINTS / 8, 256>>>(D, idx);
        gemm_k<<<dim3(c.O / 64, NPOINTS / 64), 256>>>(c.Fin, c.ldf, whit, c.O,
                                                      tbuf, c.O, NPOINTS, c.O, c.C);
        if (c.O >= 128) {
            edge_fused8_k<<<dim3(c.O / 128, NPOINTS / 4), 320>>>(
                c.Fin, c.ldf, c.C, c.O, idx, wlot, tbuf, gmax, gmin, psum, psq);
        } else {
            edge_fused4_k<<<dim3(c.O / 64, NPOINTS / 4), 320>>>(
                c.Fin, c.ldf, c.C, c.O, idx, wlot, tbuf, gmax, gmin, psum, psq);
        }
        statsred_k<<<c.O, 256>>>(psum, psq, NPOINTS / 4, c.O, 1.0 / (double)MROWS,
                                 c.gamma, c.beta, scale, shift);
        bnapply_k<<<(NPOINTS * c.O + 255) / 256, 256>>>(gmax, gmin, scale, shift,
                                                        c.O, feat, 512, c.colout);
    }

    // conv5: (8192 x 512) @ (512 x 1024) with fused stats partials
    gemm5_k<<<dim3(1024 / 128, NPOINTS / 128), 256>>>(feat, 512, w5t, 1024, h5, 1024,
                                                      512, psum, psq, 1024);
    statsred_k<<<1024, 256>>>(psum, psq, NPOINTS / 128, 1024, 1.0 / (double)NPOINTS,
                              g5, b5, scale, shift);
    pool_k<<<dim3(4, 8), 256>>>(h5, scale, shift, pooled);

    // head
    fc_k<<<512, 128>>>(pooled, 2048, lw1, nullptr, fc1raw, 512);
    bnrow_k<<<2, 256>>>(fc1raw, 512, g6, b6, fc1);
    fc_k<<<256, 128>>>(fc1, 512, lw2, lb2, fc2raw, 256);
    bnrow_k<<<1, 256>>>(fc2raw, 256, g7, b7, fc2);
    fc_k<<<40, 128>>>(fc2, 256, lw3, lb3, (float*)d_out, 40);
}

// round 11
// speedup vs baseline: 1.7553x; 1.0147x over previous
#include <cuda_runtime.h>
#include <math.h>
#include <stdint.h>
#include <stddef.h>

// ---------------------------------------------------------------------------
// DGCNN classifier, B=8, N=1024, K=20. fp32 throughout.
// Round 10: double-buffered (software-pipelined) edge / dist / conv5 kernels.
// Load values + accumulation orders identical -> bit-identical outputs.
// ---------------------------------------------------------------------------

#define BATCH 8
#define NPTS 1024
#define KNN 20
#define NPOINTS (BATCH * NPTS)          // 8192
#define MROWS (NPOINTS * KNN)           // 163840
#define NEG_BIG (-3.0e38f)
#define POS_BIG (3.0e38f)

__device__ float g_xp[NPOINTS * 3];
__device__ float g_feat[NPOINTS * 512];
__device__ float g_D[(size_t)BATCH * NPTS * NPTS];      // 32 MB
__device__ int   g_idx[NPOINTS * KNN];
__device__ float g_xx[NPOINTS];
__device__ float g_t[NPOINTS * 256];                    // 8 MB
__device__ float g_max[NPOINTS * 256];
__device__ float g_min[NPOINTS * 256];
__device__ float g_h5[(size_t)NPOINTS * 1024];          // 33 MB
__device__ float g_psum[2048 * 256];
__device__ float g_psq[2048 * 256];
__device__ float g_scale[1024];
__device__ float g_shift[1024];
__device__ float g_wlot[128 * 256];
__device__ float g_whit[128 * 256];
__device__ float g_w5t[512 * 1024];
__device__ float g_pooled[BATCH * 2048];
__device__ float g_fc1raw[BATCH * 512];
__device__ float g_fc1[BATCH * 512];
__device__ float g_fc2raw[BATCH * 256];
__device__ float g_fc2[BATCH * 256];

// ---------------------------------------------------------------------------
// small utility kernels
// ---------------------------------------------------------------------------

__global__ void transpose_x_k(const float* __restrict__ x, float* __restrict__ xp) {
    int l = blockIdx.x * blockDim.x + threadIdx.x;
    if (l >= BATCH * NPTS * 3) return;
    int c = l % 3;
    int n = (l / 3) % NPTS;
    int b = l / (3 * NPTS);
    xp[l] = x[((size_t)b * 3 + c) * NPTS + n];
}

__global__ void wprep_k(const float* __restrict__ W, int O, int C,
                        float* __restrict__ wlot, float* __restrict__ whit) {
    int l = blockIdx.x * blockDim.x + threadIdx.x;
    if (l >= O * C) return;
    int o = l % O;
    int c = l / O;
    wlot[l] = W[(size_t)o * 2 * C + c];
    whit[l] = W[(size_t)o * 2 * C + C + c];
}

__global__ void wt_k(const float* __restrict__ W, int O, int Kc, float* __restrict__ Wt) {
    int l = blockIdx.x * blockDim.x + threadIdx.x;
    if (l >= O * Kc) return;
    int o = l % O;
    int c = l / O;
    Wt[l] = W[(size_t)o * Kc + c];
}

__global__ void xx_k(const float* __restrict__ F, int ldf, int C, float* __restrict__ xx) {
    int g = blockIdx.x * blockDim.x + threadIdx.x;
    int p = g >> 5, lane = g & 31;
    if (p >= NPOINTS) return;
    const float* f = F + (size_t)p * ldf;
    float s = 0.f;
    for (int c = lane; c < C; c += 32) { float v = f[c]; s += v * v; }
    #pragma unroll
    for (int off = 16; off; off >>= 1) s += __shfl_down_sync(0xffffffffu, s, off);
    if (lane == 0) xx[p] = s;
}

// ---------------------------------------------------------------------------
// pairwise neg-dist, 128x128 tile, 8x8 per thread, SYMMETRIC, double-buffered
// ---------------------------------------------------------------------------
__global__ __launch_bounds__(256)
void dist8_k(const float* __restrict__ F, int ldf, int C,
             const float* __restrict__ xx, float* __restrict__ D) {
    int bi = blockIdx.y, bj = blockIdx.x;
    if (bj < bi) return;
    __shared__ float Fi[2][16][128];
    __shared__ float Fj[2][16][128];
    int b = blockIdx.z;
    int i0 = bi * 128, j0 = bj * 128;
    int tid = threadIdx.x;
    int tm = tid / 16, tn = tid % 16;
    const float* Fb = F + (size_t)b * NPTS * ldf;
    float acc[8][8];
    #pragma unroll
    for (int i = 0; i < 8; i++)
        #pragma unroll
        for (int j = 0; j < 8; j++) acc[i][j] = 0.f;

    int nch = (C + 15) / 16;

    // load chunk 0
    #pragma unroll
    for (int q = 0; q < 8; q++) {
        int l = q * 256 + tid;
        int kk = l & 15, m = l >> 4;
        Fi[0][kk][m] = (kk < C) ? Fb[(size_t)(i0 + m) * ldf + kk] : 0.f;
        Fj[0][kk][m] = (kk < C) ? Fb[(size_t)(j0 + m) * ldf + kk] : 0.f;
    }
    __syncthreads();

    for (int ch = 0; ch < nch; ch++) {
        int cur = ch & 1;
        if (ch + 1 < nch) {
            int c0 = (ch + 1) * 16;
            int nxt = cur ^ 1;
            #pragma unroll
            for (int q = 0; q < 8; q++) {
                int l = q * 256 + tid;
                int kk = l & 15, m = l >> 4;
                Fi[nxt][kk][m] = (c0 + kk < C) ? Fb[(size_t)(i0 + m) * ldf + c0 + kk] : 0.f;
                Fj[nxt][kk][m] = (c0 + kk < C) ? Fb[(size_t)(j0 + m) * ldf + c0 + kk] : 0.f;
            }
        }
        #pragma unroll
        for (int kk = 0; kk < 16; kk++) {
            float a[8], bb[8];
            *(float4*)&a[0] = *(const float4*)&Fi[cur][kk][tm * 8];
            *(float4*)&a[4] = *(const float4*)&Fi[cur][kk][tm * 8 + 4];
            *(float4*)&bb[0] = *(const float4*)&Fj[cur][kk][tn * 8];
            *(float4*)&bb[4] = *(const float4*)&Fj[cur][kk][tn * 8 + 4];
            #pragma unroll
            for (int i = 0; i < 8; i++)
                #pragma unroll
                for (int j = 0; j < 8; j++) acc[i][j] += a[i] * bb[j];
        }
        __syncthreads();
    }
    float xi[8], xj[8];
    #pragma unroll
    for (int i = 0; i < 8; i++) xi[i] = xx[b * NPTS + i0 + tm * 8 + i];
    #pragma unroll
    for (int j = 0; j < 8; j++) xj[j] = xx[b * NPTS + j0 + tn * 8 + j];

    #pragma unroll
    for (int i = 0; i < 8; i++) {
        int ii = i0 + tm * 8 + i;
        float out[8];
        #pragma unroll
        for (int j = 0; j < 8; j++) out[j] = -(xi[i] - 2.f * acc[i][j] + xj[j]);
        float* dst = &D[((size_t)b * NPTS + ii) * NPTS + j0 + tn * 8];
        *(float4*)&dst[0] = *(float4*)&out[0];
        *(float4*)&dst[4] = *(float4*)&out[4];
    }
    if (bj > bi) {
        #pragma unroll
        for (int j = 0; j < 8; j++) {
            int jj = j0 + tn * 8 + j;
            float out[8];
            #pragma unroll
            for (int i = 0; i < 8; i++) out[i] = -(xj[j] - 2.f * acc[i][j] + xi[i]);
            float* dst = &D[((size_t)b * NPTS + jj) * NPTS + i0 + tm * 8];
            *(float4*)&dst[0] = *(float4*)&out[0];
            *(float4*)&dst[4] = *(float4*)&out[4];
        }
    }
}

// ---------------------------------------------------------------------------
// warp-per-row top-20 by iterative argmax, row cached in registers.
// ---------------------------------------------------------------------------
__global__ void topk_warp_k(const float* __restrict__ D, int* __restrict__ idx) {
    int warp = threadIdx.x >> 5, lane = threadIdx.x & 31;
    int row = blockIdx.x * 8 + warp;
    float vals[32];
    const float* dr = D + (size_t)row * NPTS;
    #pragma unroll
    for (int i = 0; i < 32; i++) vals[i] = dr[i * 32 + lane];

    float lbv = vals[0]; int lbi = 0;
    #pragma unroll
    for (int i = 1; i < 32; i++) if (vals[i] > lbv) { lbv = vals[i]; lbi = i; }

    for (int it = 0; it < KNN; it++) {
        float cv = lbv;
        int cg = lbi * 32 + lane;
        #pragma unroll
        for (int off = 16; off; off >>= 1) {
            float ov = __shfl_down_sync(0xffffffffu, cv, off);
            int oi = __shfl_down_sync(0xffffffffu, cg, off);
            if (ov > cv || (ov == cv && oi < cg)) { cv = ov; cg = oi; }
        }
        int winner = __shfl_sync(0xffffffffu, cg, 0);
        if (lane == 0) idx[row * KNN + it] = winner;
        if ((winner & 31) == lane) {
            int slot = winner >> 5;
            #pragma unroll
            for (int i = 0; i < 32; i++) if (i == slot) vals[i] = NEG_BIG;
            lbv = vals[0]; lbi = 0;
            #pragma unroll
            for (int i = 1; i < 32; i++) if (vals[i] > lbv) { lbv = vals[i]; lbi = i; }
        }
    }
}

// ---------------------------------------------------------------------------
// generic 64x64 tiled GEMM (for t = F * Whit)
// ---------------------------------------------------------------------------
__global__ void gemm_k(const float* __restrict__ A, int lda,
                       const float* __restrict__ B, int ldb,
                       float* __restrict__ C, int ldc,
                       int M, int N, int K) {
    __shared__ float As[16][65];
    __shared__ float Bs[16][64];
    int tid = threadIdx.x;
    int tm = tid / 16, tn = tid % 16;
    int m0 = blockIdx.y * 64;
    int n0 = blockIdx.x * 64;
    float acc[4][4];
    #pragma unroll
    for (int i = 0; i < 4; i++)
        #pragma unroll
        for (int j = 0; j < 4; j++) acc[i][j] = 0.f;

    for (int k0 = 0; k0 < K; k0 += 16) {
        for (int l = tid; l < 64 * 16; l += 256) {
            int m = l >> 4, kk = l & 15;
            As[kk][m] = (k0 + kk < K) ? A[(size_t)(m0 + m) * lda + k0 + kk] : 0.f;
        }
        for (int l = tid; l < 16 * 64; l += 256) {
            int kk = l >> 6, n = l & 63;
            Bs[kk][n] = (k0 + kk < K) ? B[(size_t)(k0 + kk) * ldb + n0 + n] : 0.f;
        }
        __syncthreads();
        #pragma unroll
        for (int kk = 0; kk < 16; kk++) {
            float a[4], b[4];
            #pragma unroll
            for (int i = 0; i < 4; i++) a[i] = As[kk][tm * 4 + i];
            #pragma unroll
            for (int j = 0; j < 4; j++) b[j] = Bs[kk][tn * 4 + j];
            #pragma unroll
            for (int i = 0; i < 4; i++)
                #pragma unroll
                for (int j = 0; j < 4; j++) acc[i][j] += a[i] * b[j];
        }
        __syncthreads();
    }
    #pragma unroll
    for (int i = 0; i < 4; i++)
        #pragma unroll
        for (int j = 0; j < 4; j++)
            C[(size_t)(m0 + tm * 4 + i) * ldc + n0 + tn * 4 + j] = acc[i][j];
}

// ---------------------------------------------------------------------------
// fused edge layer body, double-buffered, dynamic smem.
// layout: [0,320)   sidx (80 int)
//         [320,640) sctr (80 int)
//         [640, ..) pipeline buffers Abuf[2][16][80], Bbuf[2][16][NCOLS]
//         red [20][NCOLS+4] ALIASES the pipeline region (dead after mainloop)
// tile = 80 rows x NCOLS cols, 320 threads, each 4 rows x TNC cols.
// ---------------------------------------------------------------------------
template <int TNC>
__device__ __forceinline__
void edge_fused_body(const float* __restrict__ F, int ldf, int C, int O,
                     const int* __restrict__ idx, const float* __restrict__ wlot,
                     const float* __restrict__ t,
                     float* __restrict__ gmax, float* __restrict__ gmin,
                     float* __restrict__ psum, float* __restrict__ psq) {
    constexpr int NCOLS = 16 * TNC;
    extern __shared__ char esm[];
    int*   sidx = (int*)esm;                       // 80
    int*   sctr = sidx + 80;                       // 80
    float* Abuf = (float*)(esm + 640);             // [2][16*80]
    float* Bbuf = Abuf + 2 * 16 * 80;              // [2][16*NCOLS]
    float* redf = (float*)(esm + 640);             // alias: [20][NCOLS+4]

    int tid = threadIdx.x;
    int tm = tid / 16;          // 0..19, rows tm*4 .. tm*4+3
    int tn = tid % 16;          // cols tn*TNC ..
    int blockPt = blockIdx.y;   // 4 points
    int n0 = blockIdx.x * NCOLS;

    if (tid < 80) {
        int gp = blockPt * 4 + tid / 20;
        int b = gp >> 10;
        int nbr = idx[blockPt * 80 + tid];
        sidx[tid] = ((b << 10) + nbr) * ldf;
        sctr[tid] = gp * ldf;
    }
    __syncthreads();

    const bool vec = (C % 16 == 0);
    int gm = tid >> 2;          // 0..79, row for vector gather
    int gc = (tid & 3) * 4;     // channel sub-offset 0,4,8,12

    float acc[4][TNC];
    #pragma unroll
    for (int i = 0; i < 4; i++)
        #pragma unroll
        for (int j = 0; j < TNC; j++) acc[i][j] = 0.f;

    int nch = (C + 15) / 16;

    // chunk loader
    auto load_chunk = [&](int c0, int buf) {
        float* A = Abuf + buf * (16 * 80);
        float* B = Bbuf + buf * (16 * NCOLS);
        if (vec) {
            float4 vn = *(const float4*)&F[(size_t)sidx[gm] + c0 + gc];
            float4 vc = *(const float4*)&F[(size_t)sctr[gm] + c0 + gc];
            A[(gc + 0) * 80 + gm] = vn.x - vc.x;
            A[(gc + 1) * 80 + gm] = vn.y - vc.y;
            A[(gc + 2) * 80 + gm] = vn.z - vc.z;
            A[(gc + 3) * 80 + gm] = vn.w - vc.w;
        } else {
            #pragma unroll
            for (int q = 0; q < 4; q++) {
                int l = q * 320 + tid;
                int m = l % 80, kk = l / 80;
                int cc = c0 + kk;
                A[kk * 80 + m] = (cc < C) ? (F[(size_t)sidx[m] + cc] - F[(size_t)sctr[m] + cc]) : 0.f;
            }
        }
        for (int l = tid; l < 16 * NCOLS; l += 320) {
            int kk = l / NCOLS, n = l % NCOLS;
            B[kk * NCOLS + n] = (c0 + kk < C) ? wlot[(size_t)(c0 + kk) * O + n0 + n] : 0.f;
        }
    };

    load_chunk(0, 0);
    __syncthreads();

    for (int ch = 0; ch < nch; ch++) {
        int cur = ch & 1;
        if (ch + 1 < nch) load_chunk((ch + 1) * 16, cur ^ 1);
        const float* A = Abuf + cur * (16 * 80);
        const float* B = Bbuf + cur * (16 * NCOLS);
        #pragma unroll
        for (int kk = 0; kk < 16; kk++) {
            float a[4], b[TNC];
            *(float4*)a = *(const float4*)&A[kk * 80 + tm * 4];
            #pragma unroll
            for (int v = 0; v < TNC / 4; v++)
                *(float4*)&b[v * 4] = *(const float4*)&B[kk * NCOLS + tn * TNC + v * 4];
            #pragma unroll
            for (int i = 0; i < 4; i++)
                #pragma unroll
                for (int j = 0; j < TNC; j++) acc[i][j] += a[i] * b[j];
        }
        __syncthreads();
    }

    // epilogue: red aliases the (now dead) pipeline buffers
    #define RED(r, c) redf[(r) * (NCOLS + 4) + (c)]

    int P = blockPt * 4 + tm / 5;
    float tvj[TNC];
    #pragma unroll
    for (int v = 0; v < TNC / 4; v++)
        *(float4*)&tvj[v * 4] = *(const float4*)&t[(size_t)P * O + n0 + tn * TNC + v * 4];

    float vmax[TNC], vmin[TNC], vs[TNC], vs2[TNC];
    #pragma unroll
    for (int j = 0; j < TNC; j++) {
        vmax[j] = NEG_BIG; vmin[j] = POS_BIG; vs[j] = 0.f; vs2[j] = 0.f;
        #pragma unroll
        for (int i = 0; i < 4; i++) {
            float v = acc[i][j] + tvj[j];
            vmax[j] = fmaxf(vmax[j], v);
            vmin[j] = fminf(vmin[j], v);
            vs[j] += v;
            vs2[j] += v * v;
        }
    }

    // pass 1: max
    #pragma unroll
    for (int j = 0; j < TNC; j++) RED(tm, tn * TNC + j) = vmax[j];
    __syncthreads();
    if (tm % 5 == 0) {
        #pragma unroll
        for (int j = 0; j < TNC; j++) {
            int c = tn * TNC + j;
            float m = RED(tm, c);
            #pragma unroll
            for (int q = 1; q < 5; q++) m = fmaxf(m, RED(tm + q, c));
            gmax[(size_t)P * O + n0 + c] = m;
        }
    }
    __syncthreads();
    // pass 2: min
    #pragma unroll
    for (int j = 0; j < TNC; j++) RED(tm, tn * TNC + j) = vmin[j];
    __syncthreads();
    if (tm % 5 == 0) {
        #pragma unroll
        for (int j = 0; j < TNC; j++) {
            int c = tn * TNC + j;
            float m = RED(tm, c);
            #pragma unroll
            for (int q = 1; q < 5; q++) m = fminf(m, RED(tm + q, c));
            gmin[(size_t)P * O + n0 + c] = m;
        }
    }
    __syncthreads();
    // pass 3: sum over all 80 rows
    #pragma unroll
    for (int j = 0; j < TNC; j++) RED(tm, tn * TNC + j) = vs[j];
    __syncthreads();
    if (tm == 0) {
        #pragma unroll
        for (int j = 0; j < TNC; j++) {
            int c = tn * TNC + j;
            float s = 0.f;
            #pragma unroll
            for (int q = 0; q < 20; q++) s += RED(q, c);
            psum[(size_t)blockPt * O + n0 + c] = s;
        }
    }
    __syncthreads();
    // pass 4: sumsq
    #pragma unroll
    for (int j = 0; j < TNC; j++) RED(tm, tn * TNC + j) = vs2[j];
    __syncthreads();
    if (tm == 0) {
        #pragma unroll
        for (int j = 0; j < TNC; j++) {
            int c = tn * TNC + j;
            float s = 0.f;
            #pragma unroll
            for (int q = 0; q < 20; q++) s += RED(q, c);
            psq[(size_t)blockPt * O + n0 + c] = s;
        }
    }
    #undef RED
}

// plain-named wrappers
__global__ __launch_bounds__(320)
void edge_fused4_k(const float* __restrict__ F, int ldf, int C, int O,
                   const int* __restrict__ idx, const float* __restrict__ wlot,
                   const float* __restrict__ t,
                   float* __restrict__ gmax, float* __restrict__ gmin,
                   float* __restrict__ psum, float* __restrict__ psq) {
    edge_fused_body<4>(F, ldf, C, O, idx, wlot, t, gmax, gmin, psum, psq);
}

__global__ __launch_bounds__(320)
void edge_fused8_k(const float* __restrict__ F, int ldf, int C, int O,
                   const int* __restrict__ idx, const float* __restrict__ wlot,
                   const float* __restrict__ t,
                   float* __restrict__ gmax, float* __restrict__ gmin,
                   float* __restrict__ psum, float* __restrict__ psq) {
    edge_fused_body<8>(F, ldf, C, O, idx, wlot, t, gmax, gmin, psum, psq);
}

// edge dynamic smem sizes
#define EDGE_SMEM(TNC) (640 + 2 * 16 * 80 * 4 + 2 * 16 * (16 * (TNC)) * 4)

// ---------------------------------------------------------------------------
// reduce stats partials -> scale/shift
// ---------------------------------------------------------------------------
__global__ void statsred_k(const float* __restrict__ psum, const float* __restrict__ psq,
                           int R, int O, double invM,
                           const float* __restrict__ gamma, const float* __restrict__ beta,
                           float* __restrict__ scale, float* __restrict__ shift) {
    int o = blockIdx.x;
    double ls = 0.0, ls2 = 0.0;
    for (int r = threadIdx.x; r < R; r += 256) {
        ls += psum[(size_t)r * O + o];
        ls2 += psq[(size_t)r * O + o];
    }
    __shared__ double sd[256], sd2[256];
    sd[threadIdx.x] = ls; sd2[threadIdx.x] = ls2;
    __syncthreads();
    for (int s = 128; s > 0; s >>= 1) {
        if (threadIdx.x < s) { sd[threadIdx.x] += sd[threadIdx.x + s]; sd2[threadIdx.x] += sd2[threadIdx.x + s]; }
        __syncthreads();
    }
    if (threadIdx.x == 0) {
        double mean = sd[0] * invM;
        double var = sd2[0] * invM - mean * mean;
        double sc = (double)gamma[o] / sqrt(var + 1e-5);
        scale[o] = (float)sc;
        shift[o] = (float)((double)beta[o] - mean * sc);
    }
}

__global__ void bnapply_k(const float* __restrict__ gmax, const float* __restrict__ gmin,
                          const float* __restrict__ scale, const float* __restrict__ shift,
                          int O, float* __restrict__ outFeat, int ldo, int colofs) {
    int l = blockIdx.x * blockDim.x + threadIdx.x;
    if (l >= NPOINTS * O) return;
    int o = l % O;
    int p = l / O;
    float sc = scale[o];
    float v = (sc >= 0.f) ? gmax[l] : gmin[l];
    float u = v * sc + shift[o];
    u = u >= 0.f ? u : 0.2f * u;
    outFeat[(size_t)p * ldo + colofs + o] = u;
}

// ---------------------------------------------------------------------------
// conv5 GEMM: 128x128 tile, 8x8 per thread, double-buffered + stats partials
// ---------------------------------------------------------------------------
__global__ __launch_bounds__(256)
void gemm5_k(const float* __restrict__ A, int lda,
             const float* __restrict__ B, int ldb,
             float* __restrict__ C, int ldc, int K,
             float* __restrict__ psum, float* __restrict__ psq, int Ostats) {
    __shared__ float As[2][16][128];
    __shared__ float Bs[2][16][128];
    int tid = threadIdx.x;
    int tm = tid / 16, tn = tid % 16;
    int m0 = blockIdx.y * 128;
    int n0 = blockIdx.x * 128;
    float acc[8][8];
    #pragma unroll
    for (int i = 0; i < 8; i++)
        #pragma unroll
        for (int j = 0; j < 8; j++) acc[i][j] = 0.f;

    int nch = K / 16;

    // load chunk 0
    #pragma unroll
    for (int q = 0; q < 8; q++) {
        int l = q * 256 + tid;
        int kk = l & 15, m = l >> 4;
        As[0][kk][m] = A[(size_t)(m0 + m) * lda + kk];
    }
    #pragma unroll
    for (int q = 0; q < 8; q++) {
        int l = q * 256 + tid;
        int kk = l >> 7, n = l & 127;
        Bs[0][kk][n] = B[(size_t)kk * ldb + n0 + n];
    }
    __syncthreads();

    for (int ch = 0; ch < nch; ch++) {
        int cur = ch & 1;
        if (ch + 1 < nch) {
            int k0 = (ch + 1) * 16;
            int nxt = cur ^ 1;
            #pragma unroll
            for (int q = 0; q < 8; q++) {
                int l = q * 256 + tid;
                int kk = l & 15, m = l >> 4;
                As[nxt][kk][m] = A[(size_t)(m0 + m) * lda + k0 + kk];
            }
            #pragma unroll
            for (int q = 0; q < 8; q++) {
                int l = q * 256 + tid;
                int kk = l >> 7, n = l & 127;
                Bs[nxt][kk][n] = B[(size_t)(k0 + kk) * ldb + n0 + n];
            }
        }
        #pragma unroll
        for (int kk = 0; kk < 16; kk++) {
            float a[8], b[8];
            *(float4*)&a[0] = *(const float4*)&As[cur][kk][tm * 8];
            *(float4*)&a[4] = *(const float4*)&As[cur][kk][tm * 8 + 4];
            *(float4*)&b[0] = *(const float4*)&Bs[cur][kk][tn * 8];
            *(float4*)&b[4] = *(const float4*)&Bs[cur][kk][tn * 8 + 4];
            #pragma unroll
            for (int i = 0; i < 8; i++)
                #pragma unroll
                for (int j = 0; j < 8; j++) acc[i][j] += a[i] * b[j];
        }
        __syncthreads();
    }
    #pragma unroll
    for (int i = 0; i < 8; i++) {
        float* dst = &C[(size_t)(m0 + tm * 8 + i) * ldc + n0 + tn * 8];
        *(float4*)&dst[0] = *(float4*)&acc[i][0];
        *(float4*)&dst[4] = *(float4*)&acc[i][4];
    }
    // stats partials: reuse As[0] as reduction buffer [16][128]
    float(*red)[128] = As[0];
    float cs[8], cq[8];
    #pragma unroll
    for (int j = 0; j < 8; j++) {
        cs[j] = 0.f; cq[j] = 0.f;
        #pragma unroll
        for (int i = 0; i < 8; i++) { float v = acc[i][j]; cs[j] += v; cq[j] += v * v; }
    }
    __syncthreads();
    #pragma unroll
    for (int j = 0; j < 8; j++) red[tm][tn * 8 + j] = cs[j];
    __syncthreads();
    if (tm == 0) {
        #pragma unroll
        for (int j = 0; j < 8; j++) {
            int c = tn * 8 + j;
            float s = 0.f;
            #pragma unroll
            for (int q = 0; q < 16; q++) s += red[q][c];
            psum[(size_t)blockIdx.y * Ostats + n0 + c] = s;
        }
    }
    __syncthreads();
    #pragma unroll
    for (int j = 0; j < 8; j++) red[tm][tn * 8 + j] = cq[j];
    __syncthreads();
    if (tm == 0) {
        #pragma unroll
        for (int j = 0; j < 8; j++) {
            int c = tn * 8 + j;
            float s = 0.f;
            #pragma unroll
            for (int q = 0; q < 16; q++) s += red[q][c];
            psq[(size_t)blockIdx.y * Ostats + n0 + c] = s;
        }
    }
}

// ---------------------------------------------------------------------------
// conv5 pooling
// ---------------------------------------------------------------------------
__global__ void pool_k(const float* __restrict__ h5, const float* __restrict__ scale,
                       const float* __restrict__ shift, float* __restrict__ pooled) {
    int b = blockIdx.y;
    int o = blockIdx.x * blockDim.x + threadIdx.x;
    float sc = scale[o], sh = shift[o];
    float mx = NEG_BIG, sm = 0.f;
    for (int n = 0; n < NPTS; n++) {
        float v = h5[((size_t)b * NPTS + n) * 1024 + o] * sc + sh;
        v = v >= 0.f ? v : 0.2f * v;
        mx = fmaxf(mx, v);
        sm += v;
    }
    pooled[b * 2048 + o] = mx;
    pooled[b * 2048 + 1024 + o] = sm * (1.f / (float)NPTS);
}

// ---------------------------------------------------------------------------
// tiny FC + per-batch BN
// ---------------------------------------------------------------------------
__global__ void fc_k(const float* __restrict__ X, int bcols,
                     const float* __restrict__ W, const float* __restrict__ bias,
                     float* __restrict__ Y, int O) {
    int o = blockIdx.x;
    const float* w = W + (size_t)o * bcols;
    float acc[BATCH];
    #pragma unroll
    for (int b = 0; b < BATCH; b++) acc[b] = 0.f;
    for (int c = threadIdx.x; c < bcols; c += blockDim.x) {
        float wv = w[c];
        #pragma unroll
        for (int b = 0; b < BATCH; b++) acc[b] += X[(size_t)b * bcols + c] * wv;
    }
    #pragma unroll
    for (int b = 0; b < BATCH; b++)
        #pragma unroll
        for (int off = 16; off; off >>= 1)
            acc[b] += __shfl_down_sync(0xffffffffu, acc[b], off);
    __shared__ float sm[BATCH][4];
    int warp = threadIdx.x >> 5, lane = threadIdx.x & 31;
    if (lane == 0)
        #pragma unroll
        for (int b = 0; b < BATCH; b++) sm[b][warp] = acc[b];
    __syncthreads();
    if (threadIdx.x == 0) {
        float bs = bias ? bias[o] : 0.f;
        #pragma unroll
        for (int b = 0; b < BATCH; b++)
            Y[(size_t)b * O + o] = sm[b][0] + sm[b][1] + sm[b][2] + sm[b][3] + bs;
    }
}

__global__ void bnrow_k(const float* __restrict__ Yraw, int O,
                        const float* __restrict__ gamma, const float* __restrict__ beta,
                        float* __restrict__ Yact) {
    int o = blockIdx.x * blockDim.x + threadIdx.x;
    if (o >= O) return;
    float v[BATCH];
    double s = 0.0, s2 = 0.0;
    #pragma unroll
    for (int b = 0; b < BATCH; b++) {
        v[b] = Yraw[(size_t)b * O + o];
        s += v[b]; s2 += (double)v[b] * v[b];
    }
    double mean = s / (double)BATCH;
    double var = s2 / (double)BATCH - mean * mean;
    double sc = (double)gamma[o] / sqrt(var + 1e-5);
    double sh = (double)beta[o] - mean * sc;
    #pragma unroll
    for (int b = 0; b < BATCH; b++) {
        float u = (float)((double)v[b] * sc + sh);
        Yact[(size_t)b * O + o] = u >= 0.f ? u : 0.2f * u;
    }
}

// ---------------------------------------------------------------------------
// host orchestration
// ---------------------------------------------------------------------------
static inline float* sym_addr(const void* symbol) {
    void* p = nullptr;
    cudaGetSymbolAddress(&p, symbol);
    return (float*)p;
}

extern "C" void kernel_launch(void* const* d_in, const int* in_sizes, int n_in,
                              void* d_out, int out_size) {
    const float* x   = (const float*)d_in[0];
    const float* w1  = (const float*)d_in[1];
    const float* g1  = (const float*)d_in[2];
    const float* b1  = (const float*)d_in[3];
    const float* w2  = (const float*)d_in[4];
    const float* g2  = (const float*)d_in[5];
    const float* b2  = (const float*)d_in[6];
    const float* w3  = (const float*)d_in[7];
    const float* g3  = (const float*)d_in[8];
    const float* b3  = (const float*)d_in[9];
    const float* w4  = (const float*)d_in[10];
    const float* g4  = (const float*)d_in[11];
    const float* b4  = (const float*)d_in[12];
    const float* w5  = (const float*)d_in[13];
    const float* g5  = (const float*)d_in[14];
    const float* b5  = (const float*)d_in[15];
    const float* lw1 = (const float*)d_in[16];
    const float* g6  = (const float*)d_in[17];
    const float* b6  = (const float*)d_in[18];
    const float* lw2 = (const float*)d_in[19];
    const float* lb2 = (const float*)d_in[20];
    const float* g7  = (const float*)d_in[21];
    const float* b7  = (const float*)d_in[22];
    const float* lw3 = (const float*)d_in[23];
    const float* lb3 = (const float*)d_in[24];

    float* xp    = sym_addr(g_xp);
    float* feat  = sym_addr(g_feat);
    float* D     = sym_addr(g_D);
    int*   idx   = (int*)sym_addr(g_idx);
    float* xxv   = sym_addr(g_xx);
    float* tbuf  = sym_addr(g_t);
    float* gmax  = sym_addr(g_max);
    float* gmin  = sym_addr(g_min);
    float* h5    = sym_addr(g_h5);
    float* psum  = sym_addr(g_psum);
    float* psq   = sym_addr(g_psq);
    float* scale = sym_addr(g_scale);
    float* shift = sym_addr(g_shift);
    float* wlot  = sym_addr(g_wlot);
    float* whit  = sym_addr(g_whit);
    float* w5t   = sym_addr(g_w5t);
    float* pooled = sym_addr(g_pooled);
    float* fc1raw = sym_addr(g_fc1raw);
    float* fc1    = sym_addr(g_fc1);
    float* fc2raw = sym_addr(g_fc2raw);
    float* fc2    = sym_addr(g_fc2);

    transpose_x_k<<<(BATCH * NPTS * 3 + 255) / 256, 256>>>(x, xp);
    wt_k<<<(1024 * 512 + 255) / 256, 256>>>(w5, 1024, 512, w5t);

    struct Cfg {
        const float* Fin; int ldf; int C; int O; int colout;
        const float* W; const float* gamma; const float* beta;
    };
    Cfg cfgs[4] = {
        { xp,          3,   3,   64,  0,   w1, g1, b1 },
        { feat + 0,    512, 64,  64,  64,  w2, g2, b2 },
        { feat + 64,   512, 64,  128, 128, w3, g3, b3 },
        { feat + 128,  512, 128, 256, 256, w4, g4, b4 },
    };

    for (int L = 0; L < 4; L++) {
        const Cfg& c = cfgs[L];
        wprep_k<<<(c.O * c.C + 255) / 256, 256>>>(c.W, c.O, c.C, wlot, whit);
        xx_k<<<(NPOINTS * 32 + 255) / 256, 256>>>(c.Fin, c.ldf, c.C, xxv);
        dist8_k<<<dim3(8, 8, 8), 256>>>(c.Fin, c.ldf, c.C, xxv, D);
        topk_warp_k<<<NPOINTS / 8, 256>>>(D, idx);
        gemm_k<<<dim3(c.O / 64, NPOINTS / 64), 256>>>(c.Fin, c.ldf, whit, c.O,
                                                      tbuf, c.O, NPOINTS, c.O, c.C);
        if (c.O >= 128) {
            edge_fused8_k<<<dim3(c.O / 128, NPOINTS / 4), 320, EDGE_SMEM(8)>>>(
                c.Fin, c.ldf, c.C, c.O, idx, wlot, tbuf, gmax, gmin, psum, psq);
        } else {
            edge_fused4_k<<<dim3(c.O / 64, NPOINTS / 4), 320, EDGE_SMEM(4)>>>(
                c.Fin, c.ldf, c.C, c.O, idx, wlot, tbuf, gmax, gmin, psum, psq);
        }
        statsred_k<<<c.O, 256>>>(psum, psq, NPOINTS / 4, c.O, 1.0 / (double)MROWS,
                                 c.gamma, c.beta, scale, shift);
        bnapply_k<<<(NPOINTS * c.O + 255) / 256, 256>>>(gmax, gmin, scale, shift,
                                                        c.O, feat, 512, c.colout);
    }

    // conv5: (8192 x 512) @ (512 x 1024) with fused stats partials
    gemm5_k<<<dim3(1024 / 128, NPOINTS / 128), 256>>>(feat, 512, w5t, 1024, h5, 1024,
                                                      512, psum, psq, 1024);
    statsred_k<<<1024, 256>>>(psum, psq, NPOINTS / 128, 1024, 1.0 / (double)NPOINTS,
                              g5, b5, scale, shift);
    pool_k<<<dim3(4, 8), 256>>>(h5, scale, shift, pooled);

    // head
    fc_k<<<512, 128>>>(pooled, 2048, lw1, nullptr, fc1raw, 512);
    bnrow_k<<<2, 256>>>(fc1raw, 512, g6, b6, fc1);
    fc_k<<<256, 128>>>(fc1, 512, lw2, lb2, fc2raw, 256);
    bnrow_k<<<1, 256>>>(fc2raw, 256, g7, b7, fc2);
    fc_k<<<40, 128>>>(fc2, 256, lw3, lb3, (float*)d_out, 40);
}

// round 13
// speedup vs baseline: 1.8070x; 1.0294x over previous
#include <cuda_runtime.h>
#include <math.h>
#include <stdint.h>
#include <stddef.h>

// ---------------------------------------------------------------------------
// DGCNN classifier, B=8, N=1024, K=20. fp32 throughout.
// Round 13 (= round-12 resubmit after broker failure): parallel 2-stage
// pooling, 128-tile t-GEMM, C=3 dist special case, xx fused into bnapply.
// ---------------------------------------------------------------------------

#define BATCH 8
#define NPTS 1024
#define KNN 20
#define NPOINTS (BATCH * NPTS)          // 8192
#define MROWS (NPOINTS * KNN)           // 163840
#define NEG_BIG (-3.0e38f)
#define POS_BIG (3.0e38f)

__device__ float g_xp[NPOINTS * 3];
__device__ float g_feat[NPOINTS * 512];
__device__ float g_D[(size_t)BATCH * NPTS * NPTS];      // 32 MB
__device__ int   g_idx[NPOINTS * KNN];
__device__ float g_xx[NPOINTS];
__device__ float g_t[NPOINTS * 256];                    // 8 MB
__device__ float g_max[NPOINTS * 256];
__device__ float g_min[NPOINTS * 256];
__device__ float g_h5[(size_t)NPOINTS * 1024];          // 33 MB
__device__ float g_psum[2048 * 256];
__device__ float g_psq[2048 * 256];
__device__ float g_scale[1024];
__device__ float g_shift[1024];
__device__ float g_wlot[128 * 256];
__device__ float g_whit[128 * 256];
__device__ float g_w5t[512 * 1024];
__device__ float g_pooled[BATCH * 2048];
__device__ float g_fc1raw[BATCH * 512];
__device__ float g_fc1[BATCH * 512];
__device__ float g_fc2raw[BATCH * 256];
__device__ float g_fc2[BATCH * 256];

// ---------------------------------------------------------------------------
// small utility kernels
// ---------------------------------------------------------------------------

__global__ void transpose_x_k(const float* __restrict__ x, float* __restrict__ xp) {
    int l = blockIdx.x * blockDim.x + threadIdx.x;
    if (l >= BATCH * NPTS * 3) return;
    int c = l % 3;
    int n = (l / 3) % NPTS;
    int b = l / (3 * NPTS);
    xp[l] = x[((size_t)b * 3 + c) * NPTS + n];
}

__global__ void wprep_k(const float* __restrict__ W, int O, int C,
                        float* __restrict__ wlot, float* __restrict__ whit) {
    int l = blockIdx.x * blockDim.x + threadIdx.x;
    if (l >= O * C) return;
    int o = l % O;
    int c = l / O;
    wlot[l] = W[(size_t)o * 2 * C + c];
    whit[l] = W[(size_t)o * 2 * C + C + c];
}

__global__ void wt_k(const float* __restrict__ W, int O, int Kc, float* __restrict__ Wt) {
    int l = blockIdx.x * blockDim.x + threadIdx.x;
    if (l >= O * Kc) return;
    int o = l % O;
    int c = l / O;
    Wt[l] = W[(size_t)o * Kc + c];
}

// xx for layer 1 input (xp, C=3)
__global__ void xx_k(const float* __restrict__ F, int ldf, int C, float* __restrict__ xx) {
    int g = blockIdx.x * blockDim.x + threadIdx.x;
    int p = g >> 5, lane = g & 31;
    if (p >= NPOINTS) return;
    const float* f = F + (size_t)p * ldf;
    float s = 0.f;
    for (int c = lane; c < C; c += 32) { float v = f[c]; s += v * v; }
    #pragma unroll
    for (int off = 16; off; off >>= 1) s += __shfl_down_sync(0xffffffffu, s, off);
    if (lane == 0) xx[p] = s;
}

// ---------------------------------------------------------------------------
// pairwise neg-dist, C=3 special case (layer 1): xyz in smem, no K-loop.
// ---------------------------------------------------------------------------
__global__ __launch_bounds__(256)
void dist3_k(const float* __restrict__ F,
             const float* __restrict__ xx, float* __restrict__ D) {
    int bi = blockIdx.y, bj = blockIdx.x;
    if (bj < bi) return;
    __shared__ float Fi[3][128];
    __shared__ float Fj[3][128];
    int b = blockIdx.z;
    int i0 = bi * 128, j0 = bj * 128;
    int tid = threadIdx.x;
    int tm = tid / 16, tn = tid % 16;
    const float* Fb = F + (size_t)b * NPTS * 3;
    if (tid < 128) {
        Fi[0][tid] = Fb[(size_t)(i0 + tid) * 3 + 0];
        Fi[1][tid] = Fb[(size_t)(i0 + tid) * 3 + 1];
        Fi[2][tid] = Fb[(size_t)(i0 + tid) * 3 + 2];
    } else {
        int m = tid - 128;
        Fj[0][m] = Fb[(size_t)(j0 + m) * 3 + 0];
        Fj[1][m] = Fb[(size_t)(j0 + m) * 3 + 1];
        Fj[2][m] = Fb[(size_t)(j0 + m) * 3 + 2];
    }
    __syncthreads();

    float acc[8][8];
    #pragma unroll
    for (int i = 0; i < 8; i++)
        #pragma unroll
        for (int j = 0; j < 8; j++) acc[i][j] = 0.f;
    #pragma unroll
    for (int kk = 0; kk < 3; kk++) {
        float a[8], bb[8];
        #pragma unroll
        for (int i = 0; i < 8; i++) a[i] = Fi[kk][tm * 8 + i];
        #pragma unroll
        for (int j = 0; j < 8; j++) bb[j] = Fj[kk][tn * 8 + j];
        #pragma unroll
        for (int i = 0; i < 8; i++)
            #pragma unroll
            for (int j = 0; j < 8; j++) acc[i][j] += a[i] * bb[j];
    }

    float xi[8], xj[8];
    #pragma unroll
    for (int i = 0; i < 8; i++) xi[i] = xx[b * NPTS + i0 + tm * 8 + i];
    #pragma unroll
    for (int j = 0; j < 8; j++) xj[j] = xx[b * NPTS + j0 + tn * 8 + j];

    #pragma unroll
    for (int i = 0; i < 8; i++) {
        int ii = i0 + tm * 8 + i;
        float out[8];
        #pragma unroll
        for (int j = 0; j < 8; j++) out[j] = -(xi[i] - 2.f * acc[i][j] + xj[j]);
        float* dst = &D[((size_t)b * NPTS + ii) * NPTS + j0 + tn * 8];
        *(float4*)&dst[0] = *(float4*)&out[0];
        *(float4*)&dst[4] = *(float4*)&out[4];
    }
    if (bj > bi) {
        #pragma unroll
        for (int j = 0; j < 8; j++) {
            int jj = j0 + tn * 8 + j;
            float out[8];
            #pragma unroll
            for (int i = 0; i < 8; i++) out[i] = -(xj[j] - 2.f * acc[i][j] + xi[i]);
            float* dst = &D[((size_t)b * NPTS + jj) * NPTS + i0 + tm * 8];
            *(float4*)&dst[0] = *(float4*)&out[0];
            *(float4*)&dst[4] = *(float4*)&out[4];
        }
    }
}

// ---------------------------------------------------------------------------
// pairwise neg-dist, generic (C>=16), 128x128, 8x8, SYMMETRIC, double-buffered
// ---------------------------------------------------------------------------
__global__ __launch_bounds__(256)
void dist8_k(const float* __restrict__ F, int ldf, int C,
             const float* __restrict__ xx, float* __restrict__ D) {
    int bi = blockIdx.y, bj = blockIdx.x;
    if (bj < bi) return;
    __shared__ float Fi[2][16][128];
    __shared__ float Fj[2][16][128];
    int b = blockIdx.z;
    int i0 = bi * 128, j0 = bj * 128;
    int tid = threadIdx.x;
    int tm = tid / 16, tn = tid % 16;
    const float* Fb = F + (size_t)b * NPTS * ldf;
    float acc[8][8];
    #pragma unroll
    for (int i = 0; i < 8; i++)
        #pragma unroll
        for (int j = 0; j < 8; j++) acc[i][j] = 0.f;

    int nch = (C + 15) / 16;

    #pragma unroll
    for (int q = 0; q < 8; q++) {
        int l = q * 256 + tid;
        int kk = l & 15, m = l >> 4;
        Fi[0][kk][m] = (kk < C) ? Fb[(size_t)(i0 + m) * ldf + kk] : 0.f;
        Fj[0][kk][m] = (kk < C) ? Fb[(size_t)(j0 + m) * ldf + kk] : 0.f;
    }
    __syncthreads();

    for (int ch = 0; ch < nch; ch++) {
        int cur = ch & 1;
        if (ch + 1 < nch) {
            int c0 = (ch + 1) * 16;
            int nxt = cur ^ 1;
            #pragma unroll
            for (int q = 0; q < 8; q++) {
                int l = q * 256 + tid;
                int kk = l & 15, m = l >> 4;
                Fi[nxt][kk][m] = (c0 + kk < C) ? Fb[(size_t)(i0 + m) * ldf + c0 + kk] : 0.f;
                Fj[nxt][kk][m] = (c0 + kk < C) ? Fb[(size_t)(j0 + m) * ldf + c0 + kk] : 0.f;
            }
        }
        #pragma unroll
        for (int kk = 0; kk < 16; kk++) {
            float a[8], bb[8];
            *(float4*)&a[0] = *(const float4*)&Fi[cur][kk][tm * 8];
            *(float4*)&a[4] = *(const float4*)&Fi[cur][kk][tm * 8 + 4];
            *(float4*)&bb[0] = *(const float4*)&Fj[cur][kk][tn * 8];
            *(float4*)&bb[4] = *(const float4*)&Fj[cur][kk][tn * 8 + 4];
            #pragma unroll
            for (int i = 0; i < 8; i++)
                #pragma unroll
                for (int j = 0; j < 8; j++) acc[i][j] += a[i] * bb[j];
        }
        __syncthreads();
    }
    float xi[8], xj[8];
    #pragma unroll
    for (int i = 0; i < 8; i++) xi[i] = xx[b * NPTS + i0 + tm * 8 + i];
    #pragma unroll
    for (int j = 0; j < 8; j++) xj[j] = xx[b * NPTS + j0 + tn * 8 + j];

    #pragma unroll
    for (int i = 0; i < 8; i++) {
        int ii = i0 + tm * 8 + i;
        float out[8];
        #pragma unroll
        for (int j = 0; j < 8; j++) out[j] = -(xi[i] - 2.f * acc[i][j] + xj[j]);
        float* dst = &D[((size_t)b * NPTS + ii) * NPTS + j0 + tn * 8];
        *(float4*)&dst[0] = *(float4*)&out[0];
        *(float4*)&dst[4] = *(float4*)&out[4];
    }
    if (bj > bi) {
        #pragma unroll
        for (int j = 0; j < 8; j++) {
            int jj = j0 + tn * 8 + j;
            float out[8];
            #pragma unroll
            for (int i = 0; i < 8; i++) out[i] = -(xj[j] - 2.f * acc[i][j] + xi[i]);
            float* dst = &D[((size_t)b * NPTS + jj) * NPTS + i0 + tm * 8];
            *(float4*)&dst[0] = *(float4*)&out[0];
            *(float4*)&dst[4] = *(float4*)&out[4];
        }
    }
}

// ---------------------------------------------------------------------------
// warp-per-row top-20 by iterative argmax, row cached in registers.
// ---------------------------------------------------------------------------
__global__ void topk_warp_k(const float* __restrict__ D, int* __restrict__ idx) {
    int warp = threadIdx.x >> 5, lane = threadIdx.x & 31;
    int row = blockIdx.x * 8 + warp;
    float vals[32];
    const float* dr = D + (size_t)row * NPTS;
    #pragma unroll
    for (int i = 0; i < 32; i++) vals[i] = dr[i * 32 + lane];

    float lbv = vals[0]; int lbi = 0;
    #pragma unroll
    for (int i = 1; i < 32; i++) if (vals[i] > lbv) { lbv = vals[i]; lbi = i; }

    for (int it = 0; it < KNN; it++) {
        float cv = lbv;
        int cg = lbi * 32 + lane;
        #pragma unroll
        for (int off = 16; off; off >>= 1) {
            float ov = __shfl_down_sync(0xffffffffu, cv, off);
            int oi = __shfl_down_sync(0xffffffffu, cg, off);
            if (ov > cv || (ov == cv && oi < cg)) { cv = ov; cg = oi; }
        }
        int winner = __shfl_sync(0xffffffffu, cg, 0);
        if (lane == 0) idx[row * KNN + it] = winner;
        if ((winner & 31) == lane) {
            int slot = winner >> 5;
            #pragma unroll
            for (int i = 0; i < 32; i++) if (i == slot) vals[i] = NEG_BIG;
            lbv = vals[0]; lbi = 0;
            #pragma unroll
            for (int i = 1; i < 32; i++) if (vals[i] > lbv) { lbv = vals[i]; lbi = i; }
        }
    }
}

// ---------------------------------------------------------------------------
// generic 64x64 tiled GEMM (t for O=64 layers)
// ---------------------------------------------------------------------------
__global__ void gemm_k(const float* __restrict__ A, int lda,
                       const float* __restrict__ B, int ldb,
                       float* __restrict__ C, int ldc,
                       int M, int N, int K) {
    __shared__ float As[16][65];
    __shared__ float Bs[16][64];
    int tid = threadIdx.x;
    int tm = tid / 16, tn = tid % 16;
    int m0 = blockIdx.y * 64;
    int n0 = blockIdx.x * 64;
    float acc[4][4];
    #pragma unroll
    for (int i = 0; i < 4; i++)
        #pragma unroll
        for (int j = 0; j < 4; j++) acc[i][j] = 0.f;

    for (int k0 = 0; k0 < K; k0 += 16) {
        for (int l = tid; l < 64 * 16; l += 256) {
            int m = l >> 4, kk = l & 15;
            As[kk][m] = (k0 + kk < K) ? A[(size_t)(m0 + m) * lda + k0 + kk] : 0.f;
        }
        for (int l = tid; l < 16 * 64; l += 256) {
            int kk = l >> 6, n = l & 63;
            Bs[kk][n] = (k0 + kk < K) ? B[(size_t)(k0 + kk) * ldb + n0 + n] : 0.f;
        }
        __syncthreads();
        #pragma unroll
        for (int kk = 0; kk < 16; kk++) {
            float a[4], b[4];
            #pragma unroll
            for (int i = 0; i < 4; i++) a[i] = As[kk][tm * 4 + i];
            #pragma unroll
            for (int j = 0; j < 4; j++) b[j] = Bs[kk][tn * 4 + j];
            #pragma unroll
            for (int i = 0; i < 4; i++)
                #pragma unroll
                for (int j = 0; j < 4; j++) acc[i][j] += a[i] * b[j];
        }
        __syncthreads();
    }
    #pragma unroll
    for (int i = 0; i < 4; i++)
        #pragma unroll
        for (int j = 0; j < 4; j++)
            C[(size_t)(m0 + tm * 4 + i) * ldc + n0 + tn * 4 + j] = acc[i][j];
}

// ---------------------------------------------------------------------------
// 128x128 tiled GEMM, 8x8 per thread, double-buffered (t for O>=128)
// K multiple of 16; N multiple of 128.
// ---------------------------------------------------------------------------
__global__ __launch_bounds__(256)
void gemm128_k(const float* __restrict__ A, int lda,
               const float* __restrict__ B, int ldb,
               float* __restrict__ C, int ldc, int K) {
    __shared__ float As[2][16][128];
    __shared__ float Bs[2][16][128];
    int tid = threadIdx.x;
    int tm = tid / 16, tn = tid % 16;
    int m0 = blockIdx.y * 128;
    int n0 = blockIdx.x * 128;
    float acc[8][8];
    #pragma unroll
    for (int i = 0; i < 8; i++)
        #pragma unroll
        for (int j = 0; j < 8; j++) acc[i][j] = 0.f;

    int nch = K / 16;
    #pragma unroll
    for (int q = 0; q < 8; q++) {
        int l = q * 256 + tid;
        int kk = l & 15, m = l >> 4;
        As[0][kk][m] = A[(size_t)(m0 + m) * lda + kk];
    }
    #pragma unroll
    for (int q = 0; q < 8; q++) {
        int l = q * 256 + tid;
        int kk = l >> 7, n = l & 127;
        Bs[0][kk][n] = B[(size_t)kk * ldb + n0 + n];
    }
    __syncthreads();

    for (int ch = 0; ch < nch; ch++) {
        int cur = ch & 1;
        if (ch + 1 < nch) {
            int k0 = (ch + 1) * 16;
            int nxt = cur ^ 1;
            #pragma unroll
            for (int q = 0; q < 8; q++) {
                int l = q * 256 + tid;
                int kk = l & 15, m = l >> 4;
                As[nxt][kk][m] = A[(size_t)(m0 + m) * lda + k0 + kk];
            }
            #pragma unroll
            for (int q = 0; q < 8; q++) {
                int l = q * 256 + tid;
                int kk = l >> 7, n = l & 127;
                Bs[nxt][kk][n] = B[(size_t)(k0 + kk) * ldb + n0 + n];
            }
        }
        #pragma unroll
        for (int kk = 0; kk < 16; kk++) {
            float a[8], b[8];
            *(float4*)&a[0] = *(const float4*)&As[cur][kk][tm * 8];
            *(float4*)&a[4] = *(const float4*)&As[cur][kk][tm * 8 + 4];
            *(float4*)&b[0] = *(const float4*)&Bs[cur][kk][tn * 8];
            *(float4*)&b[4] = *(const float4*)&Bs[cur][kk][tn * 8 + 4];
            #pragma unroll
            for (int i = 0; i < 8; i++)
                #pragma unroll
                for (int j = 0; j < 8; j++) acc[i][j] += a[i] * b[j];
        }
        __syncthreads();
    }
    #pragma unroll
    for (int i = 0; i < 8; i++) {
        float* dst = &C[(size_t)(m0 + tm * 8 + i) * ldc + n0 + tn * 8];
        *(float4*)&dst[0] = *(float4*)&acc[i][0];
        *(float4*)&dst[4] = *(float4*)&acc[i][4];
    }
}

// ---------------------------------------------------------------------------
// fused edge layer body, double-buffered, dynamic smem
// ---------------------------------------------------------------------------
template <int TNC>
__device__ __forceinline__
void edge_fused_body(const float* __restrict__ F, int ldf, int C, int O,
                     const int* __restrict__ idx, const float* __restrict__ wlot,
                     const float* __restrict__ t,
                     float* __restrict__ gmax, float* __restrict__ gmin,
                     float* __restrict__ psum, float* __restrict__ psq) {
    constexpr int NCOLS = 16 * TNC;
    extern __shared__ char esm[];
    int*   sidx = (int*)esm;
    int*   sctr = sidx + 80;
    float* Abuf = (float*)(esm + 640);
    float* Bbuf = Abuf + 2 * 16 * 80;
    float* redf = (float*)(esm + 640);

    int tid = threadIdx.x;
    int tm = tid / 16;
    int tn = tid % 16;
    int blockPt = blockIdx.y;
    int n0 = blockIdx.x * NCOLS;

    if (tid < 80) {
        int gp = blockPt * 4 + tid / 20;
        int b = gp >> 10;
        int nbr = idx[blockPt * 80 + tid];
        sidx[tid] = ((b << 10) + nbr) * ldf;
        sctr[tid] = gp * ldf;
    }
    __syncthreads();

    const bool vec = (C % 16 == 0);
    int gm = tid >> 2;
    int gc = (tid & 3) * 4;

    float acc[4][TNC];
    #pragma unroll
    for (int i = 0; i < 4; i++)
        #pragma unroll
        for (int j = 0; j < TNC; j++) acc[i][j] = 0.f;

    int nch = (C + 15) / 16;

    auto load_chunk = [&](int c0, int buf) {
        float* A = Abuf + buf * (16 * 80);
        float* B = Bbuf + buf * (16 * NCOLS);
        if (vec) {
            float4 vn = *(const float4*)&F[(size_t)sidx[gm] + c0 + gc];
            float4 vc = *(const float4*)&F[(size_t)sctr[gm] + c0 + gc];
            A[(gc + 0) * 80 + gm] = vn.x - vc.x;
            A[(gc + 1) * 80 + gm] = vn.y - vc.y;
            A[(gc + 2) * 80 + gm] = vn.z - vc.z;
            A[(gc + 3) * 80 + gm] = vn.w - vc.w;
        } else {
            #pragma unroll
            for (int q = 0; q < 4; q++) {
                int l = q * 320 + tid;
                int m = l % 80, kk = l / 80;
                int cc = c0 + kk;
                A[kk * 80 + m] = (cc < C) ? (F[(size_t)sidx[m] + cc] - F[(size_t)sctr[m] + cc]) : 0.f;
            }
        }
        for (int l = tid; l < 16 * NCOLS; l += 320) {
            int kk = l / NCOLS, n = l % NCOLS;
            B[kk * NCOLS + n] = (c0 + kk < C) ? wlot[(size_t)(c0 + kk) * O + n0 + n] : 0.f;
        }
    };

    load_chunk(0, 0);
    __syncthreads();

    for (int ch = 0; ch < nch; ch++) {
        int cur = ch & 1;
        if (ch + 1 < nch) load_chunk((ch + 1) * 16, cur ^ 1);
        const float* A = Abuf + cur * (16 * 80);
        const float* B = Bbuf + cur * (16 * NCOLS);
        #pragma unroll
        for (int kk = 0; kk < 16; kk++) {
            float a[4], b[TNC];
            *(float4*)a = *(const float4*)&A[kk * 80 + tm * 4];
            #pragma unroll
            for (int v = 0; v < TNC / 4; v++)
                *(float4*)&b[v * 4] = *(const float4*)&B[kk * NCOLS + tn * TNC + v * 4];
            #pragma unroll
            for (int i = 0; i < 4; i++)
                #pragma unroll
                for (int j = 0; j < TNC; j++) acc[i][j] += a[i] * b[j];
        }
        __syncthreads();
    }

    #define RED(r, c) redf[(r) * (NCOLS + 4) + (c)]

    int P = blockPt * 4 + tm / 5;
    float tvj[TNC];
    #pragma unroll
    for (int v = 0; v < TNC / 4; v++)
        *(float4*)&tvj[v * 4] = *(const float4*)&t[(size_t)P * O + n0 + tn * TNC + v * 4];

    float vmax[TNC], vmin[TNC], vs[TNC], vs2[TNC];
    #pragma unroll
    for (int j = 0; j < TNC; j++) {
        vmax[j] = NEG_BIG; vmin[j] = POS_BIG; vs[j] = 0.f; vs2[j] = 0.f;
        #pragma unroll
        for (int i = 0; i < 4; i++) {
            float v = acc[i][j] + tvj[j];
            vmax[j] = fmaxf(vmax[j], v);
            vmin[j] = fminf(vmin[j], v);
            vs[j] += v;
            vs2[j] += v * v;
        }
    }

    #pragma unroll
    for (int j = 0; j < TNC; j++) RED(tm, tn * TNC + j) = vmax[j];
    __syncthreads();
    if (tm % 5 == 0) {
        #pragma unroll
        for (int j = 0; j < TNC; j++) {
            int c = tn * TNC + j;
            float m = RED(tm, c);
            #pragma unroll
            for (int q = 1; q < 5; q++) m = fmaxf(m, RED(tm + q, c));
            gmax[(size_t)P * O + n0 + c] = m;
        }
    }
    __syncthreads();
    #pragma unroll
    for (int j = 0; j < TNC; j++) RED(tm, tn * TNC + j) = vmin[j];
    __syncthreads();
    if (tm % 5 == 0) {
        #pragma unroll
        for (int j = 0; j < TNC; j++) {
            int c = tn * TNC + j;
            float m = RED(tm, c);
            #pragma unroll
            for (int q = 1; q < 5; q++) m = fminf(m, RED(tm + q, c));
            gmin[(size_t)P * O + n0 + c] = m;
        }
    }
    __syncthreads();
    #pragma unroll
    for (int j = 0; j < TNC; j++) RED(tm, tn * TNC + j) = vs[j];
    __syncthreads();
    if (tm == 0) {
        #pragma unroll
        for (int j = 0; j < TNC; j++) {
            int c = tn * TNC + j;
            float s = 0.f;
            #pragma unroll
            for (int q = 0; q < 20; q++) s += RED(q, c);
            psum[(size_t)blockPt * O + n0 + c] = s;
        }
    }
    __syncthreads();
    #pragma unroll
    for (int j = 0; j < TNC; j++) RED(tm, tn * TNC + j) = vs2[j];
    __syncthreads();
    if (tm == 0) {
        #pragma unroll
        for (int j = 0; j < TNC; j++) {
            int c = tn * TNC + j;
            float s = 0.f;
            #pragma unroll
            for (int q = 0; q < 20; q++) s += RED(q, c);
            psq[(size_t)blockPt * O + n0 + c] = s;
        }
    }
    #undef RED
}

__global__ __launch_bounds__(320)
void edge_fused4_k(const float* __restrict__ F, int ldf, int C, int O,
                   const int* __restrict__ idx, const float* __restrict__ wlot,
                   const float* __restrict__ t,
                   float* __restrict__ gmax, float* __restrict__ gmin,
                   float* __restrict__ psum, float* __restrict__ psq) {
    edge_fused_body<4>(F, ldf, C, O, idx, wlot, t, gmax, gmin, psum, psq);
}

__global__ __launch_bounds__(320)
void edge_fused8_k(const float* __restrict__ F, int ldf, int C, int O,
                   const int* __restrict__ idx, const float* __restrict__ wlot,
                   const float* __restrict__ t,
                   float* __restrict__ gmax, float* __restrict__ gmin,
                   float* __restrict__ psum, float* __restrict__ psq) {
    edge_fused_body<8>(F, ldf, C, O, idx, wlot, t, gmax, gmin, psum, psq);
}

#define EDGE_SMEM(TNC) (640 + 2 * 16 * 80 * 4 + 2 * 16 * (16 * (TNC)) * 4)

// ---------------------------------------------------------------------------
// reduce stats partials -> scale/shift
// ---------------------------------------------------------------------------
__global__ void statsred_k(const float* __restrict__ psum, const float* __restrict__ psq,
                           int R, int O, double invM,
                           const float* __restrict__ gamma, const float* __restrict__ beta,
                           float* __restrict__ scale, float* __restrict__ shift) {
    int o = blockIdx.x;
    double ls = 0.0, ls2 = 0.0;
    for (int r = threadIdx.x; r < R; r += 256) {
        ls += psum[(size_t)r * O + o];
        ls2 += psq[(size_t)r * O + o];
    }
    __shared__ double sd[256], sd2[256];
    sd[threadIdx.x] = ls; sd2[threadIdx.x] = ls2;
    __syncthreads();
    for (int s = 128; s > 0; s >>= 1) {
        if (threadIdx.x < s) { sd[threadIdx.x] += sd[threadIdx.x + s]; sd2[threadIdx.x] += sd2[threadIdx.x + s]; }
        __syncthreads();
    }
    if (threadIdx.x == 0) {
        double mean = sd[0] * invM;
        double var = sd2[0] * invM - mean * mean;
        double sc = (double)gamma[o] / sqrt(var + 1e-5);
        scale[o] = (float)sc;
        shift[o] = (float)((double)beta[o] - mean * sc);
    }
}

// ---------------------------------------------------------------------------
// bnapply + fused xx for the next layer (bit-identical to xx_k ordering)
// ---------------------------------------------------------------------------
__global__ void bnapply_xx_k(const float* __restrict__ gmax, const float* __restrict__ gmin,
                             const float* __restrict__ scale, const float* __restrict__ shift,
                             int O, float* __restrict__ outFeat, int ldo, int colofs,
                             float* __restrict__ xx) {
    int warp = threadIdx.x >> 5, lane = threadIdx.x & 31;
    int p = blockIdx.x * 8 + warp;
    float ss = 0.f;
    for (int o = lane; o < O; o += 32) {
        float sc = scale[o];
        size_t l = (size_t)p * O + o;
        float v = (sc >= 0.f) ? gmax[l] : gmin[l];
        float u = v * sc + shift[o];
        u = u >= 0.f ? u : 0.2f * u;
        outFeat[(size_t)p * ldo + colofs + o] = u;
        ss += u * u;
    }
    #pragma unroll
    for (int off = 16; off; off >>= 1) ss += __shfl_down_sync(0xffffffffu, ss, off);
    if (lane == 0) xx[p] = ss;
}

// ---------------------------------------------------------------------------
// conv5 GEMM: 128x128 tile, 8x8 per thread, double-buffered + stats partials
// ---------------------------------------------------------------------------
__global__ __launch_bounds__(256)
void gemm5_k(const float* __restrict__ A, int lda,
             const float* __restrict__ B, int ldb,
             float* __restrict__ C, int ldc, int K,
             float* __restrict__ psum, float* __restrict__ psq, int Ostats) {
    __shared__ float As[2][16][128];
    __shared__ float Bs[2][16][128];
    int tid = threadIdx.x;
    int tm = tid / 16, tn = tid % 16;
    int m0 = blockIdx.y * 128;
    int n0 = blockIdx.x * 128;
    float acc[8][8];
    #pragma unroll
    for (int i = 0; i < 8; i++)
        #pragma unroll
        for (int j = 0; j < 8; j++) acc[i][j] = 0.f;

    int nch = K / 16;
    #pragma unroll
    for (int q = 0; q < 8; q++) {
        int l = q * 256 + tid;
        int kk = l & 15, m = l >> 4;
        As[0][kk][m] = A[(size_t)(m0 + m) * lda + kk];
    }
    #pragma unroll
    for (int q = 0; q < 8; q++) {
        int l = q * 256 + tid;
        int kk = l >> 7, n = l & 127;
        Bs[0][kk][n] = B[(size_t)kk * ldb + n0 + n];
    }
    __syncthreads();

    for (int ch = 0; ch < nch; ch++) {
        int cur = ch & 1;
        if (ch + 1 < nch) {
            int k0 = (ch + 1) * 16;
            int nxt = cur ^ 1;
            #pragma unroll
            for (int q = 0; q < 8; q++) {
                int l = q * 256 + tid;
                int kk = l & 15, m = l >> 4;
                As[nxt][kk][m] = A[(size_t)(m0 + m) * lda + k0 + kk];
            }
            #pragma unroll
            for (int q = 0; q < 8; q++) {
                int l = q * 256 + tid;
                int kk = l >> 7, n = l & 127;
                Bs[nxt][kk][n] = B[(size_t)(k0 + kk) * ldb + n0 + n];
            }
        }
        #pragma unroll
        for (int kk = 0; kk < 16; kk++) {
            float a[8], b[8];
            *(float4*)&a[0] = *(const float4*)&As[cur][kk][tm * 8];
            *(float4*)&a[4] = *(const float4*)&As[cur][kk][tm * 8 + 4];
            *(float4*)&b[0] = *(const float4*)&Bs[cur][kk][tn * 8];
            *(float4*)&b[4] = *(const float4*)&Bs[cur][kk][tn * 8 + 4];
            #pragma unroll
            for (int i = 0; i < 8; i++)
                #pragma unroll
                for (int j = 0; j < 8; j++) acc[i][j] += a[i] * b[j];
        }
        __syncthreads();
    }
    #pragma unroll
    for (int i = 0; i < 8; i++) {
        float* dst = &C[(size_t)(m0 + tm * 8 + i) * ldc + n0 + tn * 8];
        *(float4*)&dst[0] = *(float4*)&acc[i][0];
        *(float4*)&dst[4] = *(float4*)&acc[i][4];
    }
    float(*red)[128] = As[0];
    float cs[8], cq[8];
    #pragma unroll
    for (int j = 0; j < 8; j++) {
        cs[j] = 0.f; cq[j] = 0.f;
        #pragma unroll
        for (int i = 0; i < 8; i++) { float v = acc[i][j]; cs[j] += v; cq[j] += v * v; }
    }
    __syncthreads();
    #pragma unroll
    for (int j = 0; j < 8; j++) red[tm][tn * 8 + j] = cs[j];
    __syncthreads();
    if (tm == 0) {
        #pragma unroll
        for (int j = 0; j < 8; j++) {
            int c = tn * 8 + j;
            float s = 0.f;
            #pragma unroll
            for (int q = 0; q < 16; q++) s += red[q][c];
            psum[(size_t)blockIdx.y * Ostats + n0 + c] = s;
        }
    }
    __syncthreads();
    #pragma unroll
    for (int j = 0; j < 8; j++) red[tm][tn * 8 + j] = cq[j];
    __syncthreads();
    if (tm == 0) {
        #pragma unroll
        for (int j = 0; j < 8; j++) {
            int c = tn * 8 + j;
            float s = 0.f;
            #pragma unroll
            for (int q = 0; q < 16; q++) s += red[q][c];
            psq[(size_t)blockIdx.y * Ostats + n0 + c] = s;
        }
    }
}

// ---------------------------------------------------------------------------
// conv5 pooling, 2-stage: stage 1 over 128-row chunks, stage 2 combines.
// ---------------------------------------------------------------------------
__global__ void pool1_k(const float* __restrict__ h5, const float* __restrict__ scale,
                        const float* __restrict__ shift,
                        float* __restrict__ pmax, float* __restrict__ psumv) {
    int b = blockIdx.y;
    int zc = blockIdx.z;
    int o = blockIdx.x * blockDim.x + threadIdx.x;
    float sc = scale[o], sh = shift[o];
    float mx = NEG_BIG, sm = 0.f;
    int nbase = zc * 128;
    for (int n = nbase; n < nbase + 128; n++) {
        float v = h5[((size_t)b * NPTS + n) * 1024 + o] * sc + sh;
        v = v >= 0.f ? v : 0.2f * v;
        mx = fmaxf(mx, v);
        sm += v;
    }
    pmax[((size_t)zc * 8 + b) * 1024 + o] = mx;
    psumv[((size_t)zc * 8 + b) * 1024 + o] = sm;
}

__global__ void pool2_k(const float* __restrict__ pmax, const float* __restrict__ psumv,
                        float* __restrict__ pooled) {
    int b = blockIdx.y;
    int o = blockIdx.x * blockDim.x + threadIdx.x;
    float mx = NEG_BIG, sm = 0.f;
    #pragma unroll
    for (int z = 0; z < 8; z++) {
        mx = fmaxf(mx, pmax[((size_t)z * 8 + b) * 1024 + o]);
        sm += psumv[((size_t)z * 8 + b) * 1024 + o];
    }
    pooled[b * 2048 + o] = mx;
    pooled[b * 2048 + 1024 + o] = sm * (1.f / (float)NPTS);
}

// ---------------------------------------------------------------------------
// tiny FC + per-batch BN
// ---------------------------------------------------------------------------
__global__ void fc_k(const float* __restrict__ X, int bcols,
                     const float* __restrict__ W, const float* __restrict__ bias,
                     float* __restrict__ Y, int O) {
    int o = blockIdx.x;
    const float* w = W + (size_t)o * bcols;
    float acc[BATCH];
    #pragma unroll
    for (int b = 0; b < BATCH; b++) acc[b] = 0.f;
    for (int c = threadIdx.x; c < bcols; c += blockDim.x) {
        float wv = w[c];
        #pragma unroll
        for (int b = 0; b < BATCH; b++) acc[b] += X[(size_t)b * bcols + c] * wv;
    }
    #pragma unroll
    for (int b = 0; b < BATCH; b++)
        #pragma unroll
        for (int off = 16; off; off >>= 1)
            acc[b] += __shfl_down_sync(0xffffffffu, acc[b], off);
    __shared__ float sm[BATCH][4];
    int warp = threadIdx.x >> 5, lane = threadIdx.x & 31;
    if (lane == 0)
        #pragma unroll
        for (int b = 0; b < BATCH; b++) sm[b][warp] = acc[b];
    __syncthreads();
    if (threadIdx.x == 0) {
        float bs = bias ? bias[o] : 0.f;
        #pragma unroll
        for (int b = 0; b < BATCH; b++)
            Y[(size_t)b * O + o] = sm[b][0] + sm[b][1] + sm[b][2] + sm[b][3] + bs;
    }
}

__global__ void bnrow_k(const float* __restrict__ Yraw, int O,
                        const float* __restrict__ gamma, const float* __restrict__ beta,
                        float* __restrict__ Yact) {
    int o = blockIdx.x * blockDim.x + threadIdx.x;
    if (o >= O) return;
    float v[BATCH];
    double s = 0.0, s2 = 0.0;
    #pragma unroll
    for (int b = 0; b < BATCH; b++) {
        v[b] = Yraw[(size_t)b * O + o];
        s += v[b]; s2 += (double)v[b] * v[b];
    }
    double mean = s / (double)BATCH;
    double var = s2 / (double)BATCH - mean * mean;
    double sc = (double)gamma[o] / sqrt(var + 1e-5);
    double sh = (double)beta[o] - mean * sc;
    #pragma unroll
    for (int b = 0; b < BATCH; b++) {
        float u = (float)((double)v[b] * sc + sh);
        Yact[(size_t)b * O + o] = u >= 0.f ? u : 0.2f * u;
    }
}

// ---------------------------------------------------------------------------
// host orchestration
// ---------------------------------------------------------------------------
static inline float* sym_addr(const void* symbol) {
    void* p = nullptr;
    cudaGetSymbolAddress(&p, symbol);
    return (float*)p;
}

extern "C" void kernel_launch(void* const* d_in, const int* in_sizes, int n_in,
                              void* d_out, int out_size) {
    const float* x   = (const float*)d_in[0];
    const float* w1  = (const float*)d_in[1];
    const float* g1  = (const float*)d_in[2];
    const float* b1  = (const float*)d_in[3];
    const float* w2  = (const float*)d_in[4];
    const float* g2  = (const float*)d_in[5];
    const float* b2  = (const float*)d_in[6];
    const float* w3  = (const float*)d_in[7];
    const float* g3  = (const float*)d_in[8];
    const float* b3  = (const float*)d_in[9];
    const float* w4  = (const float*)d_in[10];
    const float* g4  = (const float*)d_in[11];
    const float* b4  = (const float*)d_in[12];
    const float* w5  = (const float*)d_in[13];
    const float* g5  = (const float*)d_in[14];
    const float* b5  = (const float*)d_in[15];
    const float* lw1 = (const float*)d_in[16];
    const float* g6  = (const float*)d_in[17];
    const float* b6  = (const float*)d_in[18];
    const float* lw2 = (const float*)d_in[19];
    const float* lb2 = (const float*)d_in[20];
    const float* g7  = (const float*)d_in[21];
    const float* b7  = (const float*)d_in[22];
    const float* lw3 = (const float*)d_in[23];
    const float* lb3 = (const float*)d_in[24];

    float* xp    = sym_addr(g_xp);
    float* feat  = sym_addr(g_feat);
    float* D     = sym_addr(g_D);
    int*   idx   = (int*)sym_addr(g_idx);
    float* xxv   = sym_addr(g_xx);
    float* tbuf  = sym_addr(g_t);
    float* gmax  = sym_addr(g_max);
    float* gmin  = sym_addr(g_min);
    float* h5    = sym_addr(g_h5);
    float* psum  = sym_addr(g_psum);
    float* psq   = sym_addr(g_psq);
    float* scale = sym_addr(g_scale);
    float* shift = sym_addr(g_shift);
    float* wlot  = sym_addr(g_wlot);
    float* whit  = sym_addr(g_whit);
    float* w5t   = sym_addr(g_w5t);
    float* pooled = sym_addr(g_pooled);
    float* fc1raw = sym_addr(g_fc1raw);
    float* fc1    = sym_addr(g_fc1);
    float* fc2raw = sym_addr(g_fc2raw);
    float* fc2    = sym_addr(g_fc2);

    transpose_x_k<<<(BATCH * NPTS * 3 + 255) / 256, 256>>>(x, xp);
    wt_k<<<(1024 * 512 + 255) / 256, 256>>>(w5, 1024, 512, w5t);
    // xx for layer 1 input only; later layers get xx from bnapply_xx_k
    xx_k<<<(NPOINTS * 32 + 255) / 256, 256>>>(xp, 3, 3, xxv);

    struct Cfg {
        const float* Fin; int ldf; int C; int O; int colout;
        const float* W; const float* gamma; const float* beta;
    };
    Cfg cfgs[4] = {
        { xp,          3,   3,   64,  0,   w1, g1, b1 },
        { feat + 0,    512, 64,  64,  64,  w2, g2, b2 },
        { feat + 64,   512, 64,  128, 128, w3, g3, b3 },
        { feat + 128,  512, 128, 256, 256, w4, g4, b4 },
    };

    for (int L = 0; L < 4; L++) {
        const Cfg& c = cfgs[L];
        wprep_k<<<(c.O * c.C + 255) / 256, 256>>>(c.W, c.O, c.C, wlot, whit);
        if (c.C == 3)
            dist3_k<<<dim3(8, 8, 8), 256>>>(c.Fin, xxv, D);
        else
            dist8_k<<<dim3(8, 8, 8), 256>>>(c.Fin, c.ldf, c.C, xxv, D);
        topk_warp_k<<<NPOINTS / 8, 256>>>(D, idx);
        if (c.O >= 128)
            gemm128_k<<<dim3(c.O / 128, NPOINTS / 128), 256>>>(c.Fin, c.ldf, whit, c.O,
                                                               tbuf, c.O, c.C);
        else
            gemm_k<<<dim3(c.O / 64, NPOINTS / 64), 256>>>(c.Fin, c.ldf, whit, c.O,
                                                          tbuf, c.O, NPOINTS, c.O, c.C);
        if (c.O >= 128) {
            edge_fused8_k<<<dim3(c.O / 128, NPOINTS / 4), 320, EDGE_SMEM(8)>>>(
                c.Fin, c.ldf, c.C, c.O, idx, wlot, tbuf, gmax, gmin, psum, psq);
        } else {
            edge_fused4_k<<<dim3(c.O / 64, NPOINTS / 4), 320, EDGE_SMEM(4)>>>(
                c.Fin, c.ldf, c.C, c.O, idx, wlot, tbuf, gmax, gmin, psum, psq);
        }
        statsred_k<<<c.O, 256>>>(psum, psq, NPOINTS / 4, c.O, 1.0 / (double)MROWS,
                                 c.gamma, c.beta, scale, shift);
        // writes feat block + xx for the NEXT layer (bit-identical to xx_k)
        bnapply_xx_k<<<NPOINTS / 8, 256>>>(gmax, gmin, scale, shift, c.O,
                                           feat, 512, c.colout, xxv);
    }

    // conv5: (8192 x 512) @ (512 x 1024) with fused stats partials
    gemm5_k<<<dim3(1024 / 128, NPOINTS / 128), 256>>>(feat, 512, w5t, 1024, h5, 1024,
                                                      512, psum, psq, 1024);
    statsred_k<<<1024, 256>>>(psum, psq, NPOINTS / 128, 1024, 1.0 / (double)NPOINTS,
                              g5, b5, scale, shift);
    // 2-stage pooling; psum/psq are dead here, reuse as partial buffers
    pool1_k<<<dim3(4, 8, 8), 256>>>(h5, scale, shift, psum, psq);
    pool2_k<<<dim3(4, 8), 256>>>(psum, psq, pooled);

    // head
    fc_k<<<512, 128>>>(pooled, 2048, lw1, nullptr, fc1raw, 512);
    bnrow_k<<<2, 256>>>(fc1raw, 512, g6, b6, fc1);
    fc_k<<<256, 128>>>(fc1, 512, lw2, lb2, fc2raw, 256);
    bnrow_k<<<1, 256>>>(fc2raw, 256, g7, b7, fc2);
    fc_k<<<40, 128>>>(fc2, 256, lw3, lb3, (float*)d_out, 40);
}

// round 14
// speedup vs baseline: 1.9260x; 1.0659x over previous
#include <cuda_runtime.h>
#include <math.h>
#include <stdint.h>
#include <stddef.h>

// ---------------------------------------------------------------------------
// DGCNN classifier, B=8, N=1024, K=20.
// Round 14: conv5 on tensor cores via 3xTF32 split MMA (fp32-level accuracy);
// knn path (dist/topk/edge/t/bnapply) unchanged, bit-identical to round 13.
// ---------------------------------------------------------------------------

#define BATCH 8
#define NPTS 1024
#define KNN 20
#define NPOINTS (BATCH * NPTS)          // 8192
#define MROWS (NPOINTS * KNN)           // 163840
#define NEG_BIG (-3.0e38f)
#define POS_BIG (3.0e38f)

__device__ float g_xp[NPOINTS * 3];
__device__ float g_feat[NPOINTS * 512];
__device__ float g_D[(size_t)BATCH * NPTS * NPTS];      // 32 MB
__device__ int   g_idx[NPOINTS * KNN];
__device__ float g_xx[NPOINTS];
__device__ float g_t[NPOINTS * 256];                    // 8 MB
__device__ float g_max[NPOINTS * 256];
__device__ float g_min[NPOINTS * 256];
__device__ float g_h5[(size_t)NPOINTS * 1024];          // 33 MB
__device__ float g_psum[2048 * 256];
__device__ float g_psq[2048 * 256];
__device__ float g_scale[1024];
__device__ float g_shift[1024];
__device__ float g_wlot[128 * 256];
__device__ float g_whit[128 * 256];
__device__ float g_w5t[512 * 1024];
__device__ float g_pooled[BATCH * 2048];
__device__ float g_fc1raw[BATCH * 512];
__device__ float g_fc1[BATCH * 512];
__device__ float g_fc2raw[BATCH * 256];
__device__ float g_fc2[BATCH * 256];

// ---------------------------------------------------------------------------
// small utility kernels
// ---------------------------------------------------------------------------

__global__ void transpose_x_k(const float* __restrict__ x, float* __restrict__ xp) {
    int l = blockIdx.x * blockDim.x + threadIdx.x;
    if (l >= BATCH * NPTS * 3) return;
    int c = l % 3;
    int n = (l / 3) % NPTS;
    int b = l / (3 * NPTS);
    xp[l] = x[((size_t)b * 3 + c) * NPTS + n];
}

__global__ void wprep_k(const float* __restrict__ W, int O, int C,
                        float* __restrict__ wlot, float* __restrict__ whit) {
    int l = blockIdx.x * blockDim.x + threadIdx.x;
    if (l >= O * C) return;
    int o = l % O;
    int c = l / O;
    wlot[l] = W[(size_t)o * 2 * C + c];
    whit[l] = W[(size_t)o * 2 * C + C + c];
}

__global__ void wt_k(const float* __restrict__ W, int O, int Kc, float* __restrict__ Wt) {
    int l = blockIdx.x * blockDim.x + threadIdx.x;
    if (l >= O * Kc) return;
    int o = l % O;
    int c = l / O;
    Wt[l] = W[(size_t)o * Kc + c];
}

// xx for layer 1 input (xp, C=3)
__global__ void xx_k(const float* __restrict__ F, int ldf, int C, float* __restrict__ xx) {
    int g = blockIdx.x * blockDim.x + threadIdx.x;
    int p = g >> 5, lane = g & 31;
    if (p >= NPOINTS) return;
    const float* f = F + (size_t)p * ldf;
    float s = 0.f;
    for (int c = lane; c < C; c += 32) { float v = f[c]; s += v * v; }
    #pragma unroll
    for (int off = 16; off; off >>= 1) s += __shfl_down_sync(0xffffffffu, s, off);
    if (lane == 0) xx[p] = s;
}

// ---------------------------------------------------------------------------
// pairwise neg-dist, C=3 special case (layer 1)
// ---------------------------------------------------------------------------
__global__ __launch_bounds__(256)
void dist3_k(const float* __restrict__ F,
             const float* __restrict__ xx, float* __restrict__ D) {
    int bi = blockIdx.y, bj = blockIdx.x;
    if (bj < bi) return;
    __shared__ float Fi[3][128];
    __shared__ float Fj[3][128];
    int b = blockIdx.z;
    int i0 = bi * 128, j0 = bj * 128;
    int tid = threadIdx.x;
    int tm = tid / 16, tn = tid % 16;
    const float* Fb = F + (size_t)b * NPTS * 3;
    if (tid < 128) {
        Fi[0][tid] = Fb[(size_t)(i0 + tid) * 3 + 0];
        Fi[1][tid] = Fb[(size_t)(i0 + tid) * 3 + 1];
        Fi[2][tid] = Fb[(size_t)(i0 + tid) * 3 + 2];
    } else {
        int m = tid - 128;
        Fj[0][m] = Fb[(size_t)(j0 + m) * 3 + 0];
        Fj[1][m] = Fb[(size_t)(j0 + m) * 3 + 1];
        Fj[2][m] = Fb[(size_t)(j0 + m) * 3 + 2];
    }
    __syncthreads();

    float acc[8][8];
    #pragma unroll
    for (int i = 0; i < 8; i++)
        #pragma unroll
        for (int j = 0; j < 8; j++) acc[i][j] = 0.f;
    #pragma unroll
    for (int kk = 0; kk < 3; kk++) {
        float a[8], bb[8];
        #pragma unroll
        for (int i = 0; i < 8; i++) a[i] = Fi[kk][tm * 8 + i];
        #pragma unroll
        for (int j = 0; j < 8; j++) bb[j] = Fj[kk][tn * 8 + j];
        #pragma unroll
        for (int i = 0; i < 8; i++)
            #pragma unroll
            for (int j = 0; j < 8; j++) acc[i][j] += a[i] * bb[j];
    }

    float xi[8], xj[8];
    #pragma unroll
    for (int i = 0; i < 8; i++) xi[i] = xx[b * NPTS + i0 + tm * 8 + i];
    #pragma unroll
    for (int j = 0; j < 8; j++) xj[j] = xx[b * NPTS + j0 + tn * 8 + j];

    #pragma unroll
    for (int i = 0; i < 8; i++) {
        int ii = i0 + tm * 8 + i;
        float out[8];
        #pragma unroll
        for (int j = 0; j < 8; j++) out[j] = -(xi[i] - 2.f * acc[i][j] + xj[j]);
        float* dst = &D[((size_t)b * NPTS + ii) * NPTS + j0 + tn * 8];
        *(float4*)&dst[0] = *(float4*)&out[0];
        *(float4*)&dst[4] = *(float4*)&out[4];
    }
    if (bj > bi) {
        #pragma unroll
        for (int j = 0; j < 8; j++) {
            int jj = j0 + tn * 8 + j;
            float out[8];
            #pragma unroll
            for (int i = 0; i < 8; i++) out[i] = -(xj[j] - 2.f * acc[i][j] + xi[i]);
            float* dst = &D[((size_t)b * NPTS + jj) * NPTS + i0 + tm * 8];
            *(float4*)&dst[0] = *(float4*)&out[0];
            *(float4*)&dst[4] = *(float4*)&out[4];
        }
    }
}

// ---------------------------------------------------------------------------
// pairwise neg-dist, generic (C>=16), 128x128, 8x8, SYMMETRIC, double-buffered
// ---------------------------------------------------------------------------
__global__ __launch_bounds__(256)
void dist8_k(const float* __restrict__ F, int ldf, int C,
             const float* __restrict__ xx, float* __restrict__ D) {
    int bi = blockIdx.y, bj = blockIdx.x;
    if (bj < bi) return;
    __shared__ float Fi[2][16][128];
    __shared__ float Fj[2][16][128];
    int b = blockIdx.z;
    int i0 = bi * 128, j0 = bj * 128;
    int tid = threadIdx.x;
    int tm = tid / 16, tn = tid % 16;
    const float* Fb = F + (size_t)b * NPTS * ldf;
    float acc[8][8];
    #pragma unroll
    for (int i = 0; i < 8; i++)
        #pragma unroll
        for (int j = 0; j < 8; j++) acc[i][j] = 0.f;

    int nch = (C + 15) / 16;

    #pragma unroll
    for (int q = 0; q < 8; q++) {
        int l = q * 256 + tid;
        int kk = l & 15, m = l >> 4;
        Fi[0][kk][m] = (kk < C) ? Fb[(size_t)(i0 + m) * ldf + kk] : 0.f;
        Fj[0][kk][m] = (kk < C) ? Fb[(size_t)(j0 + m) * ldf + kk] : 0.f;
    }
    __syncthreads();

    for (int ch = 0; ch < nch; ch++) {
        int cur = ch & 1;
        if (ch + 1 < nch) {
            int c0 = (ch + 1) * 16;
            int nxt = cur ^ 1;
            #pragma unroll
            for (int q = 0; q < 8; q++) {
                int l = q * 256 + tid;
                int kk = l & 15, m = l >> 4;
                Fi[nxt][kk][m] = (c0 + kk < C) ? Fb[(size_t)(i0 + m) * ldf + c0 + kk] : 0.f;
                Fj[nxt][kk][m] = (c0 + kk < C) ? Fb[(size_t)(j0 + m) * ldf + c0 + kk] : 0.f;
            }
        }
        #pragma unroll
        for (int kk = 0; kk < 16; kk++) {
            float a[8], bb[8];
            *(float4*)&a[0] = *(const float4*)&Fi[cur][kk][tm * 8];
            *(float4*)&a[4] = *(const float4*)&Fi[cur][kk][tm * 8 + 4];
            *(float4*)&bb[0] = *(const float4*)&Fj[cur][kk][tn * 8];
            *(float4*)&bb[4] = *(const float4*)&Fj[cur][kk][tn * 8 + 4];
            #pragma unroll
            for (int i = 0; i < 8; i++)
                #pragma unroll
                for (int j = 0; j < 8; j++) acc[i][j] += a[i] * bb[j];
        }
        __syncthreads();
    }
    float xi[8], xj[8];
    #pragma unroll
    for (int i = 0; i < 8; i++) xi[i] = xx[b * NPTS + i0 + tm * 8 + i];
    #pragma unroll
    for (int j = 0; j < 8; j++) xj[j] = xx[b * NPTS + j0 + tn * 8 + j];

    #pragma unroll
    for (int i = 0; i < 8; i++) {
        int ii = i0 + tm * 8 + i;
        float out[8];
        #pragma unroll
        for (int j = 0; j < 8; j++) out[j] = -(xi[i] - 2.f * acc[i][j] + xj[j]);
        float* dst = &D[((size_t)b * NPTS + ii) * NPTS + j0 + tn * 8];
        *(float4*)&dst[0] = *(float4*)&out[0];
        *(float4*)&dst[4] = *(float4*)&out[4];
    }
    if (bj > bi) {
        #pragma unroll
        for (int j = 0; j < 8; j++) {
            int jj = j0 + tn * 8 + j;
            float out[8];
            #pragma unroll
            for (int i = 0; i < 8; i++) out[i] = -(xj[j] - 2.f * acc[i][j] + xi[i]);
            float* dst = &D[((size_t)b * NPTS + jj) * NPTS + i0 + tm * 8];
            *(float4*)&dst[0] = *(float4*)&out[0];
            *(float4*)&dst[4] = *(float4*)&out[4];
        }
    }
}

// ---------------------------------------------------------------------------
// warp-per-row top-20 by iterative argmax, row cached in registers.
// ---------------------------------------------------------------------------
__global__ void topk_warp_k(const float* __restrict__ D, int* __restrict__ idx) {
    int warp = threadIdx.x >> 5, lane = threadIdx.x & 31;
    int row = blockIdx.x * 8 + warp;
    float vals[32];
    const float* dr = D + (size_t)row * NPTS;
    #pragma unroll
    for (int i = 0; i < 32; i++) vals[i] = dr[i * 32 + lane];

    float lbv = vals[0]; int lbi = 0;
    #pragma unroll
    for (int i = 1; i < 32; i++) if (vals[i] > lbv) { lbv = vals[i]; lbi = i; }

    for (int it = 0; it < KNN; it++) {
        float cv = lbv;
        int cg = lbi * 32 + lane;
        #pragma unroll
        for (int off = 16; off; off >>= 1) {
            float ov = __shfl_down_sync(0xffffffffu, cv, off);
            int oi = __shfl_down_sync(0xffffffffu, cg, off);
            if (ov > cv || (ov == cv && oi < cg)) { cv = ov; cg = oi; }
        }
        int winner = __shfl_sync(0xffffffffu, cg, 0);
        if (lane == 0) idx[row * KNN + it] = winner;
        if ((winner & 31) == lane) {
            int slot = winner >> 5;
            #pragma unroll
            for (int i = 0; i < 32; i++) if (i == slot) vals[i] = NEG_BIG;
            lbv = vals[0]; lbi = 0;
            #pragma unroll
            for (int i = 1; i < 32; i++) if (vals[i] > lbv) { lbv = vals[i]; lbi = i; }
        }
    }
}

// ---------------------------------------------------------------------------
// generic 64x64 tiled GEMM (t for O=64 layers)
// ---------------------------------------------------------------------------
__global__ void gemm_k(const float* __restrict__ A, int lda,
                       const float* __restrict__ B, int ldb,
                       float* __restrict__ C, int ldc,
                       int M, int N, int K) {
    __shared__ float As[16][65];
    __shared__ float Bs[16][64];
    int tid = threadIdx.x;
    int tm = tid / 16, tn = tid % 16;
    int m0 = blockIdx.y * 64;
    int n0 = blockIdx.x * 64;
    float acc[4][4];
    #pragma unroll
    for (int i = 0; i < 4; i++)
        #pragma unroll
        for (int j = 0; j < 4; j++) acc[i][j] = 0.f;

    for (int k0 = 0; k0 < K; k0 += 16) {
        for (int l = tid; l < 64 * 16; l += 256) {
            int m = l >> 4, kk = l & 15;
            As[kk][m] = (k0 + kk < K) ? A[(size_t)(m0 + m) * lda + k0 + kk] : 0.f;
        }
        for (int l = tid; l < 16 * 64; l += 256) {
            int kk = l >> 6, n = l & 63;
            Bs[kk][n] = (k0 + kk < K) ? B[(size_t)(k0 + kk) * ldb + n0 + n] : 0.f;
        }
        __syncthreads();
        #pragma unroll
        for (int kk = 0; kk < 16; kk++) {
            float a[4], b[4];
            #pragma unroll
            for (int i = 0; i < 4; i++) a[i] = As[kk][tm * 4 + i];
            #pragma unroll
            for (int j = 0; j < 4; j++) b[j] = Bs[kk][tn * 4 + j];
            #pragma unroll
            for (int i = 0; i < 4; i++)
                #pragma unroll
                for (int j = 0; j < 4; j++) acc[i][j] += a[i] * b[j];
        }
        __syncthreads();
    }
    #pragma unroll
    for (int i = 0; i < 4; i++)
        #pragma unroll
        for (int j = 0; j < 4; j++)
            C[(size_t)(m0 + tm * 4 + i) * ldc + n0 + tn * 4 + j] = acc[i][j];
}

// ---------------------------------------------------------------------------
// 128x128 tiled GEMM, 8x8 per thread, double-buffered (t for O>=128)
// ---------------------------------------------------------------------------
__global__ __launch_bounds__(256)
void gemm128_k(const float* __restrict__ A, int lda,
               const float* __restrict__ B, int ldb,
               float* __restrict__ C, int ldc, int K) {
    __shared__ float As[2][16][128];
    __shared__ float Bs[2][16][128];
    int tid = threadIdx.x;
    int tm = tid / 16, tn = tid % 16;
    int m0 = blockIdx.y * 128;
    int n0 = blockIdx.x * 128;
    float acc[8][8];
    #pragma unroll
    for (int i = 0; i < 8; i++)
        #pragma unroll
        for (int j = 0; j < 8; j++) acc[i][j] = 0.f;

    int nch = K / 16;
    #pragma unroll
    for (int q = 0; q < 8; q++) {
        int l = q * 256 + tid;
        int kk = l & 15, m = l >> 4;
        As[0][kk][m] = A[(size_t)(m0 + m) * lda + kk];
    }
    #pragma unroll
    for (int q = 0; q < 8; q++) {
        int l = q * 256 + tid;
        int kk = l >> 7, n = l & 127;
        Bs[0][kk][n] = B[(size_t)kk * ldb + n0 + n];
    }
    __syncthreads();

    for (int ch = 0; ch < nch; ch++) {
        int cur = ch & 1;
        if (ch + 1 < nch) {
            int k0 = (ch + 1) * 16;
            int nxt = cur ^ 1;
            #pragma unroll
            for (int q = 0; q < 8; q++) {
                int l = q * 256 + tid;
                int kk = l & 15, m = l >> 4;
                As[nxt][kk][m] = A[(size_t)(m0 + m) * lda + k0 + kk];
            }
            #pragma unroll
            for (int q = 0; q < 8; q++) {
                int l = q * 256 + tid;
                int kk = l >> 7, n = l & 127;
                Bs[nxt][kk][n] = B[(size_t)(k0 + kk) * ldb + n0 + n];
            }
        }
        #pragma unroll
        for (int kk = 0; kk < 16; kk++) {
            float a[8], b[8];
            *(float4*)&a[0] = *(const float4*)&As[cur][kk][tm * 8];
            *(float4*)&a[4] = *(const float4*)&As[cur][kk][tm * 8 + 4];
            *(float4*)&b[0] = *(const float4*)&Bs[cur][kk][tn * 8];
            *(float4*)&b[4] = *(const float4*)&Bs[cur][kk][tn * 8 + 4];
            #pragma unroll
            for (int i = 0; i < 8; i++)
                #pragma unroll
                for (int j = 0; j < 8; j++) acc[i][j] += a[i] * b[j];
        }
        __syncthreads();
    }
    #pragma unroll
    for (int i = 0; i < 8; i++) {
        float* dst = &C[(size_t)(m0 + tm * 8 + i) * ldc + n0 + tn * 8];
        *(float4*)&dst[0] = *(float4*)&acc[i][0];
        *(float4*)&dst[4] = *(float4*)&acc[i][4];
    }
}

// ---------------------------------------------------------------------------
// fused edge layer body, double-buffered, dynamic smem
// ---------------------------------------------------------------------------
template <int TNC>
__device__ __forceinline__
void edge_fused_body(const float* __restrict__ F, int ldf, int C, int O,
                     const int* __restrict__ idx, const float* __restrict__ wlot,
                     const float* __restrict__ t,
                     float* __restrict__ gmax, float* __restrict__ gmin,
                     float* __restrict__ psum, float* __restrict__ psq) {
    constexpr int NCOLS = 16 * TNC;
    extern __shared__ char esm[];
    int*   sidx = (int*)esm;
    int*   sctr = sidx + 80;
    float* Abuf = (float*)(esm + 640);
    float* Bbuf = Abuf + 2 * 16 * 80;
    float* redf = (float*)(esm + 640);

    int tid = threadIdx.x;
    int tm = tid / 16;
    int tn = tid % 16;
    int blockPt = blockIdx.y;
    int n0 = blockIdx.x * NCOLS;

    if (tid < 80) {
        int gp = blockPt * 4 + tid / 20;
        int b = gp >> 10;
        int nbr = idx[blockPt * 80 + tid];
        sidx[tid] = ((b << 10) + nbr) * ldf;
        sctr[tid] = gp * ldf;
    }
    __syncthreads();

    const bool vec = (C % 16 == 0);
    int gm = tid >> 2;
    int gc = (tid & 3) * 4;

    float acc[4][TNC];
    #pragma unroll
    for (int i = 0; i < 4; i++)
        #pragma unroll
        for (int j = 0; j < TNC; j++) acc[i][j] = 0.f;

    int nch = (C + 15) / 16;

    auto load_chunk = [&](int c0, int buf) {
        float* A = Abuf + buf * (16 * 80);
        float* B = Bbuf + buf * (16 * NCOLS);
        if (vec) {
            float4 vn = *(const float4*)&F[(size_t)sidx[gm] + c0 + gc];
            float4 vc = *(const float4*)&F[(size_t)sctr[gm] + c0 + gc];
            A[(gc + 0) * 80 + gm] = vn.x - vc.x;
            A[(gc + 1) * 80 + gm] = vn.y - vc.y;
            A[(gc + 2) * 80 + gm] = vn.z - vc.z;
            A[(gc + 3) * 80 + gm] = vn.w - vc.w;
        } else {
            #pragma unroll
            for (int q = 0; q < 4; q++) {
                int l = q * 320 + tid;
                int m = l % 80, kk = l / 80;
                int cc = c0 + kk;
                A[kk * 80 + m] = (cc < C) ? (F[(size_t)sidx[m] + cc] - F[(size_t)sctr[m] + cc]) : 0.f;
            }
        }
        for (int l = tid; l < 16 * NCOLS; l += 320) {
            int kk = l / NCOLS, n = l % NCOLS;
            B[kk * NCOLS + n] = (c0 + kk < C) ? wlot[(size_t)(c0 + kk) * O + n0 + n] : 0.f;
        }
    };

    load_chunk(0, 0);
    __syncthreads();

    for (int ch = 0; ch < nch; ch++) {
        int cur = ch & 1;
        if (ch + 1 < nch) load_chunk((ch + 1) * 16, cur ^ 1);
        const float* A = Abuf + cur * (16 * 80);
        const float* B = Bbuf + cur * (16 * NCOLS);
        #pragma unroll
        for (int kk = 0; kk < 16; kk++) {
            float a[4], b[TNC];
            *(float4*)a = *(const float4*)&A[kk * 80 + tm * 4];
            #pragma unroll
            for (int v = 0; v < TNC / 4; v++)
                *(float4*)&b[v * 4] = *(const float4*)&B[kk * NCOLS + tn * TNC + v * 4];
            #pragma unroll
            for (int i = 0; i < 4; i++)
                #pragma unroll
                for (int j = 0; j < TNC; j++) acc[i][j] += a[i] * b[j];
        }
        __syncthreads();
    }

    #define RED(r, c) redf[(r) * (NCOLS + 4) + (c)]

    int P = blockPt * 4 + tm / 5;
    float tvj[TNC];
    #pragma unroll
    for (int v = 0; v < TNC / 4; v++)
        *(float4*)&tvj[v * 4] = *(const float4*)&t[(size_t)P * O + n0 + tn * TNC + v * 4];

    float vmax[TNC], vmin[TNC], vs[TNC], vs2[TNC];
    #pragma unroll
    for (int j = 0; j < TNC; j++) {
        vmax[j] = NEG_BIG; vmin[j] = POS_BIG; vs[j] = 0.f; vs2[j] = 0.f;
        #pragma unroll
        for (int i = 0; i < 4; i++) {
            float v = acc[i][j] + tvj[j];
            vmax[j] = fmaxf(vmax[j], v);
            vmin[j] = fminf(vmin[j], v);
            vs[j] += v;
            vs2[j] += v * v;
        }
    }

    #pragma unroll
    for (int j = 0; j < TNC; j++) RED(tm, tn * TNC + j) = vmax[j];
    __syncthreads();
    if (tm % 5 == 0) {
        #pragma unroll
        for (int j = 0; j < TNC; j++) {
            int c = tn * TNC + j;
            float m = RED(tm, c);
            #pragma unroll
            for (int q = 1; q < 5; q++) m = fmaxf(m, RED(tm + q, c));
            gmax[(size_t)P * O + n0 + c] = m;
        }
    }
    __syncthreads();
    #pragma unroll
    for (int j = 0; j < TNC; j++) RED(tm, tn * TNC + j) = vmin[j];
    __syncthreads();
    if (tm % 5 == 0) {
        #pragma unroll
        for (int j = 0; j < TNC; j++) {
            int c = tn * TNC + j;
            float m = RED(tm, c);
            #pragma unroll
            for (int q = 1; q < 5; q++) m = fminf(m, RED(tm + q, c));
            gmin[(size_t)P * O + n0 + c] = m;
        }
    }
    __syncthreads();
    #pragma unroll
    for (int j = 0; j < TNC; j++) RED(tm, tn * TNC + j) = vs[j];
    __syncthreads();
    if (tm == 0) {
        #pragma unroll
        for (int j = 0; j < TNC; j++) {
            int c = tn * TNC + j;
            float s = 0.f;
            #pragma unroll
            for (int q = 0; q < 20; q++) s += RED(q, c);
            psum[(size_t)blockPt * O + n0 + c] = s;
        }
    }
    __syncthreads();
    #pragma unroll
    for (int j = 0; j < TNC; j++) RED(tm, tn * TNC + j) = vs2[j];
    __syncthreads();
    if (tm == 0) {
        #pragma unroll
        for (int j = 0; j < TNC; j++) {
            int c = tn * TNC + j;
            float s = 0.f;
            #pragma unroll
            for (int q = 0; q < 20; q++) s += RED(q, c);
            psq[(size_t)blockPt * O + n0 + c] = s;
        }
    }
    #undef RED
}

__global__ __launch_bounds__(320)
void edge_fused4_k(const float* __restrict__ F, int ldf, int C, int O,
                   const int* __restrict__ idx, const float* __restrict__ wlot,
                   const float* __restrict__ t,
                   float* __restrict__ gmax, float* __restrict__ gmin,
                   float* __restrict__ psum, float* __restrict__ psq) {
    edge_fused_body<4>(F, ldf, C, O, idx, wlot, t, gmax, gmin, psum, psq);
}

__global__ __launch_bounds__(320)
void edge_fused8_k(const float* __restrict__ F, int ldf, int C, int O,
                   const int* __restrict__ idx, const float* __restrict__ wlot,
                   const float* __restrict__ t,
                   float* __restrict__ gmax, float* __restrict__ gmin,
                   float* __restrict__ psum, float* __restrict__ psq) {
    edge_fused_body<8>(F, ldf, C, O, idx, wlot, t, gmax, gmin, psum, psq);
}

#define EDGE_SMEM(TNC) (640 + 2 * 16 * 80 * 4 + 2 * 16 * (16 * (TNC)) * 4)

// ---------------------------------------------------------------------------
// reduce stats partials -> scale/shift
// ---------------------------------------------------------------------------
__global__ void statsred_k(const float* __restrict__ psum, const float* __restrict__ psq,
                           int R, int O, double invM,
                           const float* __restrict__ gamma, const float* __restrict__ beta,
                           float* __restrict__ scale, float* __restrict__ shift) {
    int o = blockIdx.x;
    double ls = 0.0, ls2 = 0.0;
    for (int r = threadIdx.x; r < R; r += 256) {
        ls += psum[(size_t)r * O + o];
        ls2 += psq[(size_t)r * O + o];
    }
    __shared__ double sd[256], sd2[256];
    sd[threadIdx.x] = ls; sd2[threadIdx.x] = ls2;
    __syncthreads();
    for (int s = 128; s > 0; s >>= 1) {
        if (threadIdx.x < s) { sd[threadIdx.x] += sd[threadIdx.x + s]; sd2[threadIdx.x] += sd2[threadIdx.x + s]; }
        __syncthreads();
    }
    if (threadIdx.x == 0) {
        double mean = sd[0] * invM;
        double var = sd2[0] * invM - mean * mean;
        double sc = (double)gamma[o] / sqrt(var + 1e-5);
        scale[o] = (float)sc;
        shift[o] = (float)((double)beta[o] - mean * sc);
    }
}

// ---------------------------------------------------------------------------
// bnapply + fused xx for the next layer (bit-identical to xx_k ordering)
// ---------------------------------------------------------------------------
__global__ void bnapply_xx_k(const float* __restrict__ gmax, const float* __restrict__ gmin,
                             const float* __restrict__ scale, const float* __restrict__ shift,
                             int O, float* __restrict__ outFeat, int ldo, int colofs,
                             float* __restrict__ xx) {
    int warp = threadIdx.x >> 5, lane = threadIdx.x & 31;
    int p = blockIdx.x * 8 + warp;
    float ss = 0.f;
    for (int o = lane; o < O; o += 32) {
        float sc = scale[o];
        size_t l = (size_t)p * O + o;
        float v = (sc >= 0.f) ? gmax[l] : gmin[l];
        float u = v * sc + shift[o];
        u = u >= 0.f ? u : 0.2f * u;
        outFeat[(size_t)p * ldo + colofs + o] = u;
        ss += u * u;
    }
    #pragma unroll
    for (int off = 16; off; off >>= 1) ss += __shfl_down_sync(0xffffffffu, ss, off);
    if (lane == 0) xx[p] = ss;
}

// ---------------------------------------------------------------------------
// conv5 GEMM on tensor cores: 3xTF32 split MMA (m16n8k8), ~fp32 accuracy.
// Tile 128x128, 8 warps (2x4), warp tile 64x32; K chunk 16, single-buffered.
// A smem stride 20, B stride 136: conflict-free for the fragment pattern.
// ---------------------------------------------------------------------------
__device__ __forceinline__ uint32_t f2tf32(float v) {
    uint32_t r;
    asm("cvt.rna.tf32.f32 %0, %1;" : "=r"(r) : "f"(v));
    return r;
}

__device__ __forceinline__ void mma_tf32(float* d, uint32_t a0, uint32_t a1,
                                         uint32_t a2, uint32_t a3,
                                         uint32_t b0, uint32_t b1) {
    asm volatile(
        "mma.sync.aligned.m16n8k8.row.col.f32.tf32.tf32.f32 "
        "{%0,%1,%2,%3}, {%4,%5,%6,%7}, {%8,%9}, {%0,%1,%2,%3};"
        : "+f"(d[0]), "+f"(d[1]), "+f"(d[2]), "+f"(d[3])
        : "r"(a0), "r"(a1), "r"(a2), "r"(a3), "r"(b0), "r"(b1));
}

__global__ __launch_bounds__(256)
void gemm5_tf32_k(const float* __restrict__ A, int lda,
                  const float* __restrict__ B, int ldb,
                  float* __restrict__ C, int ldc, int K) {
    __shared__ uint32_t Ah[128][20], Al[128][20];
    __shared__ uint32_t Bh[16][136], Bl[16][136];
    int tid = threadIdx.x;
    int warp = tid >> 5, lane = tid & 31;
    int wm = warp >> 2;          // 0..1 (row 64-block)
    int wn = warp & 3;           // 0..3 (col 32-block)
    int grp = lane >> 2, tig = lane & 3;
    int m0 = blockIdx.y * 128, n0 = blockIdx.x * 128;

    float acc[4][4][4];
    #pragma unroll
    for (int mf = 0; mf < 4; mf++)
        #pragma unroll
        for (int nf = 0; nf < 4; nf++)
            #pragma unroll
            for (int r = 0; r < 4; r++) acc[mf][nf][r] = 0.f;

    for (int k0 = 0; k0 < K; k0 += 16) {
        #pragma unroll
        for (int q = 0; q < 8; q++) {
            int l = q * 256 + tid;
            int m = l >> 4, kk = l & 15;
            float v = A[(size_t)(m0 + m) * lda + k0 + kk];
            uint32_t hi = f2tf32(v);
            uint32_t lo = f2tf32(v - __uint_as_float(hi));
            Ah[m][kk] = hi; Al[m][kk] = lo;
        }
        #pragma unroll
        for (int q = 0; q < 8; q++) {
            int l = q * 256 + tid;
            int kk = l >> 7, n = l & 127;
            float v = B[(size_t)(k0 + kk) * ldb + n0 + n];
            uint32_t hi = f2tf32(v);
            uint32_t lo = f2tf32(v - __uint_as_float(hi));
            Bh[kk][n] = hi; Bl[kk][n] = lo;
        }
        __syncthreads();

        #pragma unroll
        for (int ks = 0; ks < 16; ks += 8) {
            uint32_t bh[4][2], bl[4][2];
            #pragma unroll
            for (int nf = 0; nf < 4; nf++) {
                int col = wn * 32 + nf * 8 + grp;
                bh[nf][0] = Bh[ks + tig][col];
                bh[nf][1] = Bh[ks + tig + 4][col];
                bl[nf][0] = Bl[ks + tig][col];
                bl[nf][1] = Bl[ks + tig + 4][col];
            }
            #pragma unroll
            for (int mf = 0; mf < 4; mf++) {
                int r0 = wm * 64 + mf * 16 + grp;
                uint32_t ah0 = Ah[r0][ks + tig];
                uint32_t ah1 = Ah[r0 + 8][ks + tig];
                uint32_t ah2 = Ah[r0][ks + tig + 4];
                uint32_t ah3 = Ah[r0 + 8][ks + tig + 4];
                uint32_t al0 = Al[r0][ks + tig];
                uint32_t al1 = Al[r0 + 8][ks + tig];
                uint32_t al2 = Al[r0][ks + tig + 4];
                uint32_t al3 = Al[r0 + 8][ks + tig + 4];
                #pragma unroll
                for (int nf = 0; nf < 4; nf++) {
                    float* d = acc[mf][nf];
                    mma_tf32(d, al0, al1, al2, al3, bh[nf][0], bh[nf][1]);
                    mma_tf32(d, ah0, ah1, ah2, ah3, bl[nf][0], bl[nf][1]);
                    mma_tf32(d, ah0, ah1, ah2, ah3, bh[nf][0], bh[nf][1]);
                }
            }
        }
        __syncthreads();
    }

    // epilogue: D fragment layout (r, 2*tig), (r, 2*tig+1), (r+8, ...), etc.
    #pragma unroll
    for (int mf = 0; mf < 4; mf++) {
        int r = m0 + wm * 64 + mf * 16 + grp;
        #pragma unroll
        for (int nf = 0; nf < 4; nf++) {
            int c = n0 + wn * 32 + nf * 8 + 2 * tig;
            *(float2*)&C[(size_t)r * ldc + c]       = make_float2(acc[mf][nf][0], acc[mf][nf][1]);
            *(float2*)&C[(size_t)(r + 8) * ldc + c] = make_float2(acc[mf][nf][2], acc[mf][nf][3]);
        }
    }
}

// ---------------------------------------------------------------------------
// h5 stats: per-channel sum/sumsq partials over 128-row chunks (coalesced).
// grid 64 blocks x 256 threads; 4 channels per thread.
// ---------------------------------------------------------------------------
__global__ void stats_h5_k(const float* __restrict__ h5,
                           float* __restrict__ psum, float* __restrict__ psq) {
    int blk = blockIdx.x;
    int tid = threadIdx.x;
    float s[4] = {0.f, 0.f, 0.f, 0.f};
    float s2[4] = {0.f, 0.f, 0.f, 0.f};
    int rbase = blk * 128;
    for (int r = 0; r < 128; r++) {
        const float* row = h5 + (size_t)(rbase + r) * 1024;
        #pragma unroll
        for (int q = 0; q < 4; q++) {
            float v = row[tid + q * 256];
            s[q] += v; s2[q] += v * v;
        }
    }
    #pragma unroll
    for (int q = 0; q < 4; q++) {
        psum[(size_t)blk * 1024 + tid + q * 256] = s[q];
        psq[(size_t)blk * 1024 + tid + q * 256] = s2[q];
    }
}

// ---------------------------------------------------------------------------
// conv5 pooling, 2-stage
// ---------------------------------------------------------------------------
__global__ void pool1_k(const float* __restrict__ h5, const float* __restrict__ scale,
                        const float* __restrict__ shift,
                        float* __restrict__ pmax, float* __restrict__ psumv) {
    int b = blockIdx.y;
    int zc = blockIdx.z;
    int o = blockIdx.x * blockDim.x + threadIdx.x;
    float sc = scale[o], sh = shift[o];
    float mx = NEG_BIG, sm = 0.f;
    int nbase = zc * 128;
    for (int n = nbase; n < nbase + 128; n++) {
        float v = h5[((size_t)b * NPTS + n) * 1024 + o] * sc + sh;
        v = v >= 0.f ? v : 0.2f * v;
        mx = fmaxf(mx, v);
        sm += v;
    }
    pmax[((size_t)zc * 8 + b) * 1024 + o] = mx;
    psumv[((size_t)zc * 8 + b) * 1024 + o] = sm;
}

__global__ void pool2_k(const float* __restrict__ pmax, const float* __restrict__ psumv,
                        float* __restrict__ pooled) {
    int b = blockIdx.y;
    int o = blockIdx.x * blockDim.x + threadIdx.x;
    float mx = NEG_BIG, sm = 0.f;
    #pragma unroll
    for (int z = 0; z < 8; z++) {
        mx = fmaxf(mx, pmax[((size_t)z * 8 + b) * 1024 + o]);
        sm += psumv[((size_t)z * 8 + b) * 1024 + o];
    }
    pooled[b * 2048 + o] = mx;
    pooled[b * 2048 + 1024 + o] = sm * (1.f / (float)NPTS);
}

// ---------------------------------------------------------------------------
// tiny FC + per-batch BN
// ---------------------------------------------------------------------------
__global__ void fc_k(const float* __restrict__ X, int bcols,
                     const float* __restrict__ W, const float* __restrict__ bias,
                     float* __restrict__ Y, int O) {
    int o = blockIdx.x;
    const float* w = W + (size_t)o * bcols;
    float acc[BATCH];
    #pragma unroll
    for (int b = 0; b < BATCH; b++) acc[b] = 0.f;
    for (int c = threadIdx.x; c < bcols; c += blockDim.x) {
        float wv = w[c];
        #pragma unroll
        for (int b = 0; b < BATCH; b++) acc[b] += X[(size_t)b * bcols + c] * wv;
    }
    #pragma unroll
    for (int b = 0; b < BATCH; b++)
        #pragma unroll
        for (int off = 16; off; off >>= 1)
            acc[b] += __shfl_down_sync(0xffffffffu, acc[b], off);
    __shared__ float sm[BATCH][4];
    int warp = threadIdx.x >> 5, lane = threadIdx.x & 31;
    if (lane == 0)
        #pragma unroll
        for (int b = 0; b < BATCH; b++) sm[b][warp] = acc[b];
    __syncthreads();
    if (threadIdx.x == 0) {
        float bs = bias ? bias[o] : 0.f;
        #pragma unroll
        for (int b = 0; b < BATCH; b++)
            Y[(size_t)b * O + o] = sm[b][0] + sm[b][1] + sm[b][2] + sm[b][3] + bs;
    }
}

__global__ void bnrow_k(const float* __restrict__ Yraw, int O,
                        const float* __restrict__ gamma, const float* __restrict__ beta,
                        float* __restrict__ Yact) {
    int o = blockIdx.x * blockDim.x + threadIdx.x;
    if (o >= O) return;
    float v[BATCH];
    double s = 0.0, s2 = 0.0;
    #pragma unroll
    for (int b = 0; b < BATCH; b++) {
        v[b] = Yraw[(size_t)b * O + o];
        s += v[b]; s2 += (double)v[b] * v[b];
    }
    double mean = s / (double)BATCH;
    double var = s2 / (double)BATCH - mean * mean;
    double sc = (double)gamma[o] / sqrt(var + 1e-5);
    double sh = (double)beta[o] - mean * sc;
    #pragma unroll
    for (int b = 0; b < BATCH; b++) {
        float u = (float)((double)v[b] * sc + sh);
        Yact[(size_t)b * O + o] = u >= 0.f ? u : 0.2f * u;
    }
}

// ---------------------------------------------------------------------------
// host orchestration
// ---------------------------------------------------------------------------
static inline float* sym_addr(const void* symbol) {
    void* p = nullptr;
    cudaGetSymbolAddress(&p, symbol);
    return (float*)p;
}

extern "C" void kernel_launch(void* const* d_in, const int* in_sizes, int n_in,
                              void* d_out, int out_size) {
    const float* x   = (const float*)d_in[0];
    const float* w1  = (const float*)d_in[1];
    const float* g1  = (const float*)d_in[2];
    const float* b1  = (const float*)d_in[3];
    const float* w2  = (const float*)d_in[4];
    const float* g2  = (const float*)d_in[5];
    const float* b2  = (const float*)d_in[6];
    const float* w3  = (const float*)d_in[7];
    const float* g3  = (const float*)d_in[8];
    const float* b3  = (const float*)d_in[9];
    const float* w4  = (const float*)d_in[10];
    const float* g4  = (const float*)d_in[11];
    const float* b4  = (const float*)d_in[12];
    const float* w5  = (const float*)d_in[13];
    const float* g5  = (const float*)d_in[14];
    const float* b5  = (const float*)d_in[15];
    const float* lw1 = (const float*)d_in[16];
    const float* g6  = (const float*)d_in[17];
    const float* b6  = (const float*)d_in[18];
    const float* lw2 = (const float*)d_in[19];
    const float* lb2 = (const float*)d_in[20];
    const float* g7  = (const float*)d_in[21];
    const float* b7  = (const float*)d_in[22];
    const float* lw3 = (const float*)d_in[23];
    const float* lb3 = (const float*)d_in[24];

    float* xp    = sym_addr(g_xp);
    float* feat  = sym_addr(g_feat);
    float* D     = sym_addr(g_D);
    int*   idx   = (int*)sym_addr(g_idx);
    float* xxv   = sym_addr(g_xx);
    float* tbuf  = sym_addr(g_t);
    float* gmax  = sym_addr(g_max);
    float* gmin  = sym_addr(g_min);
    float* h5    = sym_addr(g_h5);
    float* psum  = sym_addr(g_psum);
    float* psq   = sym_addr(g_psq);
    float* scale = sym_addr(g_scale);
    float* shift = sym_addr(g_shift);
    float* wlot  = sym_addr(g_wlot);
    float* whit  = sym_addr(g_whit);
    float* w5t   = sym_addr(g_w5t);
    float* pooled = sym_addr(g_pooled);
    float* fc1raw = sym_addr(g_fc1raw);
    float* fc1    = sym_addr(g_fc1);
    float* fc2raw = sym_addr(g_fc2raw);
    float* fc2    = sym_addr(g_fc2);

    transpose_x_k<<<(BATCH * NPTS * 3 + 255) / 256, 256>>>(x, xp);
    wt_k<<<(1024 * 512 + 255) / 256, 256>>>(w5, 1024, 512, w5t);
    xx_k<<<(NPOINTS * 32 + 255) / 256, 256>>>(xp, 3, 3, xxv);

    struct Cfg {
        const float* Fin; int ldf; int C; int O; int colout;
        const float* W; const float* gamma; const float* beta;
    };
    Cfg cfgs[4] = {
        { xp,          3,   3,   64,  0,   w1, g1, b1 },
        { feat + 0,    512, 64,  64,  64,  w2, g2, b2 },
        { feat + 64,   512, 64,  128, 128, w3, g3, b3 },
        { feat + 128,  512, 128, 256, 256, w4, g4, b4 },
    };

    for (int L = 0; L < 4; L++) {
        const Cfg& c = cfgs[L];
        wprep_k<<<(c.O * c.C + 255) / 256, 256>>>(c.W, c.O, c.C, wlot, whit);
        if (c.C == 3)
            dist3_k<<<dim3(8, 8, 8), 256>>>(c.Fin, xxv, D);
        else
            dist8_k<<<dim3(8, 8, 8), 256>>>(c.Fin, c.ldf, c.C, xxv, D);
        topk_warp_k<<<NPOINTS / 8, 256>>>(D, idx);
        if (c.O >= 128)
            gemm128_k<<<dim3(c.O / 128, NPOINTS / 128), 256>>>(c.Fin, c.ldf, whit, c.O,
                                                               tbuf, c.O, c.C);
        else
            gemm_k<<<dim3(c.O / 64, NPOINTS / 64), 256>>>(c.Fin, c.ldf, whit, c.O,
                                                          tbuf, c.O, NPOINTS, c.O, c.C);
        if (c.O >= 128) {
            edge_fused8_k<<<dim3(c.O / 128, NPOINTS / 4), 320, EDGE_SMEM(8)>>>(
                c.Fin, c.ldf, c.C, c.O, idx, wlot, tbuf, gmax, gmin, psum, psq);
        } else {
            edge_fused4_k<<<dim3(c.O / 64, NPOINTS / 4), 320, EDGE_SMEM(4)>>>(
                c.Fin, c.ldf, c.C, c.O, idx, wlot, tbuf, gmax, gmin, psum, psq);
        }
        statsred_k<<<c.O, 256>>>(psum, psq, NPOINTS / 4, c.O, 1.0 / (double)MROWS,
                                 c.gamma, c.beta, scale, shift);
        bnapply_xx_k<<<NPOINTS / 8, 256>>>(gmax, gmin, scale, shift, c.O,
                                           feat, 512, c.colout, xxv);
    }

    // conv5 on tensor cores (3xTF32), then separate coalesced stats pass
    gemm5_tf32_k<<<dim3(1024 / 128, NPOINTS / 128), 256>>>(feat, 512, w5t, 1024,
                                                           h5, 1024, 512);
    stats_h5_k<<<64, 256>>>(h5, psum, psq);
    statsred_k<<<1024, 256>>>(psum, psq, 64, 1024, 1.0 / (double)NPOINTS,
                              g5, b5, scale, shift);
    pool1_k<<<dim3(4, 8, 8), 256>>>(h5, scale, shift, psum, psq);
    pool2_k<<<dim3(4, 8), 256>>>(psum, psq, pooled);

    // head
    fc_k<<<512, 128>>>(pooled, 2048, lw1, nullptr, fc1raw, 512);
    bnrow_k<<<2, 256>>>(fc1raw, 512, g6, b6, fc1);
    fc_k<<<256, 128>>>(fc1, 512, lw2, lb2, fc2raw, 256);
    bnrow_k<<<1, 256>>>(fc2raw, 256, g7, b7, fc2);
    fc_k<<<40, 128>>>(fc2, 256, lw3, lb3, (float*)d_out, 40);
}

// round 16
// speedup vs baseline: 1.9736x; 1.0247x over previous
#include <cuda_runtime.h>
#include <math.h>
#include <stdint.h>
#include <stddef.h>

// ---------------------------------------------------------------------------
// DGCNN classifier, B=8, N=1024, K=20.
// Round 16: SIMT edge reverted (knn path frozen at bit-exactness; TF32 edge
// rejected in round 15), widened to 8-point blocks (bit-identical outputs &
// stats order). conv5 stays on tensor cores (3xTF32, validated round 14).
// ---------------------------------------------------------------------------

#define BATCH 8
#define NPTS 1024
#define KNN 20
#define NPOINTS (BATCH * NPTS)          // 8192
#define MROWS (NPOINTS * KNN)           // 163840
#define NEG_BIG (-3.0e38f)
#define POS_BIG (3.0e38f)

__device__ float g_xp[NPOINTS * 3];
__device__ float g_feat[NPOINTS * 512];
__device__ float g_D[(size_t)BATCH * NPTS * NPTS];      // 32 MB
__device__ int   g_idx[NPOINTS * KNN];
__device__ float g_xx[NPOINTS];
__device__ float g_t[NPOINTS * 256];                    // 8 MB
__device__ float g_max[NPOINTS * 256];
__device__ float g_min[NPOINTS * 256];
__device__ float g_h5[(size_t)NPOINTS * 1024];          // 33 MB
__device__ float g_psum[2048 * 256];
__device__ float g_psq[2048 * 256];
__device__ float g_scale[1024];
__device__ float g_shift[1024];
__device__ float g_wlot[128 * 256];
__device__ float g_whit[128 * 256];
__device__ float g_w5t[512 * 1024];
__device__ float g_pooled[BATCH * 2048];
__device__ float g_fc1raw[BATCH * 512];
__device__ float g_fc1[BATCH * 512];
__device__ float g_fc2raw[BATCH * 256];
__device__ float g_fc2[BATCH * 256];

// ---------------------------------------------------------------------------
// TF32 helpers (conv5 only — post-knn)
// ---------------------------------------------------------------------------
__device__ __forceinline__ uint32_t f2tf32(float v) {
    uint32_t r;
    asm("cvt.rna.tf32.f32 %0, %1;" : "=r"(r) : "f"(v));
    return r;
}

__device__ __forceinline__ void mma_tf32(float* d, uint32_t a0, uint32_t a1,
                                         uint32_t a2, uint32_t a3,
                                         uint32_t b0, uint32_t b1) {
    asm volatile(
        "mma.sync.aligned.m16n8k8.row.col.f32.tf32.tf32.f32 "
        "{%0,%1,%2,%3}, {%4,%5,%6,%7}, {%8,%9}, {%0,%1,%2,%3};"
        : "+f"(d[0]), "+f"(d[1]), "+f"(d[2]), "+f"(d[3])
        : "r"(a0), "r"(a1), "r"(a2), "r"(a3), "r"(b0), "r"(b1));
}

// ---------------------------------------------------------------------------
// small utility kernels
// ---------------------------------------------------------------------------

__global__ void transpose_x_k(const float* __restrict__ x, float* __restrict__ xp) {
    int l = blockIdx.x * blockDim.x + threadIdx.x;
    if (l >= BATCH * NPTS * 3) return;
    int c = l % 3;
    int n = (l / 3) % NPTS;
    int b = l / (3 * NPTS);
    xp[l] = x[((size_t)b * 3 + c) * NPTS + n];
}

__global__ void wprep_k(const float* __restrict__ W, int O, int C,
                        float* __restrict__ wlot, float* __restrict__ whit) {
    int l = blockIdx.x * blockDim.x + threadIdx.x;
    if (l >= O * C) return;
    int o = l % O;
    int c = l / O;
    wlot[l] = W[(size_t)o * 2 * C + c];
    whit[l] = W[(size_t)o * 2 * C + C + c];
}

__global__ void wt_k(const float* __restrict__ W, int O, int Kc, float* __restrict__ Wt) {
    int l = blockIdx.x * blockDim.x + threadIdx.x;
    if (l >= O * Kc) return;
    int o = l % O;
    int c = l / O;
    Wt[l] = W[(size_t)o * Kc + c];
}

__global__ void xx_k(const float* __restrict__ F, int ldf, int C, float* __restrict__ xx) {
    int g = blockIdx.x * blockDim.x + threadIdx.x;
    int p = g >> 5, lane = g & 31;
    if (p >= NPOINTS) return;
    const float* f = F + (size_t)p * ldf;
    float s = 0.f;
    for (int c = lane; c < C; c += 32) { float v = f[c]; s += v * v; }
    #pragma unroll
    for (int off = 16; off; off >>= 1) s += __shfl_down_sync(0xffffffffu, s, off);
    if (lane == 0) xx[p] = s;
}

// ---------------------------------------------------------------------------
// pairwise neg-dist, C=3 special case (layer 1)
// ---------------------------------------------------------------------------
__global__ __launch_bounds__(256)
void dist3_k(const float* __restrict__ F,
             const float* __restrict__ xx, float* __restrict__ D) {
    int bi = blockIdx.y, bj = blockIdx.x;
    if (bj < bi) return;
    __shared__ float Fi[3][128];
    __shared__ float Fj[3][128];
    int b = blockIdx.z;
    int i0 = bi * 128, j0 = bj * 128;
    int tid = threadIdx.x;
    int tm = tid / 16, tn = tid % 16;
    const float* Fb = F + (size_t)b * NPTS * 3;
    if (tid < 128) {
        Fi[0][tid] = Fb[(size_t)(i0 + tid) * 3 + 0];
        Fi[1][tid] = Fb[(size_t)(i0 + tid) * 3 + 1];
        Fi[2][tid] = Fb[(size_t)(i0 + tid) * 3 + 2];
    } else {
        int m = tid - 128;
        Fj[0][m] = Fb[(size_t)(j0 + m) * 3 + 0];
        Fj[1][m] = Fb[(size_t)(j0 + m) * 3 + 1];
        Fj[2][m] = Fb[(size_t)(j0 + m) * 3 + 2];
    }
    __syncthreads();

    float acc[8][8];
    #pragma unroll
    for (int i = 0; i < 8; i++)
        #pragma unroll
        for (int j = 0; j < 8; j++) acc[i][j] = 0.f;
    #pragma unroll
    for (int kk = 0; kk < 3; kk++) {
        float a[8], bb[8];
        #pragma unroll
        for (int i = 0; i < 8; i++) a[i] = Fi[kk][tm * 8 + i];
        #pragma unroll
        for (int j = 0; j < 8; j++) bb[j] = Fj[kk][tn * 8 + j];
        #pragma unroll
        for (int i = 0; i < 8; i++)
            #pragma unroll
            for (int j = 0; j < 8; j++) acc[i][j] += a[i] * bb[j];
    }

    float xi[8], xj[8];
    #pragma unroll
    for (int i = 0; i < 8; i++) xi[i] = xx[b * NPTS + i0 + tm * 8 + i];
    #pragma unroll
    for (int j = 0; j < 8; j++) xj[j] = xx[b * NPTS + j0 + tn * 8 + j];

    #pragma unroll
    for (int i = 0; i < 8; i++) {
        int ii = i0 + tm * 8 + i;
        float out[8];
        #pragma unroll
        for (int j = 0; j < 8; j++) out[j] = -(xi[i] - 2.f * acc[i][j] + xj[j]);
        float* dst = &D[((size_t)b * NPTS + ii) * NPTS + j0 + tn * 8];
        *(float4*)&dst[0] = *(float4*)&out[0];
        *(float4*)&dst[4] = *(float4*)&out[4];
    }
    if (bj > bi) {
        #pragma unroll
        for (int j = 0; j < 8; j++) {
            int jj = j0 + tn * 8 + j;
            float out[8];
            #pragma unroll
            for (int i = 0; i < 8; i++) out[i] = -(xj[j] - 2.f * acc[i][j] + xi[i]);
            float* dst = &D[((size_t)b * NPTS + jj) * NPTS + i0 + tm * 8];
            *(float4*)&dst[0] = *(float4*)&out[0];
            *(float4*)&dst[4] = *(float4*)&out[4];
        }
    }
}

// ---------------------------------------------------------------------------
// pairwise neg-dist, generic (C>=16), 128x128, 8x8, SYMMETRIC, double-buffered
// ---------------------------------------------------------------------------
__global__ __launch_bounds__(256)
void dist8_k(const float* __restrict__ F, int ldf, int C,
             const float* __restrict__ xx, float* __restrict__ D) {
    int bi = blockIdx.y, bj = blockIdx.x;
    if (bj < bi) return;
    __shared__ float Fi[2][16][128];
    __shared__ float Fj[2][16][128];
    int b = blockIdx.z;
    int i0 = bi * 128, j0 = bj * 128;
    int tid = threadIdx.x;
    int tm = tid / 16, tn = tid % 16;
    const float* Fb = F + (size_t)b * NPTS * ldf;
    float acc[8][8];
    #pragma unroll
    for (int i = 0; i < 8; i++)
        #pragma unroll
        for (int j = 0; j < 8; j++) acc[i][j] = 0.f;

    int nch = (C + 15) / 16;

    #pragma unroll
    for (int q = 0; q < 8; q++) {
        int l = q * 256 + tid;
        int kk = l & 15, m = l >> 4;
        Fi[0][kk][m] = (kk < C) ? Fb[(size_t)(i0 + m) * ldf + kk] : 0.f;
        Fj[0][kk][m] = (kk < C) ? Fb[(size_t)(j0 + m) * ldf + kk] : 0.f;
    }
    __syncthreads();

    for (int ch = 0; ch < nch; ch++) {
        int cur = ch & 1;
        if (ch + 1 < nch) {
            int c0 = (ch + 1) * 16;
            int nxt = cur ^ 1;
            #pragma unroll
            for (int q = 0; q < 8; q++) {
                int l = q * 256 + tid;
                int kk = l & 15, m = l >> 4;
                Fi[nxt][kk][m] = (c0 + kk < C) ? Fb[(size_t)(i0 + m) * ldf + c0 + kk] : 0.f;
                Fj[nxt][kk][m] = (c0 + kk < C) ? Fb[(size_t)(j0 + m) * ldf + c0 + kk] : 0.f;
            }
        }
        #pragma unroll
        for (int kk = 0; kk < 16; kk++) {
            float a[8], bb[8];
            *(float4*)&a[0] = *(const float4*)&Fi[cur][kk][tm * 8];
            *(float4*)&a[4] = *(const float4*)&Fi[cur][kk][tm * 8 + 4];
            *(float4*)&bb[0] = *(const float4*)&Fj[cur][kk][tn * 8];
            *(float4*)&bb[4] = *(const float4*)&Fj[cur][kk][tn * 8 + 4];
            #pragma unroll
            for (int i = 0; i < 8; i++)
                #pragma unroll
                for (int j = 0; j < 8; j++) acc[i][j] += a[i] * bb[j];
        }
        __syncthreads();
    }
    float xi[8], xj[8];
    #pragma unroll
    for (int i = 0; i < 8; i++) xi[i] = xx[b * NPTS + i0 + tm * 8 + i];
    #pragma unroll
    for (int j = 0; j < 8; j++) xj[j] = xx[b * NPTS + j0 + tn * 8 + j];

    #pragma unroll
    for (int i = 0; i < 8; i++) {
        int ii = i0 + tm * 8 + i;
        float out[8];
        #pragma unroll
        for (int j = 0; j < 8; j++) out[j] = -(xi[i] - 2.f * acc[i][j] + xj[j]);
        float* dst = &D[((size_t)b * NPTS + ii) * NPTS + j0 + tn * 8];
        *(float4*)&dst[0] = *(float4*)&out[0];
        *(float4*)&dst[4] = *(float4*)&out[4];
    }
    if (bj > bi) {
        #pragma unroll
        for (int j = 0; j < 8; j++) {
            int jj = j0 + tn * 8 + j;
            float out[8];
            #pragma unroll
            for (int i = 0; i < 8; i++) out[i] = -(xj[j] - 2.f * acc[i][j] + xi[i]);
            float* dst = &D[((size_t)b * NPTS + jj) * NPTS + i0 + tm * 8];
            *(float4*)&dst[0] = *(float4*)&out[0];
            *(float4*)&dst[4] = *(float4*)&out[4];
        }
    }
}

// ---------------------------------------------------------------------------
// warp-per-row top-20 by iterative argmax, row cached in registers.
// ---------------------------------------------------------------------------
__global__ void topk_warp_k(const float* __restrict__ D, int* __restrict__ idx) {
    int warp = threadIdx.x >> 5, lane = threadIdx.x & 31;
    int row = blockIdx.x * 8 + warp;
    float vals[32];
    const float* dr = D + (size_t)row * NPTS;
    #pragma unroll
    for (int i = 0; i < 32; i++) vals[i] = dr[i * 32 + lane];

    float lbv = vals[0]; int lbi = 0;
    #pragma unroll
    for (int i = 1; i < 32; i++) if (vals[i] > lbv) { lbv = vals[i]; lbi = i; }

    for (int it = 0; it < KNN; it++) {
        float cv = lbv;
        int cg = lbi * 32 + lane;
        #pragma unroll
        for (int off = 16; off; off >>= 1) {
            float ov = __shfl_down_sync(0xffffffffu, cv, off);
            int oi = __shfl_down_sync(0xffffffffu, cg, off);
            if (ov > cv || (ov == cv && oi < cg)) { cv = ov; cg = oi; }
        }
        int winner = __shfl_sync(0xffffffffu, cg, 0);
        if (lane == 0) idx[row * KNN + it] = winner;
        if ((winner & 31) == lane) {
            int slot = winner >> 5;
            #pragma unroll
            for (int i = 0; i < 32; i++) if (i == slot) vals[i] = NEG_BIG;
            lbv = vals[0]; lbi = 0;
            #pragma unroll
            for (int i = 1; i < 32; i++) if (vals[i] > lbv) { lbv = vals[i]; lbi = i; }
        }
    }
}

// ---------------------------------------------------------------------------
// generic 64x64 tiled GEMM (t for O=64 layers)
// ---------------------------------------------------------------------------
__global__ void gemm_k(const float* __restrict__ A, int lda,
                       const float* __restrict__ B, int ldb,
                       float* __restrict__ C, int ldc,
                       int M, int N, int K) {
    __shared__ float As[16][65];
    __shared__ float Bs[16][64];
    int tid = threadIdx.x;
    int tm = tid / 16, tn = tid % 16;
    int m0 = blockIdx.y * 64;
    int n0 = blockIdx.x * 64;
    float acc[4][4];
    #pragma unroll
    for (int i = 0; i < 4; i++)
        #pragma unroll
        for (int j = 0; j < 4; j++) acc[i][j] = 0.f;

    for (int k0 = 0; k0 < K; k0 += 16) {
        for (int l = tid; l < 64 * 16; l += 256) {
            int m = l >> 4, kk = l & 15;
            As[kk][m] = (k0 + kk < K) ? A[(size_t)(m0 + m) * lda + k0 + kk] : 0.f;
        }
        for (int l = tid; l < 16 * 64; l += 256) {
            int kk = l >> 6, n = l & 63;
            Bs[kk][n] = (k0 + kk < K) ? B[(size_t)(k0 + kk) * ldb + n0 + n] : 0.f;
        }
        __syncthreads();
        #pragma unroll
        for (int kk = 0; kk < 16; kk++) {
            float a[4], b[4];
            #pragma unroll
            for (int i = 0; i < 4; i++) a[i] = As[kk][tm * 4 + i];
            #pragma unroll
            for (int j = 0; j < 4; j++) b[j] = Bs[kk][tn * 4 + j];
            #pragma unroll
            for (int i = 0; i < 4; i++)
                #pragma unroll
                for (int j = 0; j < 4; j++) acc[i][j] += a[i] * b[j];
        }
        __syncthreads();
    }
    #pragma unroll
    for (int i = 0; i < 4; i++)
        #pragma unroll
        for (int j = 0; j < 4; j++)
            C[(size_t)(m0 + tm * 4 + i) * ldc + n0 + tn * 4 + j] = acc[i][j];
}

// ---------------------------------------------------------------------------
// 128x128 tiled GEMM, 8x8 per thread, double-buffered (t for O>=128)
// ---------------------------------------------------------------------------
__global__ __launch_bounds__(256)
void gemm128_k(const float* __restrict__ A, int lda,
               const float* __restrict__ B, int ldb,
               float* __restrict__ C, int ldc, int K) {
    __shared__ float As[2][16][128];
    __shared__ float Bs[2][16][128];
    int tid = threadIdx.x;
    int tm = tid / 16, tn = tid % 16;
    int m0 = blockIdx.y * 128;
    int n0 = blockIdx.x * 128;
    float acc[8][8];
    #pragma unroll
    for (int i = 0; i < 8; i++)
        #pragma unroll
        for (int j = 0; j < 8; j++) acc[i][j] = 0.f;

    int nch = K / 16;
    #pragma unroll
    for (int q = 0; q < 8; q++) {
        int l = q * 256 + tid;
        int kk = l & 15, m = l >> 4;
        As[0][kk][m] = A[(size_t)(m0 + m) * lda + kk];
    }
    #pragma unroll
    for (int q = 0; q < 8; q++) {
        int l = q * 256 + tid;
        int kk = l >> 7, n = l & 127;
        Bs[0][kk][n] = B[(size_t)kk * ldb + n0 + n];
    }
    __syncthreads();

    for (int ch = 0; ch < nch; ch++) {
        int cur = ch & 1;
        if (ch + 1 < nch) {
            int k0 = (ch + 1) * 16;
            int nxt = cur ^ 1;
            #pragma unroll
            for (int q = 0; q < 8; q++) {
                int l = q * 256 + tid;
                int kk = l & 15, m = l >> 4;
                As[nxt][kk][m] = A[(size_t)(m0 + m) * lda + k0 + kk];
            }
            #pragma unroll
            for (int q = 0; q < 8; q++) {
                int l = q * 256 + tid;
                int kk = l >> 7, n = l & 127;
                Bs[nxt][kk][n] = B[(size_t)(k0 + kk) * ldb + n0 + n];
            }
        }
        #pragma unroll
        for (int kk = 0; kk < 16; kk++) {
            float a[8], b[8];
            *(float4*)&a[0] = *(const float4*)&As[cur][kk][tm * 8];
            *(float4*)&a[4] = *(const float4*)&As[cur][kk][tm * 8 + 4];
            *(float4*)&b[0] = *(const float4*)&Bs[cur][kk][tn * 8];
            *(float4*)&b[4] = *(const float4*)&Bs[cur][kk][tn * 8 + 4];
            #pragma unroll
            for (int i = 0; i < 8; i++)
                #pragma unroll
                for (int j = 0; j < 8; j++) acc[i][j] += a[i] * b[j];
        }
        __syncthreads();
    }
    #pragma unroll
    for (int i = 0; i < 8; i++) {
        float* dst = &C[(size_t)(m0 + tm * 8 + i) * ldc + n0 + tn * 8];
        *(float4*)&dst[0] = *(float4*)&acc[i][0];
        *(float4*)&dst[4] = *(float4*)&acc[i][4];
    }
}

// ---------------------------------------------------------------------------
// fused edge layer (SIMT, bit-exact), 8 points per block: 160 rows x NCOLS,
// 640 threads, each 4 rows x TNC cols; double-buffered dynamic smem.
// Per-output accumulation order identical to rounds 4..14 (c0 chunks of 16,
// kk ascending, one owner thread) -> bit-identical h / max / min.
// Stats partials kept at 4-point granularity in the SAME order:
//   red rows 0..19  -> psum[2*blockPt]   (points 8b..8b+3)
//   red rows 20..39 -> psum[2*blockPt+1] (points 8b+4..8b+7)
// smem: sidx/sctr (1280B) | Abuf[2][16][160] Bbuf[2][16][NCOLS] (red aliases)
// ---------------------------------------------------------------------------
template <int TNC>
__device__ __forceinline__
void edge_fused_body(const float* __restrict__ F, int ldf, int C, int O,
                     const int* __restrict__ idx, const float* __restrict__ wlot,
                     const float* __restrict__ t,
                     float* __restrict__ gmax, float* __restrict__ gmin,
                     float* __restrict__ psum, float* __restrict__ psq) {
    constexpr int NCOLS = 16 * TNC;
    extern __shared__ char esm[];
    int*   sidx = (int*)esm;                        // 160
    int*   sctr = sidx + 160;                       // 160
    float* Abuf = (float*)(esm + 1280);             // [2][16*160]
    float* Bbuf = Abuf + 2 * 16 * 160;              // [2][16*NCOLS]
    float* redf = (float*)(esm + 1280);             // alias: [40][NCOLS+4]

    int tid = threadIdx.x;
    int tm = tid / 16;          // 0..39, rows tm*4 .. tm*4+3
    int tn = tid % 16;          // cols tn*TNC ..
    int blockPt = blockIdx.y;   // 8 points
    int n0 = blockIdx.x * NCOLS;

    if (tid < 160) {
        int gp = blockPt * 8 + tid / 20;
        int b = gp >> 10;
        int nbr = idx[blockPt * 160 + tid];
        sidx[tid] = ((b << 10) + nbr) * ldf;
        sctr[tid] = gp * ldf;
    }
    __syncthreads();

    const bool vec = (C % 16 == 0);
    int gm = tid >> 2;          // 0..159, row for vector gather
    int gc = (tid & 3) * 4;     // channel sub-offset 0,4,8,12

    float acc[4][TNC];
    #pragma unroll
    for (int i = 0; i < 4; i++)
        #pragma unroll
        for (int j = 0; j < TNC; j++) acc[i][j] = 0.f;

    int nch = (C + 15) / 16;

    auto load_chunk = [&](int c0, int buf) {
        float* A = Abuf + buf * (16 * 160);
        float* B = Bbuf + buf * (16 * NCOLS);
        if (vec) {
            float4 vn = *(const float4*)&F[(size_t)sidx[gm] + c0 + gc];
            float4 vc = *(const float4*)&F[(size_t)sctr[gm] + c0 + gc];
            A[(gc + 0) * 160 + gm] = vn.x - vc.x;
            A[(gc + 1) * 160 + gm] = vn.y - vc.y;
            A[(gc + 2) * 160 + gm] = vn.z - vc.z;
            A[(gc + 3) * 160 + gm] = vn.w - vc.w;
        } else {
            #pragma unroll
            for (int q = 0; q < 4; q++) {
                int l = q * 640 + tid;
                int m = l % 160, kk = l / 160;
                int cc = c0 + kk;
                A[kk * 160 + m] = (cc < C) ? (F[(size_t)sidx[m] + cc] - F[(size_t)sctr[m] + cc]) : 0.f;
            }
        }
        for (int l = tid; l < 16 * NCOLS; l += 640) {
            int kk = l / NCOLS, n = l % NCOLS;
            B[kk * NCOLS + n] = (c0 + kk < C) ? wlot[(size_t)(c0 + kk) * O + n0 + n] : 0.f;
        }
    };

    load_chunk(0, 0);
    __syncthreads();

    for (int ch = 0; ch < nch; ch++) {
        int cur = ch & 1;
        if (ch + 1 < nch) load_chunk((ch + 1) * 16, cur ^ 1);
        const float* A = Abuf + cur * (16 * 160);
        const float* B = Bbuf + cur * (16 * NCOLS);
        #pragma unroll
        for (int kk = 0; kk < 16; kk++) {
            float a[4], b[TNC];
            *(float4*)a = *(const float4*)&A[kk * 160 + tm * 4];
            #pragma unroll
            for (int v = 0; v < TNC / 4; v++)
                *(float4*)&b[v * 4] = *(const float4*)&B[kk * NCOLS + tn * TNC + v * 4];
            #pragma unroll
            for (int i = 0; i < 4; i++)
                #pragma unroll
                for (int j = 0; j < TNC; j++) acc[i][j] += a[i] * b[j];
        }
        __syncthreads();
    }

    // epilogue: red aliases the (now dead) pipeline buffers
    #define RED(r, c) redf[(r) * (NCOLS + 4) + (c)]

    int P = blockPt * 8 + tm / 5;
    float tvj[TNC];
    #pragma unroll
    for (int v = 0; v < TNC / 4; v++)
        *(float4*)&tvj[v * 4] = *(const float4*)&t[(size_t)P * O + n0 + tn * TNC + v * 4];

    float vmax[TNC], vmin[TNC], vs[TNC], vs2[TNC];
    #pragma unroll
    for (int j = 0; j < TNC; j++) {
        vmax[j] = NEG_BIG; vmin[j] = POS_BIG; vs[j] = 0.f; vs2[j] = 0.f;
        #pragma unroll
        for (int i = 0; i < 4; i++) {
            float v = acc[i][j] + tvj[j];
            vmax[j] = fmaxf(vmax[j], v);
            vmin[j] = fminf(vmin[j], v);
            vs[j] += v;
            vs2[j] += v * v;
        }
    }

    // pass 1: max (per point: 5 consecutive tm rows)
    #pragma unroll
    for (int j = 0; j < TNC; j++) RED(tm, tn * TNC + j) = vmax[j];
    __syncthreads();
    if (tm % 5 == 0) {
        #pragma unroll
        for (int j = 0; j < TNC; j++) {
            int c = tn * TNC + j;
            float m = RED(tm, c);
            #pragma unroll
            for (int q = 1; q < 5; q++) m = fmaxf(m, RED(tm + q, c));
            gmax[(size_t)P * O + n0 + c] = m;
        }
    }
    __syncthreads();
    // pass 2: min
    #pragma unroll
    for (int j = 0; j < TNC; j++) RED(tm, tn * TNC + j) = vmin[j];
    __syncthreads();
    if (tm % 5 == 0) {
        #pragma unroll
        for (int j = 0; j < TNC; j++) {
            int c = tn * TNC + j;
            float m = RED(tm, c);
            #pragma unroll
            for (int q = 1; q < 5; q++) m = fminf(m, RED(tm + q, c));
            gmin[(size_t)P * O + n0 + c] = m;
        }
    }
    __syncthreads();
    // pass 3: sum per 4-point half (rows 0..19 and 20..39), SAME order as before
    #pragma unroll
    for (int j = 0; j < TNC; j++) RED(tm, tn * TNC + j) = vs[j];
    __syncthreads();
    if (tm % 20 == 0) {
        int half = tm / 20;
        #pragma unroll
        for (int j = 0; j < TNC; j++) {
            int c = tn * TNC + j;
            float s = 0.f;
            #pragma unroll
            for (int q = 0; q < 20; q++) s += RED(tm + q, c);
            psum[(size_t)(blockPt * 2 + half) * O + n0 + c] = s;
        }
    }
    __syncthreads();
    // pass 4: sumsq
    #pragma unroll
    for (int j = 0; j < TNC; j++) RED(tm, tn * TNC + j) = vs2[j];
    __syncthreads();
    if (tm % 20 == 0) {
        int half = tm / 20;
        #pragma unroll
        for (int j = 0; j < TNC; j++) {
            int c = tn * TNC + j;
            float s = 0.f;
            #pragma unroll
            for (int q = 0; q < 20; q++) s += RED(tm + q, c);
            psq[(size_t)(blockPt * 2 + half) * O + n0 + c] = s;
        }
    }
    #undef RED
}

__global__ __launch_bounds__(640)
void edge_fused4_k(const float* __restrict__ F, int ldf, int C, int O,
                   const int* __restrict__ idx, const float* __restrict__ wlot,
                   const float* __restrict__ t,
                   float* __restrict__ gmax, float* __restrict__ gmin,
                   float* __restrict__ psum, float* __restrict__ psq) {
    edge_fused_body<4>(F, ldf, C, O, idx, wlot, t, gmax, gmin, psum, psq);
}

__global__ __launch_bounds__(640)
void edge_fused8_k(const float* __restrict__ F, int ldf, int C, int O,
                   const int* __restrict__ idx, const float* __restrict__ wlot,
                   const float* __restrict__ t,
                   float* __restrict__ gmax, float* __restrict__ gmin,
                   float* __restrict__ psum, float* __restrict__ psq) {
    edge_fused_body<8>(F, ldf, C, O, idx, wlot, t, gmax, gmin, psum, psq);
}

// dynamic smem: sidx/sctr + double-buffered A/B (red aliases)
#define EDGE_SMEM(TNC) (1280 + 2 * 16 * 160 * 4 + 2 * 16 * (16 * (TNC)) * 4)

// ---------------------------------------------------------------------------
// reduce stats partials -> scale/shift
// ---------------------------------------------------------------------------
__global__ void statsred_k(const float* __restrict__ psum, const float* __restrict__ psq,
                           int R, int O, double invM,
                           const float* __restrict__ gamma, const float* __restrict__ beta,
                           float* __restrict__ scale, float* __restrict__ shift) {
    int o = blockIdx.x;
    double ls = 0.0, ls2 = 0.0;
    for (int r = threadIdx.x; r < R; r += 256) {
        ls += psum[(size_t)r * O + o];
        ls2 += psq[(size_t)r * O + o];
    }
    __shared__ double sd[256], sd2[256];
    sd[threadIdx.x] = ls; sd2[threadIdx.x] = ls2;
    __syncthreads();
    for (int s = 128; s > 0; s >>= 1) {
        if (threadIdx.x < s) { sd[threadIdx.x] += sd[threadIdx.x + s]; sd2[threadIdx.x] += sd2[threadIdx.x + s]; }
        __syncthreads();
    }
    if (threadIdx.x == 0) {
        double mean = sd[0] * invM;
        double var = sd2[0] * invM - mean * mean;
        double sc = (double)gamma[o] / sqrt(var + 1e-5);
        scale[o] = (float)sc;
        shift[o] = (float)((double)beta[o] - mean * sc);
    }
}

// ---------------------------------------------------------------------------
// bnapply + fused xx for the next layer (bit-identical to xx_k ordering)
// ---------------------------------------------------------------------------
__global__ void bnapply_xx_k(const float* __restrict__ gmax, const float* __restrict__ gmin,
                             const float* __restrict__ scale, const float* __restrict__ shift,
                             int O, float* __restrict__ outFeat, int ldo, int colofs,
                             float* __restrict__ xx) {
    int warp = threadIdx.x >> 5, lane = threadIdx.x & 31;
    int p = blockIdx.x * 8 + warp;
    float ss = 0.f;
    for (int o = lane; o < O; o += 32) {
        float sc = scale[o];
        size_t l = (size_t)p * O + o;
        float v = (sc >= 0.f) ? gmax[l] : gmin[l];
        float u = v * sc + shift[o];
        u = u >= 0.f ? u : 0.2f * u;
        outFeat[(size_t)p * ldo + colofs + o] = u;
        ss += u * u;
    }
    #pragma unroll
    for (int off = 16; off; off >>= 1) ss += __shfl_down_sync(0xffffffffu, ss, off);
    if (lane == 0) xx[p] = ss;
}

// ---------------------------------------------------------------------------
// conv5 GEMM on tensor cores: 3xTF32 split MMA (validated round 14)
// ---------------------------------------------------------------------------
__global__ __launch_bounds__(256)
void gemm5_tf32_k(const float* __restrict__ A, int lda,
                  const float* __restrict__ B, int ldb,
                  float* __restrict__ C, int ldc, int K) {
    __shared__ uint32_t Ah[128][20], Al[128][20];
    __shared__ uint32_t Bh[16][136], Bl[16][136];
    int tid = threadIdx.x;
    int warp = tid >> 5, lane = tid & 31;
    int wm = warp >> 2;
    int wn = warp & 3;
    int grp = lane >> 2, tig = lane & 3;
    int m0 = blockIdx.y * 128, n0 = blockIdx.x * 128;

    float acc[4][4][4];
    #pragma unroll
    for (int mf = 0; mf < 4; mf++)
        #pragma unroll
        for (int nf = 0; nf < 4; nf++)
            #pragma unroll
            for (int r = 0; r < 4; r++) acc[mf][nf][r] = 0.f;

    for (int k0 = 0; k0 < K; k0 += 16) {
        #pragma unroll
        for (int q = 0; q < 8; q++) {
            int l = q * 256 + tid;
            int m = l >> 4, kk = l & 15;
            float v = A[(size_t)(m0 + m) * lda + k0 + kk];
            uint32_t hi = f2tf32(v);
            uint32_t lo = f2tf32(v - __uint_as_float(hi));
            Ah[m][kk] = hi; Al[m][kk] = lo;
        }
        #pragma unroll
        for (int q = 0; q < 8; q++) {
            int l = q * 256 + tid;
            int kk = l >> 7, n = l & 127;
            float v = B[(size_t)(k0 + kk) * ldb + n0 + n];
            uint32_t hi = f2tf32(v);
            uint32_t lo = f2tf32(v - __uint_as_float(hi));
            Bh[kk][n] = hi; Bl[kk][n] = lo;
        }
        __syncthreads();

        #pragma unroll
        for (int ks = 0; ks < 16; ks += 8) {
            uint32_t bh[4][2], bl[4][2];
            #pragma unroll
            for (int nf = 0; nf < 4; nf++) {
                int col = wn * 32 + nf * 8 + grp;
                bh[nf][0] = Bh[ks + tig][col];
                bh[nf][1] = Bh[ks + tig + 4][col];
                bl[nf][0] = Bl[ks + tig][col];
                bl[nf][1] = Bl[ks + tig + 4][col];
            }
            #pragma unroll
            for (int mf = 0; mf < 4; mf++) {
                int r0 = wm * 64 + mf * 16 + grp;
                uint32_t ah0 = Ah[r0][ks + tig];
                uint32_t ah1 = Ah[r0 + 8][ks + tig];
                uint32_t ah2 = Ah[r0][ks + tig + 4];
                uint32_t ah3 = Ah[r0 + 8][ks + tig + 4];
                uint32_t al0 = Al[r0][ks + tig];
                uint32_t al1 = Al[r0 + 8][ks + tig];
                uint32_t al2 = Al[r0][ks + tig + 4];
                uint32_t al3 = Al[r0 + 8][ks + tig + 4];
                #pragma unroll
                for (int nf = 0; nf < 4; nf++) {
                    float* d = acc[mf][nf];
                    mma_tf32(d, al0, al1, al2, al3, bh[nf][0], bh[nf][1]);
                    mma_tf32(d, ah0, ah1, ah2, ah3, bl[nf][0], bl[nf][1]);
                    mma_tf32(d, ah0, ah1, ah2, ah3, bh[nf][0], bh[nf][1]);
                }
            }
        }
        __syncthreads();
    }

    #pragma unroll
    for (int mf = 0; mf < 4; mf++) {
        int r = m0 + wm * 64 + mf * 16 + grp;
        #pragma unroll
        for (int nf = 0; nf < 4; nf++) {
            int c = n0 + wn * 32 + nf * 8 + 2 * tig;
            *(float2*)&C[(size_t)r * ldc + c]       = make_float2(acc[mf][nf][0], acc[mf][nf][1]);
            *(float2*)&C[(size_t)(r + 8) * ldc + c] = make_float2(acc[mf][nf][2], acc[mf][nf][3]);
        }
    }
}

// ---------------------------------------------------------------------------
// h5 stats: per-channel sum/sumsq partials over 128-row chunks (coalesced).
// ---------------------------------------------------------------------------
__global__ void stats_h5_k(const float* __restrict__ h5,
                           float* __restrict__ psum, float* __restrict__ psq) {
    int blk = blockIdx.x;
    int tid = threadIdx.x;
    float s[4] = {0.f, 0.f, 0.f, 0.f};
    float s2[4] = {0.f, 0.f, 0.f, 0.f};
    int rbase = blk * 128;
    for (int r = 0; r < 128; r++) {
        const float* row = h5 + (size_t)(rbase + r) * 1024;
        #pragma unroll
        for (int q = 0; q < 4; q++) {
            float v = row[tid + q * 256];
            s[q] += v; s2[q] += v * v;
        }
    }
    #pragma unroll
    for (int q = 0; q < 4; q++) {
        psum[(size_t)blk * 1024 + tid + q * 256] = s[q];
        psq[(size_t)blk * 1024 + tid + q * 256] = s2[q];
    }
}

// ---------------------------------------------------------------------------
// conv5 pooling, 2-stage
// ---------------------------------------------------------------------------
__global__ void pool1_k(const float* __restrict__ h5, const float* __restrict__ scale,
                        const float* __restrict__ shift,
                        float* __restrict__ pmax, float* __restrict__ psumv) {
    int b = blockIdx.y;
    int zc = blockIdx.z;
    int o = blockIdx.x * blockDim.x + threadIdx.x;
    float sc = scale[o], sh = shift[o];
    float mx = NEG_BIG, sm = 0.f;
    int nbase = zc * 128;
    for (int n = nbase; n < nbase + 128; n++) {
        float v = h5[((size_t)b * NPTS + n) * 1024 + o] * sc + sh;
        v = v >= 0.f ? v : 0.2f * v;
        mx = fmaxf(mx, v);
        sm += v;
    }
    pmax[((size_t)zc * 8 + b) * 1024 + o] = mx;
    psumv[((size_t)zc * 8 + b) * 1024 + o] = sm;
}

__global__ void pool2_k(const float* __restrict__ pmax, const float* __restrict__ psumv,
                        float* __restrict__ pooled) {
    int b = blockIdx.y;
    int o = blockIdx.x * blockDim.x + threadIdx.x;
    float mx = NEG_BIG, sm = 0.f;
    #pragma unroll
    for (int z = 0; z < 8; z++) {
        mx = fmaxf(mx, pmax[((size_t)z * 8 + b) * 1024 + o]);
        sm += psumv[((size_t)z * 8 + b) * 1024 + o];
    }
    pooled[b * 2048 + o] = mx;
    pooled[b * 2048 + 1024 + o] = sm * (1.f / (float)NPTS);
}

// ---------------------------------------------------------------------------
// tiny FC + per-batch BN
// ---------------------------------------------------------------------------
__global__ void fc_k(const float* __restrict__ X, int bcols,
                     const float* __restrict__ W, const float* __restrict__ bias,
                     float* __restrict__ Y, int O) {
    int o = blockIdx.x;
    const float* w = W + (size_t)o * bcols;
    float acc[BATCH];
    #pragma unroll
    for (int b = 0; b < BATCH; b++) acc[b] = 0.f;
    for (int c = threadIdx.x; c < bcols; c += blockDim.x) {
        float wv = w[c];
        #pragma unroll
        for (int b = 0; b < BATCH; b++) acc[b] += X[(size_t)b * bcols + c] * wv;
    }
    #pragma unroll
    for (int b = 0; b < BATCH; b++)
        #pragma unroll
        for (int off = 16; off; off >>= 1)
            acc[b] += __shfl_down_sync(0xffffffffu, acc[b], off);
    __shared__ float sm[BATCH][4];
    int warp = threadIdx.x >> 5, lane = threadIdx.x & 31;
    if (lane == 0)
        #pragma unroll
        for (int b = 0; b < BATCH; b++) sm[b][warp] = acc[b];
    __syncthreads();
    if (threadIdx.x == 0) {
        float bs = bias ? bias[o] : 0.f;
        #pragma unroll
        for (int b = 0; b < BATCH; b++)
            Y[(size_t)b * O + o] = sm[b][0] + sm[b][1] + sm[b][2] + sm[b][3] + bs;
    }
}

__global__ void bnrow_k(const float* __restrict__ Yraw, int O,
                        const float* __restrict__ gamma, const float* __restrict__ beta,
                        float* __restrict__ Yact) {
    int o = blockIdx.x * blockDim.x + threadIdx.x;
    if (o >= O) return;
    float v[BATCH];
    double s = 0.0, s2 = 0.0;
    #pragma unroll
    for (int b = 0; b < BATCH; b++) {
        v[b] = Yraw[(size_t)b * O + o];
        s += v[b]; s2 += (double)v[b] * v[b];
    }
    double mean = s / (double)BATCH;
    double var = s2 / (double)BATCH - mean * mean;
    double sc = (double)gamma[o] / sqrt(var + 1e-5);
    double sh = (double)beta[o] - mean * sc;
    #pragma unroll
    for (int b = 0; b < BATCH; b++) {
        float u = (float)((double)v[b] * sc + sh);
        Yact[(size_t)b * O + o] = u >= 0.f ? u : 0.2f * u;
    }
}

// ---------------------------------------------------------------------------
// host orchestration
// ---------------------------------------------------------------------------
static inline float* sym_addr(const void* symbol) {
    void* p = nullptr;
    cudaGetSymbolAddress(&p, symbol);
    return (float*)p;
}

extern "C" void kernel_launch(void* const* d_in, const int* in_sizes, int n_in,
                              void* d_out, int out_size) {
    const float* x   = (const float*)d_in[0];
    const float* w1  = (const float*)d_in[1];
    const float* g1  = (const float*)d_in[2];
    const float* b1  = (const float*)d_in[3];
    const float* w2  = (const float*)d_in[4];
    const float* g2  = (const float*)d_in[5];
    const float* b2  = (const float*)d_in[6];
    const float* w3  = (const float*)d_in[7];
    const float* g3  = (const float*)d_in[8];
    const float* b3  = (const float*)d_in[9];
    const float* w4  = (const float*)d_in[10];
    const float* g4  = (const float*)d_in[11];
    const float* b4  = (const float*)d_in[12];
    const float* w5  = (const float*)d_in[13];
    const float* g5  = (const float*)d_in[14];
    const float* b5  = (const float*)d_in[15];
    const float* lw1 = (const float*)d_in[16];
    const float* g6  = (const float*)d_in[17];
    const float* b6  = (const float*)d_in[18];
    const float* lw2 = (const float*)d_in[19];
    const float* lb2 = (const float*)d_in[20];
    const float* g7  = (const float*)d_in[21];
    const float* b7  = (const float*)d_in[22];
    const float* lw3 = (const float*)d_in[23];
    const float* lb3 = (const float*)d_in[24];

    float* xp    = sym_addr(g_xp);
    float* feat  = sym_addr(g_feat);
    float* D     = sym_addr(g_D);
    int*   idx   = (int*)sym_addr(g_idx);
    float* xxv   = sym_addr(g_xx);
    float* tbuf  = sym_addr(g_t);
    float* gmax  = sym_addr(g_max);
    float* gmin  = sym_addr(g_min);
    float* h5    = sym_addr(g_h5);
    float* psum  = sym_addr(g_psum);
    float* psq   = sym_addr(g_psq);
    float* scale = sym_addr(g_scale);
    float* shift = sym_addr(g_shift);
    float* wlot  = sym_addr(g_wlot);
    float* whit  = sym_addr(g_whit);
    float* w5t   = sym_addr(g_w5t);
    float* pooled = sym_addr(g_pooled);
    float* fc1raw = sym_addr(g_fc1raw);
    float* fc1    = sym_addr(g_fc1);
    float* fc2raw = sym_addr(g_fc2raw);
    float* fc2    = sym_addr(g_fc2);

    transpose_x_k<<<(BATCH * NPTS * 3 + 255) / 256, 256>>>(x, xp);
    wt_k<<<(1024 * 512 + 255) / 256, 256>>>(w5, 1024, 512, w5t);
    xx_k<<<(NPOINTS * 32 + 255) / 256, 256>>>(xp, 3, 3, xxv);

    struct Cfg {
        const float* Fin; int ldf; int C; int O; int colout;
        const float* W; const float* gamma; const float* beta;
    };
    Cfg cfgs[4] = {
        { xp,          3,   3,   64,  0,   w1, g1, b1 },
        { feat + 0,    512, 64,  64,  64,  w2, g2, b2 },
        { feat + 64,   512, 64,  128, 128, w3, g3, b3 },
        { feat + 128,  512, 128, 256, 256, w4, g4, b4 },
    };

    for (int L = 0; L < 4; L++) {
        const Cfg& c = cfgs[L];
        wprep_k<<<(c.O * c.C + 255) / 256, 256>>>(c.W, c.O, c.C, wlot, whit);
        if (c.C == 3)
            dist3_k<<<dim3(8, 8, 8), 256>>>(c.Fin, xxv, D);
        else
            dist8_k<<<dim3(8, 8, 8), 256>>>(c.Fin, c.ldf, c.C, xxv, D);
        topk_warp_k<<<NPOINTS / 8, 256>>>(D, idx);
        if (c.O >= 128)
            gemm128_k<<<dim3(c.O / 128, NPOINTS / 128), 256>>>(c.Fin, c.ldf, whit, c.O,
                                                               tbuf, c.O, c.C);
        else
            gemm_k<<<dim3(c.O / 64, NPOINTS / 64), 256>>>(c.Fin, c.ldf, whit, c.O,
                                                          tbuf, c.O, NPOINTS, c.O, c.C);
        if (c.O >= 128) {
            edge_fused8_k<<<dim3(c.O / 128, NPOINTS / 8), 640, EDGE_SMEM(8)>>>(
                c.Fin, c.ldf, c.C, c.O, idx, wlot, tbuf, gmax, gmin, psum, psq);
        } else {
            edge_fused4_k<<<dim3(c.O / 64, NPOINTS / 8), 640, EDGE_SMEM(4)>>>(
                c.Fin, c.ldf, c.C, c.O, idx, wlot, tbuf, gmax, gmin, psum, psq);
        }
        statsred_k<<<c.O, 256>>>(psum, psq, NPOINTS / 4, c.O, 1.0 / (double)MROWS,
                                 c.gamma, c.beta, scale, shift);
        bnapply_xx_k<<<NPOINTS / 8, 256>>>(gmax, gmin, scale, shift, c.O,
                                           feat, 512, c.colout, xxv);
    }

    // conv5 on tensor cores (3xTF32), then coalesced stats pass
    gemm5_tf32_k<<<dim3(1024 / 128, NPOINTS / 128), 256>>>(feat, 512, w5t, 1024,
                                                           h5, 1024, 512);
    stats_h5_k<<<64, 256>>>(h5, psum, psq);
    statsred_k<<<1024, 256>>>(psum, psq, 64, 1024, 1.0 / (double)NPOINTS,
                              g5, b5, scale, shift);
    pool1_k<<<dim3(4, 8, 8), 256>>>(h5, scale, shift, psum, psq);
    pool2_k<<<dim3(4, 8), 256>>>(psum, psq, pooled);

    // head
    fc_k<<<512, 128>>>(pooled, 2048, lw1, nullptr, fc1raw, 512);
    bnrow_k<<<2, 256>>>(fc1raw, 512, g6, b6, fc1);
    fc_k<<<256, 128>>>(fc1, 512, lw2, lb2, fc2raw, 256);
    bnrow_k<<<1, 256>>>(fc2raw, 256, g7, b7, fc2);
    fc_k<<<40, 128>>>(fc2, 256, lw3, lb3, (float*)d_out, 40);
}